// round 3
// baseline (speedup 1.0000x reference)
#include <cuda_runtime.h>
#include <cstdint>

#define N_NODES 30000
#define N_EDGES 240000
#define NGRAPH  16
#define D1      256
#define D2      512
#define D3      1024

// ---------------- scratch (no allocations allowed) ----------------
__device__ int   d_idx64;            // 1 if indices are int64, 0 if int32
__device__ float d_deg[N_NODES];
__device__ float d_dis[N_NODES];
__device__ float d_s1 [N_NODES];
__device__ float d_norm[N_EDGES];
__device__ __align__(16) float d_g2[N_NODES * D1];   // A_hat @ h1          [N,256]
__device__ __align__(16) float d_h2[N_NODES * D2];   // relu(g2@W2+b2)      [N,512]
__device__ __align__(16) float d_g3[N_NODES * D2];   // A_hat @ h2          [N,512]
__device__ __align__(16) float d_h3[N_NODES * D3];   // relu(g3@W3+b3)      [N,1024]
__device__ __align__(16) float d_pool[NGRAPH * D3];
__device__ float d_cnt[NGRAPH];

// index loader robust to int32 vs int64 storage
__device__ __forceinline__ int load_idx(const void* p, int i) {
    if (d_idx64) return (int)((const long long*)p)[i];
    return ((const int*)p)[i];
}

// vector reduction (no return) — sm_90+
__device__ __forceinline__ void red_add_v4(float* p, float4 v) {
    asm volatile("red.global.add.v4.f32 [%0], {%1,%2,%3,%4};"
                 :: "l"(p), "f"(v.x), "f"(v.y), "f"(v.z), "f"(v.w) : "memory");
}

// ---------------- dtype detection ----------------
// Reads first 64 entries of edge_index as int64; all-in-range => int64 data.
// (int32 data misreads as lo + hi*2^32 which is out of range w.h.p.)
// Byte-safe either way: 64*8 = 512 bytes <= min(480000*4, 240000*8).
__global__ void k_detect(const void* __restrict__ ei) {
    if (threadIdx.x != 0 || blockIdx.x != 0) return;
    const long long* p = (const long long*)ei;
    int ok = 1;
    for (int i = 0; i < 64; i++) {
        long long v = p[i];
        if (v < 0 || v >= N_NODES) { ok = 0; break; }
    }
    d_idx64 = ok;
}

// ---------------- degree / normalization ----------------
__global__ void k_init(void) {
    int i = blockIdx.x * blockDim.x + threadIdx.x;
    if (i < N_NODES) d_deg[i] = 1.0f;               // self loop
    if (i < NGRAPH) d_cnt[i] = 0.0f;
    if (i < NGRAPH * D3) d_pool[i] = 0.0f;
}

__global__ void k_deg_edges(const void* __restrict__ ei) {
    int e = blockIdx.x * blockDim.x + threadIdx.x;
    if (e >= N_EDGES) return;
    int dst = load_idx(ei, N_EDGES + e);
    atomicAdd(&d_deg[dst], 1.0f);
}

__global__ void k_dis_s1(const float* __restrict__ x) {
    int i = blockIdx.x * blockDim.x + threadIdx.x;
    if (i >= N_NODES) return;
    float r = rsqrtf(d_deg[i]);
    d_dis[i] = r;
    d_s1[i]  = r * r * x[i];                         // self-loop term of A_hat @ x
}

__global__ void k_norm_s1(const void* __restrict__ ei, const float* __restrict__ x) {
    int e = blockIdx.x * blockDim.x + threadIdx.x;
    if (e >= N_EDGES) return;
    int s = load_idx(ei, e), d = load_idx(ei, N_EDGES + e);
    float nv = d_dis[s] * d_dis[d];
    d_norm[e] = nv;
    atomicAdd(&d_s1[d], nv * x[s]);
}

__global__ void k_cnt(const void* __restrict__ batch) {
    int i = blockIdx.x * blockDim.x + threadIdx.x;
    if (i >= N_NODES) return;
    int g = load_idx(batch, i);
    atomicAdd(&d_cnt[g], 1.0f);
}

// ---------------- layer 1 -> g2 ----------------
// h1[i,f] = relu(s1[i]*W1[f] + b1[f])  (rank-1 layer, never materialized)
// g2 init with self-loop contribution, then edge scatter on top.
__global__ void k_g2_init(const float* __restrict__ W1, const float* __restrict__ b1) {
    int i = blockIdx.x;             // node
    int f = threadIdx.x;            // 0..255
    float r = d_dis[i];
    float h = fmaxf(fmaf(d_s1[i], W1[f], b1[f]), 0.0f);
    d_g2[(size_t)i * D1 + f] = r * r * h;
}

__global__ void k_scatter1(const void* __restrict__ ei,
                           const float* __restrict__ W1, const float* __restrict__ b1) {
    __shared__ __align__(16) float sW[D1];
    __shared__ __align__(16) float sB[D1];
    int tid = threadIdx.x;
    sW[tid] = W1[tid];
    sB[tid] = b1[tid];
    __syncthreads();
    int warp = tid >> 5, lane = tid & 31;
    int e = blockIdx.x * 8 + warp;
    if (e >= N_EDGES) return;
    int src = load_idx(ei, e), dst = load_idx(ei, N_EDGES + e);
    float nv = d_norm[e];
    float s  = d_s1[src];
    float* gout = d_g2 + (size_t)dst * D1;
#pragma unroll
    for (int it = 0; it < 2; it++) {
        int f = it * 128 + lane * 4;
        float4 w = *(const float4*)&sW[f];
        float4 b = *(const float4*)&sB[f];
        float4 v;
        v.x = nv * fmaxf(fmaf(s, w.x, b.x), 0.0f);
        v.y = nv * fmaxf(fmaf(s, w.y, b.y), 0.0f);
        v.z = nv * fmaxf(fmaf(s, w.z, b.z), 0.0f);
        v.w = nv * fmaxf(fmaf(s, w.w, b.w), 0.0f);
        red_add_v4(gout + f, v);
    }
}

// ---------------- layer 2 aggregation -> g3 ----------------
__global__ void k_g3_init(void) {
    size_t idx = (size_t)blockIdx.x * blockDim.x + threadIdx.x;   // over N*D2/4
    if (idx >= (size_t)N_NODES * D2 / 4) return;
    int i = (int)(idx / (D2 / 4));
    float r = d_dis[i];
    float4 v = *(const float4*)&d_h2[idx * 4];
    float r2 = r * r;
    v.x *= r2; v.y *= r2; v.z *= r2; v.w *= r2;
    *(float4*)&d_g3[idx * 4] = v;
}

__global__ void k_scatter2(const void* __restrict__ ei) {
    int tid = threadIdx.x;
    int warp = tid >> 5, lane = tid & 31;
    int e = blockIdx.x * 8 + warp;
    if (e >= N_EDGES) return;
    int src = load_idx(ei, e), dst = load_idx(ei, N_EDGES + e);
    float nv = d_norm[e];
    const float* hin = d_h2 + (size_t)src * D2;
    float* gout = d_g3 + (size_t)dst * D2;
#pragma unroll
    for (int it = 0; it < 4; it++) {
        int f = it * 128 + lane * 4;
        float4 v = *(const float4*)&hin[f];
        v.x *= nv; v.y *= nv; v.z *= nv; v.w *= nv;
        red_add_v4(gout + f, v);
    }
}

// ---------------- SGEMM 128x128x8, fused bias+relu ----------------
// C[M,N] = relu(A[M,K] @ B[K,N] + bias[N]);  N % 128 == 0, K % 8 == 0
#define BM 128
#define BN 128
#define BK 8
__global__ __launch_bounds__(256, 2)
void sgemm_bias_relu(const float* __restrict__ A, const float* __restrict__ B,
                     const float* __restrict__ bias, float* __restrict__ C,
                     int M, int N, int K) {
    __shared__ __align__(16) float As[BK][BM];
    __shared__ __align__(16) float Bs[BK][BN];
    int tid = threadIdx.x;
    int row0 = blockIdx.y * BM;
    int col0 = blockIdx.x * BN;

    int ty = tid >> 4;             // 0..15
    int tx = tid & 15;             // 0..15
    int rA = ty * 4;               // rows rA..rA+3 and rA+64..rA+67
    int cB = tx * 4;

    // load mappings
    int lm = tid >> 1;             // 0..127
    int lk = (tid & 1) * 4;        // 0 or 4
    int bk = tid >> 5;             // 0..7
    int bn = (tid & 31) * 4;       // 0..124

    float acc[8][8];
#pragma unroll
    for (int i = 0; i < 8; i++)
#pragma unroll
        for (int j = 0; j < 8; j++) acc[i][j] = 0.0f;

    for (int k0 = 0; k0 < K; k0 += BK) {
        float4 av = make_float4(0.f, 0.f, 0.f, 0.f);
        int gr = row0 + lm;
        if (gr < M) av = *(const float4*)(A + (size_t)gr * K + k0 + lk);
        As[lk + 0][lm] = av.x;
        As[lk + 1][lm] = av.y;
        As[lk + 2][lm] = av.z;
        As[lk + 3][lm] = av.w;
        float4 bv = *(const float4*)(B + (size_t)(k0 + bk) * N + col0 + bn);
        *(float4*)&Bs[bk][bn] = bv;
        __syncthreads();
#pragma unroll
        for (int k = 0; k < BK; k++) {
            float a[8], b[8];
            *(float4*)(a)     = *(const float4*)&As[k][rA];
            *(float4*)(a + 4) = *(const float4*)&As[k][rA + 64];
            *(float4*)(b)     = *(const float4*)&Bs[k][cB];
            *(float4*)(b + 4) = *(const float4*)&Bs[k][cB + 64];
#pragma unroll
            for (int i = 0; i < 8; i++)
#pragma unroll
                for (int j = 0; j < 8; j++) acc[i][j] = fmaf(a[i], b[j], acc[i][j]);
        }
        __syncthreads();
    }

#pragma unroll
    for (int i = 0; i < 8; i++) {
        int r = row0 + rA + ((i < 4) ? i : 60 + i);
        if (r >= M) continue;
#pragma unroll
        for (int jh = 0; jh < 2; jh++) {
            int c = col0 + cB + jh * 64;
            float4 bv = *(const float4*)&bias[c];
            float4 v;
            v.x = fmaxf(acc[i][jh * 4 + 0] + bv.x, 0.0f);
            v.y = fmaxf(acc[i][jh * 4 + 1] + bv.y, 0.0f);
            v.z = fmaxf(acc[i][jh * 4 + 2] + bv.z, 0.0f);
            v.w = fmaxf(acc[i][jh * 4 + 3] + bv.w, 0.0f);
            *(float4*)&C[(size_t)r * N + c] = v;
        }
    }
}

// ---------------- pooling + output linear ----------------
__global__ void k_pool(const void* __restrict__ batch) {
    size_t idx = (size_t)blockIdx.x * blockDim.x + threadIdx.x;   // over N*D3/4
    if (idx >= (size_t)N_NODES * D3 / 4) return;
    int i = (int)(idx / (D3 / 4));
    int f = (int)(idx % (D3 / 4)) * 4;
    int g = load_idx(batch, i);
    float4 v = *(const float4*)&d_h3[idx * 4];
    red_add_v4(&d_pool[(size_t)g * D3 + f], v);
}

__global__ void k_final(const float* __restrict__ Wo, const float* __restrict__ bo,
                        float* __restrict__ out) {
    __shared__ float p[D3];
    int g = blockIdx.x, tid = threadIdx.x;
    float inv = 1.0f / fmaxf(d_cnt[g], 1.0f);
    for (int j = tid; j < D3; j += 256) p[j] = d_pool[(size_t)g * D3 + j] * inv;
    __syncthreads();
    float a0 = 0.f, a1 = 0.f, a2 = 0.f, a3 = 0.f;
#pragma unroll 4
    for (int k = 0; k < D3; k++) {
        float pv = p[k];
        const float* w = Wo + (size_t)k * D3;
        a0 = fmaf(pv, w[tid + 0],   a0);
        a1 = fmaf(pv, w[tid + 256], a1);
        a2 = fmaf(pv, w[tid + 512], a2);
        a3 = fmaf(pv, w[tid + 768], a3);
    }
    out[g * D3 + tid + 0]   = a0 + bo[tid + 0];
    out[g * D3 + tid + 256] = a1 + bo[tid + 256];
    out[g * D3 + tid + 512] = a2 + bo[tid + 512];
    out[g * D3 + tid + 768] = a3 + bo[tid + 768];
}

// ---------------- launcher ----------------
extern "C" void kernel_launch(void* const* d_in, const int* in_sizes, int n_in,
                              void* d_out, int out_size) {
    // Pointer-order detection from element counts:
    //   dict order:  x(30000), edge_index(480000), batch(30000), W1(256), b1(256),
    //                W2(131072), b2(512), W3(524288), b3(1024), Wo(1048576), bo(1024)
    //   alphabetical: W1(256), W2(131072), W3(524288), Wo(1048576), b1(256), b2(512),
    //                b3(1024), batch(30000), bo(1024), edge_index(480000), x(30000)
    const float *x, *W1, *b1, *W2, *b2, *W3, *b3, *Wo, *bo;
    const void *ei, *batch;
    if (in_sizes[0] == N_NODES) {           // dict order
        x     = (const float*)d_in[0];
        ei    = d_in[1];
        batch = d_in[2];
        W1 = (const float*)d_in[3];  b1 = (const float*)d_in[4];
        W2 = (const float*)d_in[5];  b2 = (const float*)d_in[6];
        W3 = (const float*)d_in[7];  b3 = (const float*)d_in[8];
        Wo = (const float*)d_in[9];  bo = (const float*)d_in[10];
    } else {                                // alphabetical order
        W1 = (const float*)d_in[0];
        W2 = (const float*)d_in[1];
        W3 = (const float*)d_in[2];
        Wo = (const float*)d_in[3];
        b1 = (const float*)d_in[4];
        b2 = (const float*)d_in[5];
        b3 = (const float*)d_in[6];
        batch = d_in[7];
        bo = (const float*)d_in[8];
        ei = d_in[9];
        x  = (const float*)d_in[10];
    }
    float* out = (float*)d_out;

    float *g2, *h2, *g3, *h3;
    cudaGetSymbolAddress((void**)&g2, d_g2);
    cudaGetSymbolAddress((void**)&h2, d_h2);
    cudaGetSymbolAddress((void**)&g3, d_g3);
    cudaGetSymbolAddress((void**)&h3, d_h3);

    const int TB = 256;
    int nb_nodes = (N_NODES + TB - 1) / TB;
    int nb_edges = (N_EDGES + TB - 1) / TB;
    int nb_edge8 = (N_EDGES + 7) / 8;

    // index dtype detection (int32 vs int64), then normalization
    k_detect<<<1, 32>>>(ei);
    k_init<<<nb_nodes, TB>>>();
    k_deg_edges<<<nb_edges, TB>>>(ei);
    k_dis_s1<<<nb_nodes, TB>>>(x);
    k_norm_s1<<<nb_edges, TB>>>(ei, x);
    k_cnt<<<nb_nodes, TB>>>(batch);

    // layer 1 (rank-1) aggregated into input dim of layer 2
    k_g2_init<<<N_NODES, D1>>>(W1, b1);
    k_scatter1<<<nb_edge8, TB>>>(ei, W1, b1);

    // layer 2: h2 = relu(g2 @ W2 + b2)
    {
        dim3 grid(D2 / BN, (N_NODES + BM - 1) / BM);
        sgemm_bias_relu<<<grid, 256>>>(g2, W2, b2, h2, N_NODES, D2, D1);
    }

    // layer 2 aggregation (input dim of layer 3)
    {
        size_t tot = (size_t)N_NODES * D2 / 4;
        k_g3_init<<<(unsigned)((tot + TB - 1) / TB), TB>>>();
        k_scatter2<<<nb_edge8, TB>>>(ei);
    }

    // layer 3: h3 = relu(g3 @ W3 + b3)
    {
        dim3 grid(D3 / BN, (N_NODES + BM - 1) / BM);
        sgemm_bias_relu<<<grid, 256>>>(g3, W3, b3, h3, N_NODES, D3, D2);
    }

    // mean pool + output linear
    {
        size_t tot = (size_t)N_NODES * D3 / 4;
        k_pool<<<(unsigned)((tot + TB - 1) / TB), TB>>>(batch);
    }
    k_final<<<NGRAPH, 256>>>(Wo, bo, out);
}

// round 5
// speedup vs baseline: 1.5375x; 1.5375x over previous
#include <cuda_runtime.h>
#include <cuda_bf16.h>
#include <cstdint>

#define N_NODES 30000
#define N_EDGES 240000
#define NGRAPH  16
#define D1      256
#define D2      512
#define D3      1024

// ---------------- scratch (no allocations allowed) ----------------
__device__ int   d_idx64;            // 1 if indices are int64, 0 if int32
__device__ float d_deg[N_NODES];
__device__ float d_dis[N_NODES];
__device__ float d_s1 [N_NODES];
__device__ float d_norm[N_EDGES];
__device__ __align__(16) float d_g2[N_NODES * D1];   // A_hat @ h1          [N,256]
__device__ __align__(16) float d_h2[N_NODES * D2];   // relu(g2@W2+b2)      [N,512]
__device__ __align__(16) float d_g3[N_NODES * D2];   // A_hat @ h2          [N,512]
__device__ __align__(16) float d_pool[NGRAPH * D3];
__device__ float d_cnt[NGRAPH];

// bf16 split operands for tensor-core GEMMs
__device__ __align__(16) __nv_bfloat16 d_a2hi[N_NODES * D1];
__device__ __align__(16) __nv_bfloat16 d_a2lo[N_NODES * D1];
__device__ __align__(16) __nv_bfloat16 d_a3hi[N_NODES * D2];
__device__ __align__(16) __nv_bfloat16 d_a3lo[N_NODES * D2];
__device__ __align__(16) __nv_bfloat16 d_b2hi[D2 * D1];   // [N=512, K=256] K-major
__device__ __align__(16) __nv_bfloat16 d_b2lo[D2 * D1];
__device__ __align__(16) __nv_bfloat16 d_b3hi[D3 * D2];   // [N=1024, K=512] K-major
__device__ __align__(16) __nv_bfloat16 d_b3lo[D3 * D2];

// ---------------- small helpers ----------------
__device__ __forceinline__ int load_idx(const void* p, int i) {
    if (d_idx64) return (int)((const long long*)p)[i];
    return ((const int*)p)[i];
}
__device__ __forceinline__ void red_add_v4(float* p, float4 v) {
    asm volatile("red.global.add.v4.f32 [%0], {%1,%2,%3,%4};"
                 :: "l"(p), "f"(v.x), "f"(v.y), "f"(v.z), "f"(v.w) : "memory");
}
__device__ __forceinline__ void red_add_v2(float* p, float x, float y) {
    asm volatile("red.global.add.v2.f32 [%0], {%1,%2};"
                 :: "l"(p), "f"(x), "f"(y) : "memory");
}
__device__ __forceinline__ uint32_t smem_u32(const void* p) {
    uint32_t a;
    asm("{ .reg .u64 t; cvta.to.shared.u64 t, %1; cvt.u32.u64 %0, t; }" : "=r"(a) : "l"(p));
    return a;
}
__device__ __forceinline__ uint32_t lds32(uint32_t addr) {
    uint32_t v;
    asm volatile("ld.shared.b32 %0, [%1];" : "=r"(v) : "r"(addr));
    return v;
}
__device__ __forceinline__ void mma16816(float* c, const uint32_t* a, const uint32_t* b) {
    asm volatile(
        "mma.sync.aligned.m16n8k16.row.col.f32.bf16.bf16.f32 "
        "{%0,%1,%2,%3}, {%4,%5,%6,%7}, {%8,%9}, {%0,%1,%2,%3};"
        : "+f"(c[0]), "+f"(c[1]), "+f"(c[2]), "+f"(c[3])
        : "r"(a[0]), "r"(a[1]), "r"(a[2]), "r"(a[3]), "r"(b[0]), "r"(b[1]));
}

// ---------------- dtype detection ----------------
__global__ void k_detect(const void* __restrict__ ei) {
    if (threadIdx.x != 0 || blockIdx.x != 0) return;
    const long long* p = (const long long*)ei;
    int ok = 1;
    for (int i = 0; i < 64; i++) {
        long long v = p[i];
        if (v < 0 || v >= N_NODES) { ok = 0; break; }
    }
    d_idx64 = ok;
}

// ---------------- degree / normalization ----------------
__global__ void k_init(void) {
    int i = blockIdx.x * blockDim.x + threadIdx.x;
    if (i < N_NODES) d_deg[i] = 1.0f;
    if (i < NGRAPH) d_cnt[i] = 0.0f;
    if (i < NGRAPH * D3) d_pool[i] = 0.0f;
}

__global__ void k_deg_edges(const void* __restrict__ ei) {
    int e = blockIdx.x * blockDim.x + threadIdx.x;
    if (e >= N_EDGES) return;
    atomicAdd(&d_deg[load_idx(ei, N_EDGES + e)], 1.0f);
}

__global__ void k_dis_s1(const float* __restrict__ x) {
    int i = blockIdx.x * blockDim.x + threadIdx.x;
    if (i >= N_NODES) return;
    float r = rsqrtf(d_deg[i]);
    d_dis[i] = r;
    d_s1[i]  = r * r * x[i];
}

__global__ void k_norm_s1(const void* __restrict__ ei, const float* __restrict__ x) {
    int e = blockIdx.x * blockDim.x + threadIdx.x;
    if (e >= N_EDGES) return;
    int s = load_idx(ei, e), d = load_idx(ei, N_EDGES + e);
    float nv = d_dis[s] * d_dis[d];
    d_norm[e] = nv;
    atomicAdd(&d_s1[d], nv * x[s]);
}

__global__ void k_cnt(const void* __restrict__ batch) {
    int i = blockIdx.x * blockDim.x + threadIdx.x;
    if (i >= N_NODES) return;
    atomicAdd(&d_cnt[load_idx(batch, i)], 1.0f);
}

// ---------------- layer 1 (rank-1) -> g2 ----------------
__global__ void k_g2_init(const float* __restrict__ W1, const float* __restrict__ b1) {
    int i = blockIdx.x;
    int f = threadIdx.x;
    float r = d_dis[i];
    float h = fmaxf(fmaf(d_s1[i], W1[f], b1[f]), 0.0f);
    d_g2[(size_t)i * D1 + f] = r * r * h;
}

__global__ void k_scatter1(const void* __restrict__ ei,
                           const float* __restrict__ W1, const float* __restrict__ b1) {
    __shared__ __align__(16) float sW[D1];
    __shared__ __align__(16) float sB[D1];
    int tid = threadIdx.x;
    sW[tid] = W1[tid];
    sB[tid] = b1[tid];
    __syncthreads();
    int warp = tid >> 5, lane = tid & 31;
    int e = blockIdx.x * 8 + warp;
    if (e >= N_EDGES) return;
    int src = load_idx(ei, e), dst = load_idx(ei, N_EDGES + e);
    float nv = d_norm[e];
    float s  = d_s1[src];
    float* gout = d_g2 + (size_t)dst * D1;
#pragma unroll
    for (int it = 0; it < 2; it++) {
        int f = it * 128 + lane * 4;
        float4 w = *(const float4*)&sW[f];
        float4 b = *(const float4*)&sB[f];
        float4 v;
        v.x = nv * fmaxf(fmaf(s, w.x, b.x), 0.0f);
        v.y = nv * fmaxf(fmaf(s, w.y, b.y), 0.0f);
        v.z = nv * fmaxf(fmaf(s, w.z, b.z), 0.0f);
        v.w = nv * fmaxf(fmaf(s, w.w, b.w), 0.0f);
        red_add_v4(gout + f, v);
    }
}

// ---------------- layer 2 edge scatter (g3 self-loop done in GEMM2 epilogue) ----------------
__global__ void k_scatter2(const void* __restrict__ ei) {
    int tid = threadIdx.x;
    int warp = tid >> 5, lane = tid & 31;
    int e = blockIdx.x * 8 + warp;
    if (e >= N_EDGES) return;
    int src = load_idx(ei, e), dst = load_idx(ei, N_EDGES + e);
    float nv = d_norm[e];
    const float* hin = d_h2 + (size_t)src * D2;
    float* gout = d_g3 + (size_t)dst * D2;
#pragma unroll
    for (int it = 0; it < 4; it++) {
        int f = it * 128 + lane * 4;
        float4 v = *(const float4*)&hin[f];
        v.x *= nv; v.y *= nv; v.z *= nv; v.w *= nv;
        red_add_v4(gout + f, v);
    }
}

// ---------------- fp32 -> bf16 hi/lo split ----------------
__global__ void k_split(const float* __restrict__ in, __nv_bfloat16* __restrict__ hi,
                        __nv_bfloat16* __restrict__ lo, int n) {
    int i = blockIdx.x * blockDim.x + threadIdx.x;
    if (i >= n) return;
    float v = in[i];
    __nv_bfloat16 h = __float2bfloat16(v);
    hi[i] = h;
    lo[i] = __float2bfloat16(v - __bfloat162float(h));
}

// W [K, N] fp32 row-major -> B [N, K] bf16 hi/lo (transposed, K-major)
__global__ void k_wsplit(const float* __restrict__ W, __nv_bfloat16* __restrict__ bhi,
                         __nv_bfloat16* __restrict__ blo, int K, int N) {
    int idx = blockIdx.x * blockDim.x + threadIdx.x;
    if (idx >= N * K) return;
    int n = idx / K, k = idx - n * K;
    float v = W[(size_t)k * N + n];
    __nv_bfloat16 h = __float2bfloat16(v);
    bhi[idx] = h;
    blo[idx] = __float2bfloat16(v - __bfloat162float(h));
}

// ---------------- bf16-split GEMM via mma.sync (m16n8k16), 128x128 tiles ----------------
// D = A @ W, A = Ahi+Alo [M,K] row-major, W^T rows = Bhi+Blo [Nglob,K] K-major.
// Three products: Ahi*Bhi + Alo*Bhi + Ahi*Blo (fp32 accumulate).
// mode 0: h2 = relu(D+bias); g3 = dis^2 * h2      (layer 2)
// mode 1: relu(D+bias) pooled into d_pool[batch]  (layer 3, h3 never materialized)
__global__ __launch_bounds__(256, 2)
void mma_gemm(const __nv_bfloat16* __restrict__ Ahi, const __nv_bfloat16* __restrict__ Alo,
              const __nv_bfloat16* __restrict__ Bhi, const __nv_bfloat16* __restrict__ Blo,
              const float* __restrict__ bias, const void* __restrict__ batch,
              int M, int Nglob, int K, int mode) {
    // 128 rows x 64 bf16 (128B rows), 16B-group XOR swizzle -> conflict-free
    __shared__ __align__(16) __nv_bfloat16 smA[128 * 64];
    __shared__ __align__(16) __nv_bfloat16 smB[128 * 64];

    const int tid = threadIdx.x;
    const int wid = tid >> 5, lane = tid & 31;
    const int g = lane >> 2, tig = lane & 3;
    const int warp_m = wid & 3, warp_n = wid >> 2;
    const int row0 = blockIdx.y * 128, col0 = blockIdx.x * 128;
    const int mr = warp_m * 32, nc = warp_n * 64;

    const uint32_t Abase = smem_u32(smA);
    const uint32_t Bbase = smem_u32(smB);

    float acc[2][8][4];
#pragma unroll
    for (int mf = 0; mf < 2; mf++)
#pragma unroll
        for (int nf = 0; nf < 8; nf++)
#pragma unroll
            for (int q = 0; q < 4; q++) acc[mf][nf][q] = 0.0f;

    const int nk = K >> 6;
    for (int c = 0; c < 3 * nk; c++) {
        const __nv_bfloat16 *Ap, *Bp;
        int kc;
        if (c < nk)          { Ap = Ahi; Bp = Bhi; kc = c; }
        else if (c < 2 * nk) { Ap = Alo; Bp = Bhi; kc = c - nk; }
        else                 { Ap = Ahi; Bp = Blo; kc = c - 2 * nk; }
        const int kof = kc << 6;

        __syncthreads();
#pragma unroll
        for (int it = 0; it < 4; it++) {
            int idx = it * 256 + tid;                 // 0..1023
            int r = idx >> 3, ch = idx & 7;           // row, 16B-chunk
            uint32_t soff = (uint32_t)(r * 128 + ((ch ^ (r & 7)) << 4));
            uint4 va = make_uint4(0u, 0u, 0u, 0u);
            int grow = row0 + r;
            if (grow < M) va = *(const uint4*)(Ap + (size_t)grow * K + kof + ch * 8);
            *(uint4*)((char*)smA + soff) = va;
            uint4 vb = *(const uint4*)(Bp + (size_t)(col0 + r) * K + kof + ch * 8);
            *(uint4*)((char*)smB + soff) = vb;
        }
        __syncthreads();

#pragma unroll
        for (int ks = 0; ks < 4; ks++) {
            const int grp = ks * 2;                   // 16B group of k-step (k = ks*16)
            uint32_t a[2][4];
#pragma unroll
            for (int mf = 0; mf < 2; mf++) {
                int r = mr + mf * 16 + g;
                uint32_t sw0 = (uint32_t)(((grp)     ^ (r & 7)) << 4);
                uint32_t sw1 = (uint32_t)(((grp + 1) ^ (r & 7)) << 4);
                uint32_t base = Abase + r * 128 + tig * 4;
                a[mf][0] = lds32(base + sw0);               // A[r][k..k+1]
                a[mf][2] = lds32(base + sw1);               // A[r][k+8..k+9]
                a[mf][1] = lds32(base + 8 * 128 + sw0);     // A[r+8][k..k+1]
                a[mf][3] = lds32(base + 8 * 128 + sw1);     // A[r+8][k+8..k+9]
            }
            uint32_t b[8][2];
#pragma unroll
            for (int nf = 0; nf < 8; nf++) {
                int n = nc + nf * 8 + g;
                uint32_t sw0 = (uint32_t)(((grp)     ^ (n & 7)) << 4);
                uint32_t sw1 = (uint32_t)(((grp + 1) ^ (n & 7)) << 4);
                uint32_t base = Bbase + n * 128 + tig * 4;
                b[nf][0] = lds32(base + sw0);               // B[n][k..k+1]
                b[nf][1] = lds32(base + sw1);               // B[n][k+8..k+9]
            }
#pragma unroll
            for (int mf = 0; mf < 2; mf++)
#pragma unroll
                for (int nf = 0; nf < 8; nf++)
                    mma16816(acc[mf][nf], a[mf], b[nf]);
        }
    }

    // ---------------- epilogue ----------------
    if (mode == 0) {
#pragma unroll
        for (int mf = 0; mf < 2; mf++) {
#pragma unroll
            for (int half = 0; half < 2; half++) {
                int row = row0 + mr + mf * 16 + g + half * 8;
                if (row >= M) continue;
                float r = d_dis[row];
                float r2 = r * r;
#pragma unroll
                for (int nf = 0; nf < 8; nf++) {
                    int col = col0 + nc + nf * 8 + tig * 2;
                    float2 bv = *(const float2*)&bias[col];
                    float v0 = fmaxf(acc[mf][nf][half * 2 + 0] + bv.x, 0.0f);
                    float v1 = fmaxf(acc[mf][nf][half * 2 + 1] + bv.y, 0.0f);
                    float* h2p = d_h2 + (size_t)row * D2 + col;
                    float* g3p = d_g3 + (size_t)row * D2 + col;
                    *(float2*)h2p = make_float2(v0, v1);
                    *(float2*)g3p = make_float2(r2 * v0, r2 * v1);
                }
            }
        }
    } else {
        // relu+bias with row-validity masking, in place
#pragma unroll
        for (int mf = 0; mf < 2; mf++) {
            int ra = row0 + mr + mf * 16 + g;
            int v0ok = (ra < M), v1ok = (ra + 8 < M);
#pragma unroll
            for (int nf = 0; nf < 8; nf++) {
                int col = col0 + nc + nf * 8 + tig * 2;
                float2 bv = *(const float2*)&bias[col];
                acc[mf][nf][0] = v0ok ? fmaxf(acc[mf][nf][0] + bv.x, 0.0f) : 0.0f;
                acc[mf][nf][1] = v0ok ? fmaxf(acc[mf][nf][1] + bv.y, 0.0f) : 0.0f;
                acc[mf][nf][2] = v1ok ? fmaxf(acc[mf][nf][2] + bv.x, 0.0f) : 0.0f;
                acc[mf][nf][3] = v1ok ? fmaxf(acc[mf][nf][3] + bv.y, 0.0f) : 0.0f;
            }
        }
        unsigned mask = 0xffffffffu;
        int rv = row0 + mr + lane;                    // lane-th row of this warp's 32 rows
        int bl = (rv < N_NODES) ? load_idx(batch, rv) : -1;
        int b0 = __shfl_sync(mask, bl, 0);
        bool uni = __all_sync(mask, bl == b0);
        if (uni && b0 >= 0) {
            // sum rows in-lane (2 mfrags x 2 halves), then over g via shfl tree
            float s[8][2];
#pragma unroll
            for (int nf = 0; nf < 8; nf++) {
                s[nf][0] = acc[0][nf][0] + acc[0][nf][2] + acc[1][nf][0] + acc[1][nf][2];
                s[nf][1] = acc[0][nf][1] + acc[0][nf][3] + acc[1][nf][1] + acc[1][nf][3];
            }
#pragma unroll
            for (int off = 4; off < 32; off <<= 1)
#pragma unroll
                for (int nf = 0; nf < 8; nf++) {
                    s[nf][0] += __shfl_xor_sync(mask, s[nf][0], off);
                    s[nf][1] += __shfl_xor_sync(mask, s[nf][1], off);
                }
            if (lane < 4) {
#pragma unroll
                for (int nf = 0; nf < 8; nf++) {
                    int col = col0 + nc + nf * 8 + lane * 2;
                    red_add_v2(&d_pool[(size_t)b0 * D3 + col], s[nf][0], s[nf][1]);
                }
            }
        } else {
            // boundary warp: per-row atomics (rare)
#pragma unroll
            for (int mf = 0; mf < 2; mf++)
#pragma unroll
                for (int half = 0; half < 2; half++) {
                    int row = row0 + mr + mf * 16 + g + half * 8;
                    if (row >= M) continue;
                    int gb = load_idx(batch, row);
#pragma unroll
                    for (int nf = 0; nf < 8; nf++) {
                        int col = col0 + nc + nf * 8 + tig * 2;
                        red_add_v2(&d_pool[(size_t)gb * D3 + col],
                                   acc[mf][nf][half * 2], acc[mf][nf][half * 2 + 1]);
                    }
                }
        }
    }
}

// ---------------- final linear [16,1024] @ [1024,1024] ----------------
__global__ void k_final(const float* __restrict__ Wo, const float* __restrict__ bo,
                        float* __restrict__ out) {
    __shared__ float p[D3];
    int g = blockIdx.x, tid = threadIdx.x;
    float inv = 1.0f / fmaxf(d_cnt[g], 1.0f);
    for (int j = tid; j < D3; j += 256) p[j] = d_pool[(size_t)g * D3 + j] * inv;
    __syncthreads();
    float a0 = 0.f, a1 = 0.f, a2 = 0.f, a3 = 0.f;
#pragma unroll 4
    for (int k = 0; k < D3; k++) {
        float pv = p[k];
        const float* w = Wo + (size_t)k * D3;
        a0 = fmaf(pv, w[tid + 0],   a0);
        a1 = fmaf(pv, w[tid + 256], a1);
        a2 = fmaf(pv, w[tid + 512], a2);
        a3 = fmaf(pv, w[tid + 768], a3);
    }
    out[g * D3 + tid + 0]   = a0 + bo[tid + 0];
    out[g * D3 + tid + 256] = a1 + bo[tid + 256];
    out[g * D3 + tid + 512] = a2 + bo[tid + 512];
    out[g * D3 + tid + 768] = a3 + bo[tid + 768];
}

// ---------------- launcher ----------------
extern "C" void kernel_launch(void* const* d_in, const int* in_sizes, int n_in,
                              void* d_out, int out_size) {
    const float *x, *W1, *b1, *W2, *b2, *W3, *b3, *Wo, *bo;
    const void *ei, *batch;
    if (in_sizes[0] == N_NODES) {           // dict order
        x     = (const float*)d_in[0];
        ei    = d_in[1];
        batch = d_in[2];
        W1 = (const float*)d_in[3];  b1 = (const float*)d_in[4];
        W2 = (const float*)d_in[5];  b2 = (const float*)d_in[6];
        W3 = (const float*)d_in[7];  b3 = (const float*)d_in[8];
        Wo = (const float*)d_in[9];  bo = (const float*)d_in[10];
    } else {                                // alphabetical order
        W1 = (const float*)d_in[0];
        W2 = (const float*)d_in[1];
        W3 = (const float*)d_in[2];
        Wo = (const float*)d_in[3];
        b1 = (const float*)d_in[4];
        b2 = (const float*)d_in[5];
        b3 = (const float*)d_in[6];
        batch = d_in[7];
        bo = (const float*)d_in[8];
        ei = d_in[9];
        x  = (const float*)d_in[10];
    }
    float* out = (float*)d_out;

    float *g2, *g3;
    __nv_bfloat16 *a2hi, *a2lo, *a3hi, *a3lo, *b2hi, *b2lo, *b3hi, *b3lo;
    cudaGetSymbolAddress((void**)&g2, d_g2);
    cudaGetSymbolAddress((void**)&g3, d_g3);
    cudaGetSymbolAddress((void**)&a2hi, d_a2hi);
    cudaGetSymbolAddress((void**)&a2lo, d_a2lo);
    cudaGetSymbolAddress((void**)&a3hi, d_a3hi);
    cudaGetSymbolAddress((void**)&a3lo, d_a3lo);
    cudaGetSymbolAddress((void**)&b2hi, d_b2hi);
    cudaGetSymbolAddress((void**)&b2lo, d_b2lo);
    cudaGetSymbolAddress((void**)&b3hi, d_b3hi);
    cudaGetSymbolAddress((void**)&b3lo, d_b3lo);

    const int TB = 256;
    int nb_nodes = (N_NODES + TB - 1) / TB;
    int nb_edges = (N_EDGES + TB - 1) / TB;
    int nb_edge8 = (N_EDGES + 7) / 8;

    k_detect<<<1, 32>>>(ei);
    k_init<<<nb_nodes, TB>>>();
    k_deg_edges<<<nb_edges, TB>>>(ei);
    k_dis_s1<<<nb_nodes, TB>>>(x);
    k_norm_s1<<<nb_edges, TB>>>(ei, x);
    k_cnt<<<nb_nodes, TB>>>(batch);

    // weight transposition + bf16 split (independent of graph pipeline)
    k_wsplit<<<(D2 * D1 + TB - 1) / TB, TB>>>(W2, b2hi, b2lo, D1, D2);
    k_wsplit<<<(D3 * D2 + TB - 1) / TB, TB>>>(W3, b3hi, b3lo, D2, D3);

    // layer 1 (rank-1) aggregated into input dim of layer 2
    k_g2_init<<<N_NODES, D1>>>(W1, b1);
    k_scatter1<<<nb_edge8, TB>>>(ei, W1, b1);
    k_split<<<(N_NODES * D1 + TB - 1) / TB, TB>>>(g2, a2hi, a2lo, N_NODES * D1);

    // layer 2 GEMM (mma.sync bf16-split): writes h2 + g3 self-loop term
    {
        dim3 grid(D2 / 128, (N_NODES + 127) / 128);
        mma_gemm<<<grid, 256>>>(a2hi, a2lo, b2hi, b2lo, b2, nullptr, N_NODES, D2, D1, 0);
    }

    // layer 2 aggregation
    k_scatter2<<<nb_edge8, TB>>>(ei);
    k_split<<<(N_NODES * D2 + TB - 1) / TB, TB>>>(g3, a3hi, a3lo, N_NODES * D2);

    // layer 3 GEMM (mma.sync bf16-split) with fused pooling
    {
        dim3 grid(D3 / 128, (N_NODES + 127) / 128);
        mma_gemm<<<grid, 256>>>(a3hi, a3lo, b3hi, b3lo, b3, batch, N_NODES, D3, D2, 1);
    }

    k_final<<<NGRAPH, 256>>>(Wo, bo, out);
}

// round 6
// speedup vs baseline: 1.5793x; 1.0272x over previous
#include <cuda_runtime.h>
#include <cuda_bf16.h>
#include <cstdint>

#define N_NODES 30000
#define N_EDGES 240000
#define NGRAPH  16
#define D1      256
#define D2      512
#define D3      1024

// ---------------- scratch (no allocations allowed) ----------------
__device__ int   d_idx64;            // 1 if indices are int64, 0 if int32
__device__ float d_deg[N_NODES];
__device__ float d_dis[N_NODES];
__device__ float d_s1 [N_NODES];
__device__ float d_norm[N_EDGES];
__device__ __align__(16) float d_g2[N_NODES * D1];   // A_hat @ h1          [N,256]
__device__ __align__(16) float d_h2[N_NODES * D2];   // relu(g2@W2+b2)      [N,512]
__device__ __align__(16) float d_g3[N_NODES * D2];   // A_hat @ h2          [N,512]
__device__ __align__(16) float d_pool[NGRAPH * D3];
__device__ float d_cnt[NGRAPH];

// bf16 split operands for tensor-core GEMMs
__device__ __align__(16) __nv_bfloat16 d_a2hi[N_NODES * D1];
__device__ __align__(16) __nv_bfloat16 d_a2lo[N_NODES * D1];
__device__ __align__(16) __nv_bfloat16 d_a3hi[N_NODES * D2];
__device__ __align__(16) __nv_bfloat16 d_a3lo[N_NODES * D2];
__device__ __align__(16) __nv_bfloat16 d_b2hi[D2 * D1];   // [N=512, K=256] K-major
__device__ __align__(16) __nv_bfloat16 d_b2lo[D2 * D1];
__device__ __align__(16) __nv_bfloat16 d_b3hi[D3 * D2];   // [N=1024, K=512] K-major
__device__ __align__(16) __nv_bfloat16 d_b3lo[D3 * D2];

// ---------------- small helpers ----------------
__device__ __forceinline__ int load_idx(const void* p, int i) {
    if (d_idx64) return (int)((const long long*)p)[i];
    return ((const int*)p)[i];
}
__device__ __forceinline__ void red_add_v4(float* p, float4 v) {
    asm volatile("red.global.add.v4.f32 [%0], {%1,%2,%3,%4};"
                 :: "l"(p), "f"(v.x), "f"(v.y), "f"(v.z), "f"(v.w) : "memory");
}
__device__ __forceinline__ void red_add_v2(float* p, float x, float y) {
    asm volatile("red.global.add.v2.f32 [%0], {%1,%2};"
                 :: "l"(p), "f"(x), "f"(y) : "memory");
}
__device__ __forceinline__ uint32_t smem_u32(const void* p) {
    uint32_t a;
    asm("{ .reg .u64 t; cvta.to.shared.u64 t, %1; cvt.u32.u64 %0, t; }" : "=r"(a) : "l"(p));
    return a;
}
__device__ __forceinline__ void ldm_x4(uint32_t* r, uint32_t addr) {
    asm volatile("ldmatrix.sync.aligned.m8n8.x4.shared.b16 {%0,%1,%2,%3}, [%4];"
                 : "=r"(r[0]), "=r"(r[1]), "=r"(r[2]), "=r"(r[3]) : "r"(addr));
}
__device__ __forceinline__ void cp_async16(uint32_t dst, const void* src, uint32_t srcsize) {
    asm volatile("cp.async.cg.shared.global [%0], [%1], 16, %2;"
                 :: "r"(dst), "l"(src), "r"(srcsize) : "memory");
}
__device__ __forceinline__ void cp_commit(void) {
    asm volatile("cp.async.commit_group;" ::: "memory");
}
__device__ __forceinline__ void mma16816(float* c, const uint32_t* a, uint32_t b0, uint32_t b1) {
    asm volatile(
        "mma.sync.aligned.m16n8k16.row.col.f32.bf16.bf16.f32 "
        "{%0,%1,%2,%3}, {%4,%5,%6,%7}, {%8,%9}, {%0,%1,%2,%3};"
        : "+f"(c[0]), "+f"(c[1]), "+f"(c[2]), "+f"(c[3])
        : "r"(a[0]), "r"(a[1]), "r"(a[2]), "r"(a[3]), "r"(b0), "r"(b1));
}

// ---------------- dtype detection ----------------
__global__ void k_detect(const void* __restrict__ ei) {
    if (threadIdx.x != 0 || blockIdx.x != 0) return;
    const long long* p = (const long long*)ei;
    int ok = 1;
    for (int i = 0; i < 64; i++) {
        long long v = p[i];
        if (v < 0 || v >= N_NODES) { ok = 0; break; }
    }
    d_idx64 = ok;
}

// ---------------- degree / normalization ----------------
__global__ void k_init(void) {
    int i = blockIdx.x * blockDim.x + threadIdx.x;
    if (i < N_NODES) d_deg[i] = 1.0f;
    if (i < NGRAPH) d_cnt[i] = 0.0f;
    if (i < NGRAPH * D3) d_pool[i] = 0.0f;
}

__global__ void k_deg_edges(const void* __restrict__ ei) {
    int e = blockIdx.x * blockDim.x + threadIdx.x;
    if (e >= N_EDGES) return;
    atomicAdd(&d_deg[load_idx(ei, N_EDGES + e)], 1.0f);
}

__global__ void k_dis_s1(const float* __restrict__ x) {
    int i = blockIdx.x * blockDim.x + threadIdx.x;
    if (i >= N_NODES) return;
    float r = rsqrtf(d_deg[i]);
    d_dis[i] = r;
    d_s1[i]  = r * r * x[i];
}

__global__ void k_norm_s1(const void* __restrict__ ei, const float* __restrict__ x) {
    int e = blockIdx.x * blockDim.x + threadIdx.x;
    if (e >= N_EDGES) return;
    int s = load_idx(ei, e), d = load_idx(ei, N_EDGES + e);
    float nv = d_dis[s] * d_dis[d];
    d_norm[e] = nv;
    atomicAdd(&d_s1[d], nv * x[s]);
}

__global__ void k_cnt(const void* __restrict__ batch) {
    int i = blockIdx.x * blockDim.x + threadIdx.x;
    if (i >= N_NODES) return;
    atomicAdd(&d_cnt[load_idx(batch, i)], 1.0f);
}

// ---------------- layer 1 (rank-1) -> g2 ----------------
__global__ void k_g2_init(const float* __restrict__ W1, const float* __restrict__ b1) {
    int i = blockIdx.x;
    int f = threadIdx.x;
    float r = d_dis[i];
    float h = fmaxf(fmaf(d_s1[i], W1[f], b1[f]), 0.0f);
    d_g2[(size_t)i * D1 + f] = r * r * h;
}

__global__ void k_scatter1(const void* __restrict__ ei,
                           const float* __restrict__ W1, const float* __restrict__ b1) {
    __shared__ __align__(16) float sW[D1];
    __shared__ __align__(16) float sB[D1];
    int tid = threadIdx.x;
    sW[tid] = W1[tid];
    sB[tid] = b1[tid];
    __syncthreads();
    int warp = tid >> 5, lane = tid & 31;
    int e = blockIdx.x * 8 + warp;
    if (e >= N_EDGES) return;
    int src = load_idx(ei, e), dst = load_idx(ei, N_EDGES + e);
    float nv = d_norm[e];
    float s  = d_s1[src];
    float* gout = d_g2 + (size_t)dst * D1;
#pragma unroll
    for (int it = 0; it < 2; it++) {
        int f = it * 128 + lane * 4;
        float4 w = *(const float4*)&sW[f];
        float4 b = *(const float4*)&sB[f];
        float4 v;
        v.x = nv * fmaxf(fmaf(s, w.x, b.x), 0.0f);
        v.y = nv * fmaxf(fmaf(s, w.y, b.y), 0.0f);
        v.z = nv * fmaxf(fmaf(s, w.z, b.z), 0.0f);
        v.w = nv * fmaxf(fmaf(s, w.w, b.w), 0.0f);
        red_add_v4(gout + f, v);
    }
}

// ---------------- layer 2 edge scatter ----------------
__global__ void k_scatter2(const void* __restrict__ ei) {
    int tid = threadIdx.x;
    int warp = tid >> 5, lane = tid & 31;
    int e = blockIdx.x * 8 + warp;
    if (e >= N_EDGES) return;
    int src = load_idx(ei, e), dst = load_idx(ei, N_EDGES + e);
    float nv = d_norm[e];
    const float* hin = d_h2 + (size_t)src * D2;
    float* gout = d_g3 + (size_t)dst * D2;
#pragma unroll
    for (int it = 0; it < 4; it++) {
        int f = it * 128 + lane * 4;
        float4 v = *(const float4*)&hin[f];
        v.x *= nv; v.y *= nv; v.z *= nv; v.w *= nv;
        red_add_v4(gout + f, v);
    }
}

// ---------------- fp32 -> bf16 hi/lo split ----------------
__global__ void k_split(const float* __restrict__ in, __nv_bfloat16* __restrict__ hi,
                        __nv_bfloat16* __restrict__ lo, int n) {
    int i = blockIdx.x * blockDim.x + threadIdx.x;
    if (i >= n) return;
    float v = in[i];
    __nv_bfloat16 h = __float2bfloat16(v);
    hi[i] = h;
    lo[i] = __float2bfloat16(v - __bfloat162float(h));
}

// W [K, N] fp32 row-major -> B [N, K] bf16 hi/lo (transposed, K-major)
__global__ void k_wsplit(const float* __restrict__ W, __nv_bfloat16* __restrict__ bhi,
                         __nv_bfloat16* __restrict__ blo, int K, int N) {
    int idx = blockIdx.x * blockDim.x + threadIdx.x;
    if (idx >= N * K) return;
    int n = idx / K, k = idx - n * K;
    float v = W[(size_t)k * N + n];
    __nv_bfloat16 h = __float2bfloat16(v);
    bhi[idx] = h;
    blo[idx] = __float2bfloat16(v - __bfloat162float(h));
}

// ---------------- bf16-split GEMM: ldmatrix + cp.async double buffer ----------------
// D = A @ W, A = Ahi+Alo [M,K] row-major, W^T rows = Bhi+Blo [Nglob,K] K-major.
// Three products: Ahi*Bhi + Alo*Bhi + Ahi*Blo (fp32 accumulate).
// Dynamic smem: 2 stages x (smA 16KB + smB 16KB) = 64KB.
// mode 0: h2 = relu(D+bias); g3 = dis^2 * h2      (layer 2)
// mode 1: relu(D+bias) pooled into d_pool[batch]  (layer 3, h3 never materialized)
__global__ __launch_bounds__(256, 2)
void mma_gemm(const __nv_bfloat16* __restrict__ Ahi, const __nv_bfloat16* __restrict__ Alo,
              const __nv_bfloat16* __restrict__ Bhi, const __nv_bfloat16* __restrict__ Blo,
              const float* __restrict__ bias, const void* __restrict__ batch,
              int M, int Nglob, int K, int mode) {
    extern __shared__ __align__(16) char dynsm[];

    const int tid = threadIdx.x;
    const int wid = tid >> 5, lane = tid & 31;
    const int g = lane >> 2, tig = lane & 3;
    const int warp_m = wid & 3, warp_n = wid >> 2;
    const int row0 = blockIdx.y * 128, col0 = blockIdx.x * 128;
    const int mr = warp_m * 32, nc = warp_n * 64;

    // ldmatrix lane mapping: tile t = lane>>3, row-in-tile = lane&7
    const int t   = lane >> 3;
    const int thi = t >> 1;                   // k-high (bit selects k+8 group)
    const int rlo = (t & 1) * 8 + (lane & 7); // row within 16-row tile pair

    const uint32_t smbase = smem_u32(dynsm);
    // per-stage offsets
    const uint32_t stA[2] = { smbase, smbase + 32768u };
    const uint32_t stB[2] = { smbase + 16384u, smbase + 49152u };

    // A fragment row constants (per mf)
    int rA0 = mr + rlo, rA1 = mr + 16 + rlo;
    uint32_t aoff0 = (uint32_t)(rA0 * 128), amask0 = (uint32_t)(rA0 & 7);
    uint32_t aoff1 = (uint32_t)(rA1 * 128), amask1 = (uint32_t)(rA1 & 7);
    // B fragment row constants (per pair p: n rows nc + p*16 + rlo)
    uint32_t boff[4], bmask[4];
#pragma unroll
    for (int p = 0; p < 4; p++) {
        int rB = nc + p * 16 + rlo;
        boff[p] = (uint32_t)(rB * 128);
        bmask[p] = (uint32_t)(rB & 7);
    }

    float acc[2][8][4];
#pragma unroll
    for (int mf = 0; mf < 2; mf++)
#pragma unroll
        for (int nf = 0; nf < 8; nf++)
#pragma unroll
            for (int q = 0; q < 4; q++) acc[mf][nf][q] = 0.0f;

    const int nk = K >> 6;
    const int nchunks = 3 * nk;

    // async tile loader: 8x cp.async per thread (4 A + 4 B)
    const int lr = tid >> 1;                 // 0..127 (two chunks per row)
    const int lc2 = (tid & 1) * 4;           // chunk pair base: 0 or 4
    auto prefetch = [&](int c, int s) {
        const __nv_bfloat16 *Ap, *Bp;
        int kc;
        if (c < nk)          { Ap = Ahi; Bp = Bhi; kc = c; }
        else if (c < 2 * nk) { Ap = Alo; Bp = Bhi; kc = c - nk; }
        else                 { Ap = Ahi; Bp = Blo; kc = c - 2 * nk; }
        const int kof = kc << 6;
        int grow = row0 + lr;
        uint32_t asz = (grow < M) ? 16u : 0u;
        const __nv_bfloat16* agp = Ap + (size_t)grow * K + kof + lc2 * 8;
        const __nv_bfloat16* bgp = Bp + (size_t)(col0 + lr) * K + kof + lc2 * 8;
        uint32_t arow = (uint32_t)(lr * 128);
#pragma unroll
        for (int j = 0; j < 4; j++) {
            int ch = lc2 + j;
            uint32_t soff = arow + (uint32_t)(((ch ^ (lr & 7)) << 4));
            cp_async16(stA[s] + soff, agp + j * 8, asz);
            cp_async16(stB[s] + soff, bgp + j * 8, 16u);
        }
        cp_commit();
    };

    prefetch(0, 0);
    for (int c = 0; c < nchunks; c++) {
        const int s = c & 1;
        if (c + 1 < nchunks) {
            prefetch(c + 1, (c + 1) & 1);
            asm volatile("cp.async.wait_group 1;" ::: "memory");
        } else {
            asm volatile("cp.async.wait_group 0;" ::: "memory");
        }
        __syncthreads();

#pragma unroll
        for (int ks = 0; ks < 4; ks++) {
            const uint32_t kg = (uint32_t)(2 * ks + thi);
            uint32_t a0[4], a1[4];
            ldm_x4(a0, stA[s] + aoff0 + (((kg ^ amask0) << 4)));
            ldm_x4(a1, stA[s] + aoff1 + (((kg ^ amask1) << 4)));
#pragma unroll
            for (int p = 0; p < 4; p++) {
                uint32_t bfr[4];
                ldm_x4(bfr, stB[s] + boff[p] + (((kg ^ bmask[p]) << 4)));
                mma16816(acc[0][2 * p + 0], a0, bfr[0], bfr[2]);
                mma16816(acc[0][2 * p + 1], a0, bfr[1], bfr[3]);
                mma16816(acc[1][2 * p + 0], a1, bfr[0], bfr[2]);
                mma16816(acc[1][2 * p + 1], a1, bfr[1], bfr[3]);
            }
        }
        __syncthreads();
    }

    // ---------------- epilogue ----------------
    if (mode == 0) {
#pragma unroll
        for (int mf = 0; mf < 2; mf++) {
#pragma unroll
            for (int half = 0; half < 2; half++) {
                int row = row0 + mr + mf * 16 + g + half * 8;
                if (row >= M) continue;
                float r = d_dis[row];
                float r2 = r * r;
#pragma unroll
                for (int nf = 0; nf < 8; nf++) {
                    int col = col0 + nc + nf * 8 + tig * 2;
                    float2 bv = *(const float2*)&bias[col];
                    float v0 = fmaxf(acc[mf][nf][half * 2 + 0] + bv.x, 0.0f);
                    float v1 = fmaxf(acc[mf][nf][half * 2 + 1] + bv.y, 0.0f);
                    float* h2p = d_h2 + (size_t)row * D2 + col;
                    float* g3p = d_g3 + (size_t)row * D2 + col;
                    *(float2*)h2p = make_float2(v0, v1);
                    *(float2*)g3p = make_float2(r2 * v0, r2 * v1);
                }
            }
        }
    } else {
#pragma unroll
        for (int mf = 0; mf < 2; mf++) {
            int ra = row0 + mr + mf * 16 + g;
            int v0ok = (ra < M), v1ok = (ra + 8 < M);
#pragma unroll
            for (int nf = 0; nf < 8; nf++) {
                int col = col0 + nc + nf * 8 + tig * 2;
                float2 bv = *(const float2*)&bias[col];
                acc[mf][nf][0] = v0ok ? fmaxf(acc[mf][nf][0] + bv.x, 0.0f) : 0.0f;
                acc[mf][nf][1] = v0ok ? fmaxf(acc[mf][nf][1] + bv.y, 0.0f) : 0.0f;
                acc[mf][nf][2] = v1ok ? fmaxf(acc[mf][nf][2] + bv.x, 0.0f) : 0.0f;
                acc[mf][nf][3] = v1ok ? fmaxf(acc[mf][nf][3] + bv.y, 0.0f) : 0.0f;
            }
        }
        unsigned mask = 0xffffffffu;
        int rv = row0 + mr + lane;
        int bl = (rv < N_NODES) ? load_idx(batch, rv) : -1;
        int b0 = __shfl_sync(mask, bl, 0);
        bool uni = __all_sync(mask, bl == b0);
        if (uni && b0 >= 0) {
            float s[8][2];
#pragma unroll
            for (int nf = 0; nf < 8; nf++) {
                s[nf][0] = acc[0][nf][0] + acc[0][nf][2] + acc[1][nf][0] + acc[1][nf][2];
                s[nf][1] = acc[0][nf][1] + acc[0][nf][3] + acc[1][nf][1] + acc[1][nf][3];
            }
#pragma unroll
            for (int off = 4; off < 32; off <<= 1)
#pragma unroll
                for (int nf = 0; nf < 8; nf++) {
                    s[nf][0] += __shfl_xor_sync(mask, s[nf][0], off);
                    s[nf][1] += __shfl_xor_sync(mask, s[nf][1], off);
                }
            if (lane < 4) {
#pragma unroll
                for (int nf = 0; nf < 8; nf++) {
                    int col = col0 + nc + nf * 8 + lane * 2;
                    red_add_v2(&d_pool[(size_t)b0 * D3 + col], s[nf][0], s[nf][1]);
                }
            }
        } else {
#pragma unroll
            for (int mf = 0; mf < 2; mf++)
#pragma unroll
                for (int half = 0; half < 2; half++) {
                    int row = row0 + mr + mf * 16 + g + half * 8;
                    if (row >= M) continue;
                    int gb = load_idx(batch, row);
#pragma unroll
                    for (int nf = 0; nf < 8; nf++) {
                        int col = col0 + nc + nf * 8 + tig * 2;
                        red_add_v2(&d_pool[(size_t)gb * D3 + col],
                                   acc[mf][nf][half * 2], acc[mf][nf][half * 2 + 1]);
                    }
                }
        }
    }
}

// ---------------- final linear [16,1024] @ [1024,1024] ----------------
// 4 blocks x 256 threads; thread owns one output column, 16 graph accumulators.
// Pooled staged in smem as [k][16] so inner loop is 4x LDS128 broadcast + 16 FMA.
__global__ void k_final(const float* __restrict__ Wo, const float* __restrict__ bo,
                        float* __restrict__ out) {
    __shared__ __align__(16) float sp[256][NGRAPH];   // 16KB chunk
    __shared__ float sinv[NGRAPH];
    int tid = threadIdx.x;
    int c = blockIdx.x * 256 + tid;
    if (tid < NGRAPH) sinv[tid] = 1.0f / fmaxf(d_cnt[tid], 1.0f);
    float acc[NGRAPH];
#pragma unroll
    for (int g = 0; g < NGRAPH; g++) acc[g] = 0.0f;

    for (int kc = 0; kc < D3 / 256; kc++) {
        __syncthreads();
        for (int i = tid; i < 256 * NGRAPH; i += 256) {
            int k = i >> 4, g = i & 15;
            sp[k][g] = d_pool[(size_t)g * D3 + kc * 256 + k];
        }
        __syncthreads();
#pragma unroll 4
        for (int k = 0; k < 256; k++) {
            float w = Wo[(size_t)(kc * 256 + k) * D3 + c];
            const float4* pr = (const float4*)sp[k];
#pragma unroll
            for (int q = 0; q < 4; q++) {
                float4 pv = pr[q];
                acc[q * 4 + 0] = fmaf(pv.x, w, acc[q * 4 + 0]);
                acc[q * 4 + 1] = fmaf(pv.y, w, acc[q * 4 + 1]);
                acc[q * 4 + 2] = fmaf(pv.z, w, acc[q * 4 + 2]);
                acc[q * 4 + 3] = fmaf(pv.w, w, acc[q * 4 + 3]);
            }
        }
    }
    float b = bo[c];
#pragma unroll
    for (int g = 0; g < NGRAPH; g++)
        out[(size_t)g * D3 + c] = acc[g] * sinv[g] + b;
}

// ---------------- launcher ----------------
extern "C" void kernel_launch(void* const* d_in, const int* in_sizes, int n_in,
                              void* d_out, int out_size) {
    const float *x, *W1, *b1, *W2, *b2, *W3, *b3, *Wo, *bo;
    const void *ei, *batch;
    if (in_sizes[0] == N_NODES) {           // dict order
        x     = (const float*)d_in[0];
        ei    = d_in[1];
        batch = d_in[2];
        W1 = (const float*)d_in[3];  b1 = (const float*)d_in[4];
        W2 = (const float*)d_in[5];  b2 = (const float*)d_in[6];
        W3 = (const float*)d_in[7];  b3 = (const float*)d_in[8];
        Wo = (const float*)d_in[9];  bo = (const float*)d_in[10];
    } else {                                // alphabetical order
        W1 = (const float*)d_in[0];
        W2 = (const float*)d_in[1];
        W3 = (const float*)d_in[2];
        Wo = (const float*)d_in[3];
        b1 = (const float*)d_in[4];
        b2 = (const float*)d_in[5];
        b3 = (const float*)d_in[6];
        batch = d_in[7];
        bo = (const float*)d_in[8];
        ei = d_in[9];
        x  = (const float*)d_in[10];
    }
    float* out = (float*)d_out;

    float *g2, *g3;
    __nv_bfloat16 *a2hi, *a2lo, *a3hi, *a3lo, *b2hi, *b2lo, *b3hi, *b3lo;
    cudaGetSymbolAddress((void**)&g2, d_g2);
    cudaGetSymbolAddress((void**)&g3, d_g3);
    cudaGetSymbolAddress((void**)&a2hi, d_a2hi);
    cudaGetSymbolAddress((void**)&a2lo, d_a2lo);
    cudaGetSymbolAddress((void**)&a3hi, d_a3hi);
    cudaGetSymbolAddress((void**)&a3lo, d_a3lo);
    cudaGetSymbolAddress((void**)&b2hi, d_b2hi);
    cudaGetSymbolAddress((void**)&b2lo, d_b2lo);
    cudaGetSymbolAddress((void**)&b3hi, d_b3hi);
    cudaGetSymbolAddress((void**)&b3lo, d_b3lo);

    static int smem_set = 0;
    if (!smem_set) {
        cudaFuncSetAttribute(mma_gemm, cudaFuncAttributeMaxDynamicSharedMemorySize, 65536);
        smem_set = 1;
    }

    const int TB = 256;
    int nb_nodes = (N_NODES + TB - 1) / TB;
    int nb_edges = (N_EDGES + TB - 1) / TB;
    int nb_edge8 = (N_EDGES + 7) / 8;

    k_detect<<<1, 32>>>(ei);
    k_init<<<nb_nodes, TB>>>();
    k_deg_edges<<<nb_edges, TB>>>(ei);
    k_dis_s1<<<nb_nodes, TB>>>(x);
    k_norm_s1<<<nb_edges, TB>>>(ei, x);
    k_cnt<<<nb_nodes, TB>>>(batch);

    // weight transposition + bf16 split (independent of graph pipeline)
    k_wsplit<<<(D2 * D1 + TB - 1) / TB, TB>>>(W2, b2hi, b2lo, D1, D2);
    k_wsplit<<<(D3 * D2 + TB - 1) / TB, TB>>>(W3, b3hi, b3lo, D2, D3);

    // layer 1 (rank-1) aggregated into input dim of layer 2
    k_g2_init<<<N_NODES, D1>>>(W1, b1);
    k_scatter1<<<nb_edge8, TB>>>(ei, W1, b1);
    k_split<<<(N_NODES * D1 + TB - 1) / TB, TB>>>(g2, a2hi, a2lo, N_NODES * D1);

    // layer 2 GEMM: writes h2 + g3 self-loop term
    {
        dim3 grid(D2 / 128, (N_NODES + 127) / 128);
        mma_gemm<<<grid, 256, 65536>>>(a2hi, a2lo, b2hi, b2lo, b2, nullptr, N_NODES, D2, D1, 0);
    }

    // layer 2 aggregation
    k_scatter2<<<nb_edge8, TB>>>(ei);
    k_split<<<(N_NODES * D2 + TB - 1) / TB, TB>>>(g3, a3hi, a3lo, N_NODES * D2);

    // layer 3 GEMM with fused pooling
    {
        dim3 grid(D3 / 128, (N_NODES + 127) / 128);
        mma_gemm<<<grid, 256, 65536>>>(a3hi, a3lo, b3hi, b3lo, b3, batch, N_NODES, D3, D2, 1);
    }

    k_final<<<4, 256>>>(Wo, bo, out);
}

// round 7
// speedup vs baseline: 1.7380x; 1.1005x over previous
#include <cuda_runtime.h>
#include <cuda_bf16.h>
#include <cstdint>

#define N_NODES 30000
#define N_EDGES 240000
#define NGRAPH  16
#define D1      256
#define D2      512
#define D3      1024

// ---------------- scratch (no allocations allowed) ----------------
__device__ int   d_idx64;            // 1 if indices are int64, 0 if int32
__device__ int   d_cin[N_NODES];     // in-degree (edges only)
__device__ int   d_rowptr[N_NODES + 1];
__device__ int   d_cursor[N_NODES];
__device__ __align__(16) int2 d_epay[N_EDGES];      // (src, norm-bits) CSR payload
__device__ float d_dis[N_NODES];
__device__ float d_s1 [N_NODES];
__device__ __align__(16) float d_pool[NGRAPH * D3];
__device__ float d_cnt[NGRAPH];

// bf16 hi/lo operand & activation buffers
__device__ __align__(16) __nv_bfloat16 d_a2hi[N_NODES * D1];
__device__ __align__(16) __nv_bfloat16 d_a2lo[N_NODES * D1];
__device__ __align__(16) __nv_bfloat16 d_h2hi[N_NODES * D2];
__device__ __align__(16) __nv_bfloat16 d_h2lo[N_NODES * D2];
__device__ __align__(16) __nv_bfloat16 d_a3hi[N_NODES * D2];
__device__ __align__(16) __nv_bfloat16 d_a3lo[N_NODES * D2];
__device__ __align__(16) __nv_bfloat16 d_b2hi[D2 * D1];   // [N=512, K=256] K-major
__device__ __align__(16) __nv_bfloat16 d_b2lo[D2 * D1];
__device__ __align__(16) __nv_bfloat16 d_b3hi[D3 * D2];   // [N=1024, K=512] K-major
__device__ __align__(16) __nv_bfloat16 d_b3lo[D3 * D2];

// ---------------- small helpers ----------------
__device__ __forceinline__ int load_idx(const void* p, int i) {
    if (d_idx64) return (int)((const long long*)p)[i];
    return ((const int*)p)[i];
}
__device__ __forceinline__ void red_add_v2(float* p, float x, float y) {
    asm volatile("red.global.add.v2.f32 [%0], {%1,%2};"
                 :: "l"(p), "f"(x), "f"(y) : "memory");
}
__device__ __forceinline__ uint32_t smem_u32(const void* p) {
    uint32_t a;
    asm("{ .reg .u64 t; cvta.to.shared.u64 t, %1; cvt.u32.u64 %0, t; }" : "=r"(a) : "l"(p));
    return a;
}
__device__ __forceinline__ void ldm_x4(uint32_t* r, uint32_t addr) {
    asm volatile("ldmatrix.sync.aligned.m8n8.x4.shared.b16 {%0,%1,%2,%3}, [%4];"
                 : "=r"(r[0]), "=r"(r[1]), "=r"(r[2]), "=r"(r[3]) : "r"(addr));
}
__device__ __forceinline__ void cp_async16(uint32_t dst, const void* src, uint32_t srcsize) {
    asm volatile("cp.async.cg.shared.global [%0], [%1], 16, %2;"
                 :: "r"(dst), "l"(src), "r"(srcsize) : "memory");
}
__device__ __forceinline__ void cp_commit(void) {
    asm volatile("cp.async.commit_group;" ::: "memory");
}
__device__ __forceinline__ void mma16816(float* c, const uint32_t* a, uint32_t b0, uint32_t b1) {
    asm volatile(
        "mma.sync.aligned.m16n8k16.row.col.f32.bf16.bf16.f32 "
        "{%0,%1,%2,%3}, {%4,%5,%6,%7}, {%8,%9}, {%0,%1,%2,%3};"
        : "+f"(c[0]), "+f"(c[1]), "+f"(c[2]), "+f"(c[3])
        : "r"(a[0]), "r"(a[1]), "r"(a[2]), "r"(a[3]), "r"(b0), "r"(b1));
}
__device__ __forceinline__ float2 bf2f(uint32_t u) {
    __nv_bfloat162 h = *reinterpret_cast<__nv_bfloat162*>(&u);
    return __bfloat1622float2(h);
}
__device__ __forceinline__ uint32_t f2bf2(float a, float b) {
    __nv_bfloat162 h = __floats2bfloat162_rn(a, b);
    return *reinterpret_cast<uint32_t*>(&h);
}

// ---------------- dtype detection ----------------
__global__ void k_detect(const void* __restrict__ ei) {
    if (threadIdx.x != 0 || blockIdx.x != 0) return;
    const long long* p = (const long long*)ei;
    int ok = 1;
    for (int i = 0; i < 64; i++) {
        long long v = p[i];
        if (v < 0 || v >= N_NODES) { ok = 0; break; }
    }
    d_idx64 = ok;
}

// ---------------- setup ----------------
__global__ void k_init(void) {
    int i = blockIdx.x * blockDim.x + threadIdx.x;
    if (i < N_NODES) d_cin[i] = 0;
    if (i < NGRAPH) d_cnt[i] = 0.0f;
    if (i < NGRAPH * D3) d_pool[i] = 0.0f;
}

__global__ void k_deg_edges(const void* __restrict__ ei) {
    int e = blockIdx.x * blockDim.x + threadIdx.x;
    if (e >= N_EDGES) return;
    atomicAdd(&d_cin[load_idx(ei, N_EDGES + e)], 1);
}

__global__ void k_dis_s1(const float* __restrict__ x) {
    int i = blockIdx.x * blockDim.x + threadIdx.x;
    if (i >= N_NODES) return;
    float r = rsqrtf((float)(d_cin[i] + 1));
    d_dis[i] = r;
    d_s1[i]  = r * r * x[i];        // self-loop term of A_hat @ x
}

// single-block exclusive scan over in-degrees -> rowptr, cursor
__global__ void k_scan(void) {
    __shared__ int part[1024];
    int tid = threadIdx.x;
    const int PER = (N_NODES + 1023) / 1024;
    int base = tid * PER;
    int sum = 0;
    for (int j = 0; j < PER; j++) {
        int i = base + j;
        if (i < N_NODES) sum += d_cin[i];
    }
    part[tid] = sum;
    __syncthreads();
    for (int off = 1; off < 1024; off <<= 1) {
        int v = (tid >= off) ? part[tid - off] : 0;
        __syncthreads();
        part[tid] += v;
        __syncthreads();
    }
    int run = (tid ? part[tid - 1] : 0);
    for (int j = 0; j < PER; j++) {
        int i = base + j;
        if (i < N_NODES) {
            d_rowptr[i] = run;
            d_cursor[i] = run;
            run += d_cin[i];
        }
    }
    if (tid == 1023) d_rowptr[N_NODES] = run;
}

// CSR fill + edge contribution to s1
__global__ void k_fill(const void* __restrict__ ei, const float* __restrict__ x) {
    int e = blockIdx.x * blockDim.x + threadIdx.x;
    if (e >= N_EDGES) return;
    int s = load_idx(ei, e), d = load_idx(ei, N_EDGES + e);
    float nv = d_dis[s] * d_dis[d];
    int pos = atomicAdd(&d_cursor[d], 1);
    d_epay[pos] = make_int2(s, __float_as_int(nv));
    atomicAdd(&d_s1[d], nv * x[s]);
}

__global__ void k_cnt(const void* __restrict__ batch) {
    int i = blockIdx.x * blockDim.x + threadIdx.x;
    if (i >= N_NODES) return;
    atomicAdd(&d_cnt[load_idx(batch, i)], 1.0f);
}

// ---------------- layer 1 gather: a2 = bf16split(A_hat @ h1), h1 rank-1 on the fly ----------------
// warp per node; lane owns 8 consecutive features.
__global__ __launch_bounds__(256)
void k_gather1(const float* __restrict__ W1, const float* __restrict__ b1) {
    __shared__ float sW[D1], sB[D1];
    int tid = threadIdx.x;
    if (tid < D1) { sW[tid] = W1[tid]; sB[tid] = b1[tid]; }
    __syncthreads();
    int warp = tid >> 5, lane = tid & 31;
    int node = blockIdx.x * 8 + warp;
    if (node >= N_NODES) return;
    float w[8], b[8];
#pragma unroll
    for (int q = 0; q < 8; q++) { w[q] = sW[lane * 8 + q]; b[q] = sB[lane * 8 + q]; }
    float acc[8];
    float dis = d_dis[node];
    float coef = dis * dis, sv = d_s1[node];
#pragma unroll
    for (int q = 0; q < 8; q++) acc[q] = coef * fmaxf(fmaf(sv, w[q], b[q]), 0.0f);
    int beg = d_rowptr[node], end = d_rowptr[node + 1];
    for (int e = beg; e < end; e++) {
        int2 pay = d_epay[e];
        float nv = __int_as_float(pay.y);
        float s = d_s1[pay.x];
#pragma unroll
        for (int q = 0; q < 8; q++) acc[q] = fmaf(nv, fmaxf(fmaf(s, w[q], b[q]), 0.0f), acc[q]);
    }
    uint32_t hw[4], lw[4];
#pragma unroll
    for (int q2 = 0; q2 < 4; q2++) {
        float v0 = acc[q2 * 2], v1 = acc[q2 * 2 + 1];
        __nv_bfloat16 h0 = __float2bfloat16(v0), h1 = __float2bfloat16(v1);
        hw[q2] = f2bf2(v0, v1);
        lw[q2] = f2bf2(v0 - __bfloat162float(h0), v1 - __bfloat162float(h1));
    }
    size_t off = (size_t)node * D1 + lane * 8;
    *(uint4*)(d_a2hi + off) = make_uint4(hw[0], hw[1], hw[2], hw[3]);
    *(uint4*)(d_a2lo + off) = make_uint4(lw[0], lw[1], lw[2], lw[3]);
}

// ---------------- layer 2 gather: a3 = bf16split(A_hat @ h2), h2 stored hi/lo ----------------
// warp per node; lane owns 16 consecutive features.
__device__ __forceinline__ void acc_row16(float* acc, int row, float nv, int lane) {
    size_t off = (size_t)row * D2 + lane * 16;
    uint4 h0 = *(const uint4*)(d_h2hi + off);
    uint4 h1 = *(const uint4*)(d_h2hi + off + 8);
    uint4 l0 = *(const uint4*)(d_h2lo + off);
    uint4 l1 = *(const uint4*)(d_h2lo + off + 8);
    const uint32_t hu[8] = {h0.x, h0.y, h0.z, h0.w, h1.x, h1.y, h1.z, h1.w};
    const uint32_t lu[8] = {l0.x, l0.y, l0.z, l0.w, l1.x, l1.y, l1.z, l1.w};
#pragma unroll
    for (int q = 0; q < 8; q++) {
        float2 hv = bf2f(hu[q]);
        float2 lv = bf2f(lu[q]);
        acc[q * 2 + 0] = fmaf(nv, hv.x + lv.x, acc[q * 2 + 0]);
        acc[q * 2 + 1] = fmaf(nv, hv.y + lv.y, acc[q * 2 + 1]);
    }
}

__global__ __launch_bounds__(256)
void k_gather2(void) {
    int tid = threadIdx.x;
    int warp = tid >> 5, lane = tid & 31;
    int node = blockIdx.x * 8 + warp;
    if (node >= N_NODES) return;
    float acc[16];
#pragma unroll
    for (int q = 0; q < 16; q++) acc[q] = 0.0f;
    float dis = d_dis[node];
    acc_row16(acc, node, dis * dis, lane);
    int beg = d_rowptr[node], end = d_rowptr[node + 1];
    for (int e = beg; e < end; e++) {
        int2 pay = d_epay[e];
        acc_row16(acc, pay.x, __int_as_float(pay.y), lane);
    }
    uint32_t hw[8], lw[8];
#pragma unroll
    for (int q2 = 0; q2 < 8; q2++) {
        float v0 = acc[q2 * 2], v1 = acc[q2 * 2 + 1];
        __nv_bfloat16 h0 = __float2bfloat16(v0), h1 = __float2bfloat16(v1);
        hw[q2] = f2bf2(v0, v1);
        lw[q2] = f2bf2(v0 - __bfloat162float(h0), v1 - __bfloat162float(h1));
    }
    size_t off = (size_t)node * D2 + lane * 16;
    *(uint4*)(d_a3hi + off)     = make_uint4(hw[0], hw[1], hw[2], hw[3]);
    *(uint4*)(d_a3hi + off + 8) = make_uint4(hw[4], hw[5], hw[6], hw[7]);
    *(uint4*)(d_a3lo + off)     = make_uint4(lw[0], lw[1], lw[2], lw[3]);
    *(uint4*)(d_a3lo + off + 8) = make_uint4(lw[4], lw[5], lw[6], lw[7]);
}

// W [K, N] fp32 row-major -> B [N, K] bf16 hi/lo (transposed, K-major)
__global__ void k_wsplit(const float* __restrict__ W, __nv_bfloat16* __restrict__ bhi,
                         __nv_bfloat16* __restrict__ blo, int K, int N) {
    int idx = blockIdx.x * blockDim.x + threadIdx.x;
    if (idx >= N * K) return;
    int n = idx / K, k = idx - n * K;
    float v = W[(size_t)k * N + n];
    __nv_bfloat16 h = __float2bfloat16(v);
    bhi[idx] = h;
    blo[idx] = __float2bfloat16(v - __bfloat162float(h));
}

// ---------------- bf16-split GEMM: ldmatrix + cp.async double buffer ----------------
// mode 0: h2 = relu(D+bias) stored as bf16 hi/lo           (layer 2)
// mode 1: relu(D+bias) pooled into d_pool[batch]            (layer 3)
__global__ __launch_bounds__(256, 2)
void mma_gemm(const __nv_bfloat16* __restrict__ Ahi, const __nv_bfloat16* __restrict__ Alo,
              const __nv_bfloat16* __restrict__ Bhi, const __nv_bfloat16* __restrict__ Blo,
              const float* __restrict__ bias, const void* __restrict__ batch,
              int M, int Nglob, int K, int mode) {
    extern __shared__ __align__(16) char dynsm[];

    const int tid = threadIdx.x;
    const int wid = tid >> 5, lane = tid & 31;
    const int g = lane >> 2, tig = lane & 3;
    const int warp_m = wid & 3, warp_n = wid >> 2;
    const int row0 = blockIdx.y * 128, col0 = blockIdx.x * 128;
    const int mr = warp_m * 32, nc = warp_n * 64;

    const int t   = lane >> 3;
    const int thi = t >> 1;
    const int rlo = (t & 1) * 8 + (lane & 7);

    const uint32_t smbase = smem_u32(dynsm);
    const uint32_t stA[2] = { smbase, smbase + 32768u };
    const uint32_t stB[2] = { smbase + 16384u, smbase + 49152u };

    int rA0 = mr + rlo, rA1 = mr + 16 + rlo;
    uint32_t aoff0 = (uint32_t)(rA0 * 128), amask0 = (uint32_t)(rA0 & 7);
    uint32_t aoff1 = (uint32_t)(rA1 * 128), amask1 = (uint32_t)(rA1 & 7);
    uint32_t boff[4], bmask[4];
#pragma unroll
    for (int p = 0; p < 4; p++) {
        int rB = nc + p * 16 + rlo;
        boff[p] = (uint32_t)(rB * 128);
        bmask[p] = (uint32_t)(rB & 7);
    }

    float acc[2][8][4];
#pragma unroll
    for (int mf = 0; mf < 2; mf++)
#pragma unroll
        for (int nf = 0; nf < 8; nf++)
#pragma unroll
            for (int q = 0; q < 4; q++) acc[mf][nf][q] = 0.0f;

    const int nk = K >> 6;
    const int nchunks = 3 * nk;

    const int lr = tid >> 1;
    const int lc2 = (tid & 1) * 4;
    auto prefetch = [&](int c, int s) {
        const __nv_bfloat16 *Ap, *Bp;
        int kc;
        if (c < nk)          { Ap = Ahi; Bp = Bhi; kc = c; }
        else if (c < 2 * nk) { Ap = Alo; Bp = Bhi; kc = c - nk; }
        else                 { Ap = Ahi; Bp = Blo; kc = c - 2 * nk; }
        const int kof = kc << 6;
        int grow = row0 + lr;
        uint32_t asz = (grow < M) ? 16u : 0u;
        const __nv_bfloat16* agp = Ap + (size_t)grow * K + kof + lc2 * 8;
        const __nv_bfloat16* bgp = Bp + (size_t)(col0 + lr) * K + kof + lc2 * 8;
        uint32_t arow = (uint32_t)(lr * 128);
#pragma unroll
        for (int j = 0; j < 4; j++) {
            int ch = lc2 + j;
            uint32_t soff = arow + (uint32_t)(((ch ^ (lr & 7)) << 4));
            cp_async16(stA[s] + soff, agp + j * 8, asz);
            cp_async16(stB[s] + soff, bgp + j * 8, 16u);
        }
        cp_commit();
    };

    prefetch(0, 0);
    for (int c = 0; c < nchunks; c++) {
        const int s = c & 1;
        if (c + 1 < nchunks) {
            prefetch(c + 1, (c + 1) & 1);
            asm volatile("cp.async.wait_group 1;" ::: "memory");
        } else {
            asm volatile("cp.async.wait_group 0;" ::: "memory");
        }
        __syncthreads();

#pragma unroll
        for (int ks = 0; ks < 4; ks++) {
            const uint32_t kg = (uint32_t)(2 * ks + thi);
            uint32_t a0[4], a1[4];
            ldm_x4(a0, stA[s] + aoff0 + (((kg ^ amask0) << 4)));
            ldm_x4(a1, stA[s] + aoff1 + (((kg ^ amask1) << 4)));
#pragma unroll
            for (int p = 0; p < 4; p++) {
                uint32_t bfr[4];
                ldm_x4(bfr, stB[s] + boff[p] + (((kg ^ bmask[p]) << 4)));
                mma16816(acc[0][2 * p + 0], a0, bfr[0], bfr[2]);
                mma16816(acc[0][2 * p + 1], a0, bfr[1], bfr[3]);
                mma16816(acc[1][2 * p + 0], a1, bfr[0], bfr[2]);
                mma16816(acc[1][2 * p + 1], a1, bfr[1], bfr[3]);
            }
        }
        __syncthreads();
    }

    // ---------------- epilogue ----------------
    if (mode == 0) {
#pragma unroll
        for (int mf = 0; mf < 2; mf++) {
#pragma unroll
            for (int half = 0; half < 2; half++) {
                int row = row0 + mr + mf * 16 + g + half * 8;
                if (row >= M) continue;
#pragma unroll
                for (int nf = 0; nf < 8; nf++) {
                    int col = col0 + nc + nf * 8 + tig * 2;
                    float2 bv = *(const float2*)&bias[col];
                    float v0 = fmaxf(acc[mf][nf][half * 2 + 0] + bv.x, 0.0f);
                    float v1 = fmaxf(acc[mf][nf][half * 2 + 1] + bv.y, 0.0f);
                    __nv_bfloat16 h0 = __float2bfloat16(v0), h1 = __float2bfloat16(v1);
                    size_t off = (size_t)row * D2 + col;
                    *(uint32_t*)(d_h2hi + off) = f2bf2(v0, v1);
                    *(uint32_t*)(d_h2lo + off) =
                        f2bf2(v0 - __bfloat162float(h0), v1 - __bfloat162float(h1));
                }
            }
        }
    } else {
#pragma unroll
        for (int mf = 0; mf < 2; mf++) {
            int ra = row0 + mr + mf * 16 + g;
            int v0ok = (ra < M), v1ok = (ra + 8 < M);
#pragma unroll
            for (int nf = 0; nf < 8; nf++) {
                int col = col0 + nc + nf * 8 + tig * 2;
                float2 bv = *(const float2*)&bias[col];
                acc[mf][nf][0] = v0ok ? fmaxf(acc[mf][nf][0] + bv.x, 0.0f) : 0.0f;
                acc[mf][nf][1] = v0ok ? fmaxf(acc[mf][nf][1] + bv.y, 0.0f) : 0.0f;
                acc[mf][nf][2] = v1ok ? fmaxf(acc[mf][nf][2] + bv.x, 0.0f) : 0.0f;
                acc[mf][nf][3] = v1ok ? fmaxf(acc[mf][nf][3] + bv.y, 0.0f) : 0.0f;
            }
        }
        unsigned mask = 0xffffffffu;
        int rv = row0 + mr + lane;
        int bl = (rv < N_NODES) ? load_idx(batch, rv) : -1;
        int b0 = __shfl_sync(mask, bl, 0);
        bool uni = __all_sync(mask, bl == b0);
        if (uni && b0 >= 0) {
            float s[8][2];
#pragma unroll
            for (int nf = 0; nf < 8; nf++) {
                s[nf][0] = acc[0][nf][0] + acc[0][nf][2] + acc[1][nf][0] + acc[1][nf][2];
                s[nf][1] = acc[0][nf][1] + acc[0][nf][3] + acc[1][nf][1] + acc[1][nf][3];
            }
#pragma unroll
            for (int off = 4; off < 32; off <<= 1)
#pragma unroll
                for (int nf = 0; nf < 8; nf++) {
                    s[nf][0] += __shfl_xor_sync(mask, s[nf][0], off);
                    s[nf][1] += __shfl_xor_sync(mask, s[nf][1], off);
                }
            if (lane < 4) {
#pragma unroll
                for (int nf = 0; nf < 8; nf++) {
                    int col = col0 + nc + nf * 8 + lane * 2;
                    red_add_v2(&d_pool[(size_t)b0 * D3 + col], s[nf][0], s[nf][1]);
                }
            }
        } else {
#pragma unroll
            for (int mf = 0; mf < 2; mf++)
#pragma unroll
                for (int half = 0; half < 2; half++) {
                    int row = row0 + mr + mf * 16 + g + half * 8;
                    if (row >= M) continue;
                    int gb = load_idx(batch, row);
#pragma unroll
                    for (int nf = 0; nf < 8; nf++) {
                        int col = col0 + nc + nf * 8 + tig * 2;
                        red_add_v2(&d_pool[(size_t)gb * D3 + col],
                                   acc[mf][nf][half * 2], acc[mf][nf][half * 2 + 1]);
                    }
                }
        }
    }
}

// ---------------- final linear [16,1024] @ [1024,1024] ----------------
__global__ void k_final(const float* __restrict__ Wo, const float* __restrict__ bo,
                        float* __restrict__ out) {
    __shared__ __align__(16) float sp[256][NGRAPH];
    __shared__ float sinv[NGRAPH];
    int tid = threadIdx.x;
    int c = blockIdx.x * 256 + tid;
    if (tid < NGRAPH) sinv[tid] = 1.0f / fmaxf(d_cnt[tid], 1.0f);
    float acc[NGRAPH];
#pragma unroll
    for (int g = 0; g < NGRAPH; g++) acc[g] = 0.0f;

    for (int kc = 0; kc < D3 / 256; kc++) {
        __syncthreads();
        for (int i = tid; i < 256 * NGRAPH; i += 256) {
            int k = i >> 4, g = i & 15;
            sp[k][g] = d_pool[(size_t)g * D3 + kc * 256 + k];
        }
        __syncthreads();
#pragma unroll 4
        for (int k = 0; k < 256; k++) {
            float w = Wo[(size_t)(kc * 256 + k) * D3 + c];
            const float4* pr = (const float4*)sp[k];
#pragma unroll
            for (int q = 0; q < 4; q++) {
                float4 pv = pr[q];
                acc[q * 4 + 0] = fmaf(pv.x, w, acc[q * 4 + 0]);
                acc[q * 4 + 1] = fmaf(pv.y, w, acc[q * 4 + 1]);
                acc[q * 4 + 2] = fmaf(pv.z, w, acc[q * 4 + 2]);
                acc[q * 4 + 3] = fmaf(pv.w, w, acc[q * 4 + 3]);
            }
        }
    }
    float b = bo[c];
#pragma unroll
    for (int g = 0; g < NGRAPH; g++)
        out[(size_t)g * D3 + c] = acc[g] * sinv[g] + b;
}

// ---------------- launcher ----------------
extern "C" void kernel_launch(void* const* d_in, const int* in_sizes, int n_in,
                              void* d_out, int out_size) {
    const float *x, *W1, *b1, *W2, *b2, *W3, *b3, *Wo, *bo;
    const void *ei, *batch;
    if (in_sizes[0] == N_NODES) {           // dict order
        x     = (const float*)d_in[0];
        ei    = d_in[1];
        batch = d_in[2];
        W1 = (const float*)d_in[3];  b1 = (const float*)d_in[4];
        W2 = (const float*)d_in[5];  b2 = (const float*)d_in[6];
        W3 = (const float*)d_in[7];  b3 = (const float*)d_in[8];
        Wo = (const float*)d_in[9];  bo = (const float*)d_in[10];
    } else {                                // alphabetical order
        W1 = (const float*)d_in[0];
        W2 = (const float*)d_in[1];
        W3 = (const float*)d_in[2];
        Wo = (const float*)d_in[3];
        b1 = (const float*)d_in[4];
        b2 = (const float*)d_in[5];
        b3 = (const float*)d_in[6];
        batch = d_in[7];
        bo = (const float*)d_in[8];
        ei = d_in[9];
        x  = (const float*)d_in[10];
    }
    float* out = (float*)d_out;

    __nv_bfloat16 *a2hi, *a2lo, *a3hi, *a3lo, *b2hi, *b2lo, *b3hi, *b3lo;
    cudaGetSymbolAddress((void**)&a2hi, d_a2hi);
    cudaGetSymbolAddress((void**)&a2lo, d_a2lo);
    cudaGetSymbolAddress((void**)&a3hi, d_a3hi);
    cudaGetSymbolAddress((void**)&a3lo, d_a3lo);
    cudaGetSymbolAddress((void**)&b2hi, d_b2hi);
    cudaGetSymbolAddress((void**)&b2lo, d_b2lo);
    cudaGetSymbolAddress((void**)&b3hi, d_b3hi);
    cudaGetSymbolAddress((void**)&b3lo, d_b3lo);

    static int smem_set = 0;
    if (!smem_set) {
        cudaFuncSetAttribute(mma_gemm, cudaFuncAttributeMaxDynamicSharedMemorySize, 65536);
        smem_set = 1;
    }

    const int TB = 256;
    int nb_nodes = (N_NODES + TB - 1) / TB;
    int nb_edges = (N_EDGES + TB - 1) / TB;
    int nb_node8 = (N_NODES + 7) / 8;

    k_detect<<<1, 32>>>(ei);
    k_init<<<nb_nodes, TB>>>();
    k_deg_edges<<<nb_edges, TB>>>(ei);
    k_dis_s1<<<nb_nodes, TB>>>(x);
    k_scan<<<1, 1024>>>();
    k_fill<<<nb_edges, TB>>>(ei, x);
    k_cnt<<<nb_nodes, TB>>>(batch);

    // weight transposition + bf16 split (independent of graph pipeline)
    k_wsplit<<<(D2 * D1 + TB - 1) / TB, TB>>>(W2, b2hi, b2lo, D1, D2);
    k_wsplit<<<(D3 * D2 + TB - 1) / TB, TB>>>(W3, b3hi, b3lo, D2, D3);

    // layer 1: gather A_hat @ h1 (rank-1), emit bf16 split directly
    k_gather1<<<nb_node8, TB>>>(W1, b1);

    // layer 2 GEMM: h2 = relu(a2 @ W2 + b2) stored bf16 hi/lo
    {
        dim3 grid(D2 / 128, (N_NODES + 127) / 128);
        mma_gemm<<<grid, 256, 65536>>>(a2hi, a2lo, b2hi, b2lo, b2, nullptr, N_NODES, D2, D1, 0);
    }

    // layer 2 aggregation: gather, emit a3 bf16 split directly
    k_gather2<<<nb_node8, TB>>>();

    // layer 3 GEMM with fused pooling
    {
        dim3 grid(D3 / 128, (N_NODES + 127) / 128);
        mma_gemm<<<grid, 256, 65536>>>(a3hi, a3lo, b3hi, b3lo, b3, batch, N_NODES, D3, D2, 1);
    }

    k_final<<<4, 256>>>(Wo, bo, out);
}

// round 8
// speedup vs baseline: 2.1643x; 1.2452x over previous
#include <cuda_runtime.h>
#include <cuda_bf16.h>
#include <cstdint>

#define N_NODES 30000
#define N_EDGES 240000
#define NGRAPH  16
#define D1      256
#define D2      512
#define D3      1024

// ---------------- scratch (no allocations allowed) ----------------
__device__ int   d_idx64;            // 1 if indices are int64, 0 if int32
__device__ int   d_cin[N_NODES];     // in-degree (edges only)
__device__ int   d_rowptr[N_NODES + 1];
__device__ int   d_cursor[N_NODES];
__device__ __align__(16) int2 d_epay[N_EDGES];      // (src, norm-bits) CSR payload
__device__ float d_dis[N_NODES];
__device__ float d_s1 [N_NODES];
__device__ __align__(16) float d_pool[NGRAPH * D3];
__device__ float d_cnt[NGRAPH];

// bf16 operand & activation buffers (activations single bf16; weights hi/lo)
__device__ __align__(16) __nv_bfloat16 d_a2hi[N_NODES * D1];
__device__ __align__(16) __nv_bfloat16 d_h2hi[N_NODES * D2];
__device__ __align__(16) __nv_bfloat16 d_h2lo[N_NODES * D2];
__device__ __align__(16) __nv_bfloat16 d_a3hi[N_NODES * D2];
__device__ __align__(16) __nv_bfloat16 d_b2hi[D2 * D1];   // [N=512, K=256] K-major
__device__ __align__(16) __nv_bfloat16 d_b2lo[D2 * D1];
__device__ __align__(16) __nv_bfloat16 d_b3hi[D3 * D2];   // [N=1024, K=512] K-major
__device__ __align__(16) __nv_bfloat16 d_b3lo[D3 * D2];

// ---------------- small helpers ----------------
__device__ __forceinline__ int load_idx(const void* p, int i) {
    if (d_idx64) return (int)((const long long*)p)[i];
    return ((const int*)p)[i];
}
__device__ __forceinline__ void red_add_v2(float* p, float x, float y) {
    asm volatile("red.global.add.v2.f32 [%0], {%1,%2};"
                 :: "l"(p), "f"(x), "f"(y) : "memory");
}
__device__ __forceinline__ uint32_t smem_u32(const void* p) {
    uint32_t a;
    asm("{ .reg .u64 t; cvta.to.shared.u64 t, %1; cvt.u32.u64 %0, t; }" : "=r"(a) : "l"(p));
    return a;
}
__device__ __forceinline__ void ldm_x4(uint32_t* r, uint32_t addr) {
    asm volatile("ldmatrix.sync.aligned.m8n8.x4.shared.b16 {%0,%1,%2,%3}, [%4];"
                 : "=r"(r[0]), "=r"(r[1]), "=r"(r[2]), "=r"(r[3]) : "r"(addr));
}
__device__ __forceinline__ void cp_async16(uint32_t dst, const void* src, uint32_t srcsize) {
    asm volatile("cp.async.cg.shared.global [%0], [%1], 16, %2;"
                 :: "r"(dst), "l"(src), "r"(srcsize) : "memory");
}
__device__ __forceinline__ void cp_commit(void) {
    asm volatile("cp.async.commit_group;" ::: "memory");
}
__device__ __forceinline__ void mma16816(float* c, const uint32_t* a, uint32_t b0, uint32_t b1) {
    asm volatile(
        "mma.sync.aligned.m16n8k16.row.col.f32.bf16.bf16.f32 "
        "{%0,%1,%2,%3}, {%4,%5,%6,%7}, {%8,%9}, {%0,%1,%2,%3};"
        : "+f"(c[0]), "+f"(c[1]), "+f"(c[2]), "+f"(c[3])
        : "r"(a[0]), "r"(a[1]), "r"(a[2]), "r"(a[3]), "r"(b0), "r"(b1));
}
__device__ __forceinline__ float2 bf2f(uint32_t u) {
    __nv_bfloat162 h = *reinterpret_cast<__nv_bfloat162*>(&u);
    return __bfloat1622float2(h);
}
__device__ __forceinline__ uint32_t f2bf2(float a, float b) {
    __nv_bfloat162 h = __floats2bfloat162_rn(a, b);
    return *reinterpret_cast<uint32_t*>(&h);
}

// ---------------- dtype detection ----------------
__global__ void k_detect(const void* __restrict__ ei) {
    if (threadIdx.x != 0 || blockIdx.x != 0) return;
    const long long* p = (const long long*)ei;
    int ok = 1;
    for (int i = 0; i < 64; i++) {
        long long v = p[i];
        if (v < 0 || v >= N_NODES) { ok = 0; break; }
    }
    d_idx64 = ok;
}

// ---------------- setup ----------------
__global__ void k_init(void) {
    int i = blockIdx.x * blockDim.x + threadIdx.x;
    if (i < N_NODES) d_cin[i] = 0;
    if (i < NGRAPH) d_cnt[i] = 0.0f;
    if (i < NGRAPH * D3) d_pool[i] = 0.0f;
}

__global__ void k_deg_edges(const void* __restrict__ ei) {
    int e = blockIdx.x * blockDim.x + threadIdx.x;
    if (e >= N_EDGES) return;
    atomicAdd(&d_cin[load_idx(ei, N_EDGES + e)], 1);
}

__global__ void k_dis_s1(const float* __restrict__ x) {
    int i = blockIdx.x * blockDim.x + threadIdx.x;
    if (i >= N_NODES) return;
    float r = rsqrtf((float)(d_cin[i] + 1));
    d_dis[i] = r;
    d_s1[i]  = r * r * x[i];        // self-loop term of A_hat @ x
}

// single-block exclusive scan over in-degrees -> rowptr, cursor
__global__ void k_scan(void) {
    __shared__ int part[1024];
    int tid = threadIdx.x;
    const int PER = (N_NODES + 1023) / 1024;
    int base = tid * PER;
    int sum = 0;
    for (int j = 0; j < PER; j++) {
        int i = base + j;
        if (i < N_NODES) sum += d_cin[i];
    }
    part[tid] = sum;
    __syncthreads();
    for (int off = 1; off < 1024; off <<= 1) {
        int v = (tid >= off) ? part[tid - off] : 0;
        __syncthreads();
        part[tid] += v;
        __syncthreads();
    }
    int run = (tid ? part[tid - 1] : 0);
    for (int j = 0; j < PER; j++) {
        int i = base + j;
        if (i < N_NODES) {
            d_rowptr[i] = run;
            d_cursor[i] = run;
            run += d_cin[i];
        }
    }
    if (tid == 1023) d_rowptr[N_NODES] = run;
}

// CSR fill + edge contribution to s1
__global__ void k_fill(const void* __restrict__ ei, const float* __restrict__ x) {
    int e = blockIdx.x * blockDim.x + threadIdx.x;
    if (e >= N_EDGES) return;
    int s = load_idx(ei, e), d = load_idx(ei, N_EDGES + e);
    float nv = d_dis[s] * d_dis[d];
    int pos = atomicAdd(&d_cursor[d], 1);
    d_epay[pos] = make_int2(s, __float_as_int(nv));
    atomicAdd(&d_s1[d], nv * x[s]);
}

__global__ void k_cnt(const void* __restrict__ batch) {
    int i = blockIdx.x * blockDim.x + threadIdx.x;
    if (i >= N_NODES) return;
    atomicAdd(&d_cnt[load_idx(batch, i)], 1.0f);
}

// ---------------- layer 1 gather: a2 = bf16(A_hat @ h1), h1 rank-1 on the fly ----------------
__global__ __launch_bounds__(256)
void k_gather1(const float* __restrict__ W1, const float* __restrict__ b1) {
    __shared__ float sW[D1], sB[D1];
    int tid = threadIdx.x;
    if (tid < D1) { sW[tid] = W1[tid]; sB[tid] = b1[tid]; }
    __syncthreads();
    int warp = tid >> 5, lane = tid & 31;
    int node = blockIdx.x * 8 + warp;
    if (node >= N_NODES) return;
    float w[8], b[8];
#pragma unroll
    for (int q = 0; q < 8; q++) { w[q] = sW[lane * 8 + q]; b[q] = sB[lane * 8 + q]; }
    float acc[8];
    float dis = d_dis[node];
    float coef = dis * dis, sv = d_s1[node];
#pragma unroll
    for (int q = 0; q < 8; q++) acc[q] = coef * fmaxf(fmaf(sv, w[q], b[q]), 0.0f);
    int beg = d_rowptr[node], end = d_rowptr[node + 1];
    for (int e = beg; e < end; e++) {
        int2 pay = d_epay[e];
        float nv = __int_as_float(pay.y);
        float s = d_s1[pay.x];
#pragma unroll
        for (int q = 0; q < 8; q++) acc[q] = fmaf(nv, fmaxf(fmaf(s, w[q], b[q]), 0.0f), acc[q]);
    }
    uint32_t hw[4];
#pragma unroll
    for (int q2 = 0; q2 < 4; q2++) hw[q2] = f2bf2(acc[q2 * 2], acc[q2 * 2 + 1]);
    size_t off = (size_t)node * D1 + lane * 8;
    *(uint4*)(d_a2hi + off) = make_uint4(hw[0], hw[1], hw[2], hw[3]);
}

// ---------------- layer 2 gather: a3 = bf16(A_hat @ h2), h2 stored hi/lo ----------------
__device__ __forceinline__ void acc_row16(float* acc, int row, float nv, int lane) {
    size_t off = (size_t)row * D2 + lane * 16;
    uint4 h0 = *(const uint4*)(d_h2hi + off);
    uint4 h1 = *(const uint4*)(d_h2hi + off + 8);
    uint4 l0 = *(const uint4*)(d_h2lo + off);
    uint4 l1 = *(const uint4*)(d_h2lo + off + 8);
    const uint32_t hu[8] = {h0.x, h0.y, h0.z, h0.w, h1.x, h1.y, h1.z, h1.w};
    const uint32_t lu[8] = {l0.x, l0.y, l0.z, l0.w, l1.x, l1.y, l1.z, l1.w};
#pragma unroll
    for (int q = 0; q < 8; q++) {
        float2 hv = bf2f(hu[q]);
        float2 lv = bf2f(lu[q]);
        acc[q * 2 + 0] = fmaf(nv, hv.x + lv.x, acc[q * 2 + 0]);
        acc[q * 2 + 1] = fmaf(nv, hv.y + lv.y, acc[q * 2 + 1]);
    }
}

__global__ __launch_bounds__(256)
void k_gather2(void) {
    int tid = threadIdx.x;
    int warp = tid >> 5, lane = tid & 31;
    int node = blockIdx.x * 8 + warp;
    if (node >= N_NODES) return;
    float acc[16];
#pragma unroll
    for (int q = 0; q < 16; q++) acc[q] = 0.0f;
    float dis = d_dis[node];
    acc_row16(acc, node, dis * dis, lane);
    int beg = d_rowptr[node], end = d_rowptr[node + 1];
    for (int e = beg; e < end; e++) {
        int2 pay = d_epay[e];
        acc_row16(acc, pay.x, __int_as_float(pay.y), lane);
    }
    uint32_t hw[8];
#pragma unroll
    for (int q2 = 0; q2 < 8; q2++) hw[q2] = f2bf2(acc[q2 * 2], acc[q2 * 2 + 1]);
    size_t off = (size_t)node * D2 + lane * 16;
    *(uint4*)(d_a3hi + off)     = make_uint4(hw[0], hw[1], hw[2], hw[3]);
    *(uint4*)(d_a3hi + off + 8) = make_uint4(hw[4], hw[5], hw[6], hw[7]);
}

// W [K, N] fp32 row-major -> B [N, K] bf16 hi/lo (transposed, K-major)
__global__ void k_wsplit(const float* __restrict__ W, __nv_bfloat16* __restrict__ bhi,
                         __nv_bfloat16* __restrict__ blo, int K, int N) {
    int idx = blockIdx.x * blockDim.x + threadIdx.x;
    if (idx >= N * K) return;
    int n = idx / K, k = idx - n * K;
    float v = W[(size_t)k * N + n];
    __nv_bfloat16 h = __float2bfloat16(v);
    bhi[idx] = h;
    blo[idx] = __float2bfloat16(v - __bfloat162float(h));
}

// ---------------- bf16-split GEMM: ldmatrix + cp.async double buffer ----------------
// Two products: A*Bhi + A*Blo (weight-error compensated; activation already bf16).
// mode 0: h2 = relu(D+bias) stored as bf16 hi/lo           (layer 2)
// mode 1: relu(D+bias) pooled into d_pool[batch]            (layer 3)
__global__ __launch_bounds__(256, 2)
void mma_gemm(const __nv_bfloat16* __restrict__ A,
              const __nv_bfloat16* __restrict__ Bhi, const __nv_bfloat16* __restrict__ Blo,
              const float* __restrict__ bias, const void* __restrict__ batch,
              int M, int Nglob, int K, int mode) {
    extern __shared__ __align__(16) char dynsm[];

    const int tid = threadIdx.x;
    const int wid = tid >> 5, lane = tid & 31;
    const int g = lane >> 2, tig = lane & 3;
    const int warp_m = wid & 3, warp_n = wid >> 2;
    const int row0 = blockIdx.y * 128, col0 = blockIdx.x * 128;
    const int mr = warp_m * 32, nc = warp_n * 64;

    const int t   = lane >> 3;
    const int thi = t >> 1;
    const int rlo = (t & 1) * 8 + (lane & 7);

    const uint32_t smbase = smem_u32(dynsm);
    const uint32_t stA[2] = { smbase, smbase + 32768u };
    const uint32_t stB[2] = { smbase + 16384u, smbase + 49152u };

    int rA0 = mr + rlo, rA1 = mr + 16 + rlo;
    uint32_t aoff0 = (uint32_t)(rA0 * 128), amask0 = (uint32_t)(rA0 & 7);
    uint32_t aoff1 = (uint32_t)(rA1 * 128), amask1 = (uint32_t)(rA1 & 7);
    uint32_t boff[4], bmask[4];
#pragma unroll
    for (int p = 0; p < 4; p++) {
        int rB = nc + p * 16 + rlo;
        boff[p] = (uint32_t)(rB * 128);
        bmask[p] = (uint32_t)(rB & 7);
    }

    float acc[2][8][4];
#pragma unroll
    for (int mf = 0; mf < 2; mf++)
#pragma unroll
        for (int nf = 0; nf < 8; nf++)
#pragma unroll
            for (int q = 0; q < 4; q++) acc[mf][nf][q] = 0.0f;

    const int nk = K >> 6;
    const int nchunks = 2 * nk;

    const int lr = tid >> 1;
    const int lc2 = (tid & 1) * 4;
    auto prefetch = [&](int c, int s) {
        const __nv_bfloat16* Bp;
        int kc;
        if (c < nk) { Bp = Bhi; kc = c; }
        else        { Bp = Blo; kc = c - nk; }
        const int kof = kc << 6;
        int grow = row0 + lr;
        uint32_t asz = (grow < M) ? 16u : 0u;
        const __nv_bfloat16* agp = A + (size_t)grow * K + kof + lc2 * 8;
        const __nv_bfloat16* bgp = Bp + (size_t)(col0 + lr) * K + kof + lc2 * 8;
        uint32_t arow = (uint32_t)(lr * 128);
#pragma unroll
        for (int j = 0; j < 4; j++) {
            int ch = lc2 + j;
            uint32_t soff = arow + (uint32_t)(((ch ^ (lr & 7)) << 4));
            cp_async16(stA[s] + soff, agp + j * 8, asz);
            cp_async16(stB[s] + soff, bgp + j * 8, 16u);
        }
        cp_commit();
    };

    prefetch(0, 0);
    for (int c = 0; c < nchunks; c++) {
        const int s = c & 1;
        if (c + 1 < nchunks) {
            prefetch(c + 1, (c + 1) & 1);
            asm volatile("cp.async.wait_group 1;" ::: "memory");
        } else {
            asm volatile("cp.async.wait_group 0;" ::: "memory");
        }
        __syncthreads();

#pragma unroll
        for (int ks = 0; ks < 4; ks++) {
            const uint32_t kg = (uint32_t)(2 * ks + thi);
            uint32_t a0[4], a1[4];
            ldm_x4(a0, stA[s] + aoff0 + (((kg ^ amask0) << 4)));
            ldm_x4(a1, stA[s] + aoff1 + (((kg ^ amask1) << 4)));
#pragma unroll
            for (int p = 0; p < 4; p++) {
                uint32_t bfr[4];
                ldm_x4(bfr, stB[s] + boff[p] + (((kg ^ bmask[p]) << 4)));
                mma16816(acc[0][2 * p + 0], a0, bfr[0], bfr[2]);
                mma16816(acc[0][2 * p + 1], a0, bfr[1], bfr[3]);
                mma16816(acc[1][2 * p + 0], a1, bfr[0], bfr[2]);
                mma16816(acc[1][2 * p + 1], a1, bfr[1], bfr[3]);
            }
        }
        __syncthreads();
    }

    // ---------------- epilogue ----------------
    if (mode == 0) {
#pragma unroll
        for (int mf = 0; mf < 2; mf++) {
#pragma unroll
            for (int half = 0; half < 2; half++) {
                int row = row0 + mr + mf * 16 + g + half * 8;
                if (row >= M) continue;
#pragma unroll
                for (int nf = 0; nf < 8; nf++) {
                    int col = col0 + nc + nf * 8 + tig * 2;
                    float2 bv = *(const float2*)&bias[col];
                    float v0 = fmaxf(acc[mf][nf][half * 2 + 0] + bv.x, 0.0f);
                    float v1 = fmaxf(acc[mf][nf][half * 2 + 1] + bv.y, 0.0f);
                    __nv_bfloat16 h0 = __float2bfloat16(v0), h1 = __float2bfloat16(v1);
                    size_t off = (size_t)row * D2 + col;
                    *(uint32_t*)(d_h2hi + off) = f2bf2(v0, v1);
                    *(uint32_t*)(d_h2lo + off) =
                        f2bf2(v0 - __bfloat162float(h0), v1 - __bfloat162float(h1));
                }
            }
        }
    } else {
#pragma unroll
        for (int mf = 0; mf < 2; mf++) {
            int ra = row0 + mr + mf * 16 + g;
            int v0ok = (ra < M), v1ok = (ra + 8 < M);
#pragma unroll
            for (int nf = 0; nf < 8; nf++) {
                int col = col0 + nc + nf * 8 + tig * 2;
                float2 bv = *(const float2*)&bias[col];
                acc[mf][nf][0] = v0ok ? fmaxf(acc[mf][nf][0] + bv.x, 0.0f) : 0.0f;
                acc[mf][nf][1] = v0ok ? fmaxf(acc[mf][nf][1] + bv.y, 0.0f) : 0.0f;
                acc[mf][nf][2] = v1ok ? fmaxf(acc[mf][nf][2] + bv.x, 0.0f) : 0.0f;
                acc[mf][nf][3] = v1ok ? fmaxf(acc[mf][nf][3] + bv.y, 0.0f) : 0.0f;
            }
        }
        unsigned mask = 0xffffffffu;
        int rv = row0 + mr + lane;
        int bl = (rv < N_NODES) ? load_idx(batch, rv) : -1;
        int b0 = __shfl_sync(mask, bl, 0);
        bool uni = __all_sync(mask, bl == b0);
        if (uni && b0 >= 0) {
            float s[8][2];
#pragma unroll
            for (int nf = 0; nf < 8; nf++) {
                s[nf][0] = acc[0][nf][0] + acc[0][nf][2] + acc[1][nf][0] + acc[1][nf][2];
                s[nf][1] = acc[0][nf][1] + acc[0][nf][3] + acc[1][nf][1] + acc[1][nf][3];
            }
#pragma unroll
            for (int off = 4; off < 32; off <<= 1)
#pragma unroll
                for (int nf = 0; nf < 8; nf++) {
                    s[nf][0] += __shfl_xor_sync(mask, s[nf][0], off);
                    s[nf][1] += __shfl_xor_sync(mask, s[nf][1], off);
                }
            if (lane < 4) {
#pragma unroll
                for (int nf = 0; nf < 8; nf++) {
                    int col = col0 + nc + nf * 8 + lane * 2;
                    red_add_v2(&d_pool[(size_t)b0 * D3 + col], s[nf][0], s[nf][1]);
                }
            }
        } else {
#pragma unroll
            for (int mf = 0; mf < 2; mf++)
#pragma unroll
                for (int half = 0; half < 2; half++) {
                    int row = row0 + mr + mf * 16 + g + half * 8;
                    if (row >= M) continue;
                    int gb = load_idx(batch, row);
#pragma unroll
                    for (int nf = 0; nf < 8; nf++) {
                        int col = col0 + nc + nf * 8 + tig * 2;
                        red_add_v2(&d_pool[(size_t)gb * D3 + col],
                                   acc[mf][nf][half * 2], acc[mf][nf][half * 2 + 1]);
                    }
                }
        }
    }
}

// ---------------- final linear [16,1024] @ [1024,1024] ----------------
__global__ void k_final(const float* __restrict__ Wo, const float* __restrict__ bo,
                        float* __restrict__ out) {
    __shared__ __align__(16) float sp[256][NGRAPH];
    __shared__ float sinv[NGRAPH];
    int tid = threadIdx.x;
    int c = blockIdx.x * 256 + tid;
    if (tid < NGRAPH) sinv[tid] = 1.0f / fmaxf(d_cnt[tid], 1.0f);
    float acc[NGRAPH];
#pragma unroll
    for (int g = 0; g < NGRAPH; g++) acc[g] = 0.0f;

    for (int kc = 0; kc < D3 / 256; kc++) {
        __syncthreads();
        for (int i = tid; i < 256 * NGRAPH; i += 256) {
            int k = i >> 4, g = i & 15;
            sp[k][g] = d_pool[(size_t)g * D3 + kc * 256 + k];
        }
        __syncthreads();
#pragma unroll 4
        for (int k = 0; k < 256; k++) {
            float w = Wo[(size_t)(kc * 256 + k) * D3 + c];
            const float4* pr = (const float4*)sp[k];
#pragma unroll
            for (int q = 0; q < 4; q++) {
                float4 pv = pr[q];
                acc[q * 4 + 0] = fmaf(pv.x, w, acc[q * 4 + 0]);
                acc[q * 4 + 1] = fmaf(pv.y, w, acc[q * 4 + 1]);
                acc[q * 4 + 2] = fmaf(pv.z, w, acc[q * 4 + 2]);
                acc[q * 4 + 3] = fmaf(pv.w, w, acc[q * 4 + 3]);
            }
        }
    }
    float b = bo[c];
#pragma unroll
    for (int g = 0; g < NGRAPH; g++)
        out[(size_t)g * D3 + c] = acc[g] * sinv[g] + b;
}

// ---------------- launcher ----------------
extern "C" void kernel_launch(void* const* d_in, const int* in_sizes, int n_in,
                              void* d_out, int out_size) {
    const float *x, *W1, *b1, *W2, *b2, *W3, *b3, *Wo, *bo;
    const void *ei, *batch;
    if (in_sizes[0] == N_NODES) {           // dict order
        x     = (const float*)d_in[0];
        ei    = d_in[1];
        batch = d_in[2];
        W1 = (const float*)d_in[3];  b1 = (const float*)d_in[4];
        W2 = (const float*)d_in[5];  b2 = (const float*)d_in[6];
        W3 = (const float*)d_in[7];  b3 = (const float*)d_in[8];
        Wo = (const float*)d_in[9];  bo = (const float*)d_in[10];
    } else {                                // alphabetical order
        W1 = (const float*)d_in[0];
        W2 = (const float*)d_in[1];
        W3 = (const float*)d_in[2];
        Wo = (const float*)d_in[3];
        b1 = (const float*)d_in[4];
        b2 = (const float*)d_in[5];
        b3 = (const float*)d_in[6];
        batch = d_in[7];
        bo = (const float*)d_in[8];
        ei = d_in[9];
        x  = (const float*)d_in[10];
    }
    float* out = (float*)d_out;

    __nv_bfloat16 *a2hi, *a3hi, *b2hi, *b2lo, *b3hi, *b3lo;
    cudaGetSymbolAddress((void**)&a2hi, d_a2hi);
    cudaGetSymbolAddress((void**)&a3hi, d_a3hi);
    cudaGetSymbolAddress((void**)&b2hi, d_b2hi);
    cudaGetSymbolAddress((void**)&b2lo, d_b2lo);
    cudaGetSymbolAddress((void**)&b3hi, d_b3hi);
    cudaGetSymbolAddress((void**)&b3lo, d_b3lo);

    static int smem_set = 0;
    if (!smem_set) {
        cudaFuncSetAttribute(mma_gemm, cudaFuncAttributeMaxDynamicSharedMemorySize, 65536);
        smem_set = 1;
    }

    const int TB = 256;
    int nb_nodes = (N_NODES + TB - 1) / TB;
    int nb_edges = (N_EDGES + TB - 1) / TB;
    int nb_node8 = (N_NODES + 7) / 8;

    k_detect<<<1, 32>>>(ei);
    k_init<<<nb_nodes, TB>>>();
    k_deg_edges<<<nb_edges, TB>>>(ei);
    k_dis_s1<<<nb_nodes, TB>>>(x);
    k_scan<<<1, 1024>>>();
    k_fill<<<nb_edges, TB>>>(ei, x);
    k_cnt<<<nb_nodes, TB>>>(batch);

    // weight transposition + bf16 split (independent of graph pipeline)
    k_wsplit<<<(D2 * D1 + TB - 1) / TB, TB>>>(W2, b2hi, b2lo, D1, D2);
    k_wsplit<<<(D3 * D2 + TB - 1) / TB, TB>>>(W3, b3hi, b3lo, D2, D3);

    // layer 1: gather A_hat @ h1 (rank-1), emit bf16 directly
    k_gather1<<<nb_node8, TB>>>(W1, b1);

    // layer 2 GEMM: h2 = relu(a2 @ W2 + b2) stored bf16 hi/lo
    {
        dim3 grid(D2 / 128, (N_NODES + 127) / 128);
        mma_gemm<<<grid, 256, 65536>>>(a2hi, b2hi, b2lo, b2, nullptr, N_NODES, D2, D1, 0);
    }

    // layer 2 aggregation: gather, emit a3 bf16 directly
    k_gather2<<<nb_node8, TB>>>();

    // layer 3 GEMM with fused pooling
    {
        dim3 grid(D3 / 128, (N_NODES + 127) / 128);
        mma_gemm<<<grid, 256, 65536>>>(a3hi, b3hi, b3lo, b3, batch, N_NODES, D3, D2, 1);
    }

    k_final<<<4, 256>>>(Wo, bo, out);
}

// round 9
// speedup vs baseline: 2.2941x; 1.0600x over previous
#include <cuda_runtime.h>
#include <cuda_bf16.h>
#include <cstdint>

#define N_NODES 30000
#define N_EDGES 240000
#define NGRAPH  16
#define D1      256
#define D2      512
#define D3      1024

// ---------------- scratch (no allocations allowed) ----------------
__device__ int   d_idx64;            // 1 if indices are int64, 0 if int32
__device__ int   d_cin[N_NODES];     // in-degree (edges only)
__device__ int   d_rowptr[N_NODES + 1];
__device__ int   d_cursor[N_NODES];
__device__ __align__(16) int2 d_epay[N_EDGES];      // (src, norm-bits) CSR payload
__device__ float d_dis[N_NODES];
__device__ float d_s1 [N_NODES];
__device__ __align__(16) float d_pool[NGRAPH * D3];
__device__ float d_cnt[NGRAPH];

// bf16 operand & activation buffers (activations single bf16; weights hi/lo)
__device__ __align__(16) __nv_bfloat16 d_a2hi[N_NODES * D1];
__device__ __align__(16) __nv_bfloat16 d_h2hi[N_NODES * D2];
__device__ __align__(16) __nv_bfloat16 d_h2lo[N_NODES * D2];
__device__ __align__(16) __nv_bfloat16 d_a3hi[N_NODES * D2];
__device__ __align__(16) __nv_bfloat16 d_b2hi[D2 * D1];   // [N=512, K=256] K-major
__device__ __align__(16) __nv_bfloat16 d_b2lo[D2 * D1];
__device__ __align__(16) __nv_bfloat16 d_b3hi[D3 * D2];   // [N=1024, K=512] K-major
__device__ __align__(16) __nv_bfloat16 d_b3lo[D3 * D2];

// ---------------- small helpers ----------------
__device__ __forceinline__ int load_idx(const void* p, int i) {
    if (d_idx64) return (int)((const long long*)p)[i];
    return ((const int*)p)[i];
}
__device__ __forceinline__ void red_add_v2(float* p, float x, float y) {
    asm volatile("red.global.add.v2.f32 [%0], {%1,%2};"
                 :: "l"(p), "f"(x), "f"(y) : "memory");
}
__device__ __forceinline__ uint32_t smem_u32(const void* p) {
    uint32_t a;
    asm("{ .reg .u64 t; cvta.to.shared.u64 t, %1; cvt.u32.u64 %0, t; }" : "=r"(a) : "l"(p));
    return a;
}
__device__ __forceinline__ void ldm_x4(uint32_t* r, uint32_t addr) {
    asm volatile("ldmatrix.sync.aligned.m8n8.x4.shared.b16 {%0,%1,%2,%3}, [%4];"
                 : "=r"(r[0]), "=r"(r[1]), "=r"(r[2]), "=r"(r[3]) : "r"(addr));
}
__device__ __forceinline__ void cp_async16(uint32_t dst, const void* src, uint32_t srcsize) {
    asm volatile("cp.async.cg.shared.global [%0], [%1], 16, %2;"
                 :: "r"(dst), "l"(src), "r"(srcsize) : "memory");
}
__device__ __forceinline__ void cp_commit(void) {
    asm volatile("cp.async.commit_group;" ::: "memory");
}
__device__ __forceinline__ void mma16816(float* c, const uint32_t* a, uint32_t b0, uint32_t b1) {
    asm volatile(
        "mma.sync.aligned.m16n8k16.row.col.f32.bf16.bf16.f32 "
        "{%0,%1,%2,%3}, {%4,%5,%6,%7}, {%8,%9}, {%0,%1,%2,%3};"
        : "+f"(c[0]), "+f"(c[1]), "+f"(c[2]), "+f"(c[3])
        : "r"(a[0]), "r"(a[1]), "r"(a[2]), "r"(a[3]), "r"(b0), "r"(b1));
}
__device__ __forceinline__ float2 bf2f(uint32_t u) {
    __nv_bfloat162 h = *reinterpret_cast<__nv_bfloat162*>(&u);
    return __bfloat1622float2(h);
}
__device__ __forceinline__ uint32_t f2bf2(float a, float b) {
    __nv_bfloat162 h = __floats2bfloat162_rn(a, b);
    return *reinterpret_cast<uint32_t*>(&h);
}

// ---------------- setup (init + dtype detect fused) ----------------
__global__ void k_init(const void* __restrict__ ei) {
    int i = blockIdx.x * blockDim.x + threadIdx.x;
    if (i < N_NODES) d_cin[i] = 0;
    if (i < NGRAPH) d_cnt[i] = 0.0f;
    if (i < NGRAPH * D3) d_pool[i] = 0.0f;
    if (i == 0) {
        const long long* p = (const long long*)ei;
        int ok = 1;
        for (int j = 0; j < 64; j++) {
            long long v = p[j];
            if (v < 0 || v >= N_NODES) { ok = 0; break; }
        }
        d_idx64 = ok;
    }
}

// in-degree count + batch count in one pass
__global__ void k_deg_cnt(const void* __restrict__ ei, const void* __restrict__ batch) {
    int i = blockIdx.x * blockDim.x + threadIdx.x;
    if (i < N_EDGES) atomicAdd(&d_cin[load_idx(ei, N_EDGES + i)], 1);
    if (i < N_NODES) atomicAdd(&d_cnt[load_idx(batch, i)], 1.0f);
}

__global__ void k_dis_s1(const float* __restrict__ x) {
    int i = blockIdx.x * blockDim.x + threadIdx.x;
    if (i >= N_NODES) return;
    float r = rsqrtf((float)(d_cin[i] + 1));
    d_dis[i] = r;
    d_s1[i]  = r * r * x[i];        // self-loop term of A_hat @ x
}

// single-block exclusive scan over in-degrees -> rowptr, cursor
__global__ void k_scan(void) {
    __shared__ int part[1024];
    int tid = threadIdx.x;
    const int PER = (N_NODES + 1023) / 1024;
    int base = tid * PER;
    int sum = 0;
    for (int j = 0; j < PER; j++) {
        int i = base + j;
        if (i < N_NODES) sum += d_cin[i];
    }
    part[tid] = sum;
    __syncthreads();
    for (int off = 1; off < 1024; off <<= 1) {
        int v = (tid >= off) ? part[tid - off] : 0;
        __syncthreads();
        part[tid] += v;
        __syncthreads();
    }
    int run = (tid ? part[tid - 1] : 0);
    for (int j = 0; j < PER; j++) {
        int i = base + j;
        if (i < N_NODES) {
            d_rowptr[i] = run;
            d_cursor[i] = run;
            run += d_cin[i];
        }
    }
    if (tid == 1023) d_rowptr[N_NODES] = run;
}

// CSR fill + edge contribution to s1
__global__ void k_fill(const void* __restrict__ ei, const float* __restrict__ x) {
    int e = blockIdx.x * blockDim.x + threadIdx.x;
    if (e >= N_EDGES) return;
    int s = load_idx(ei, e), d = load_idx(ei, N_EDGES + e);
    float nv = d_dis[s] * d_dis[d];
    int pos = atomicAdd(&d_cursor[d], 1);
    d_epay[pos] = make_int2(s, __float_as_int(nv));
    atomicAdd(&d_s1[d], nv * x[s]);
}

// ---------------- layer 1 gather: a2 = bf16(A_hat @ h1), h1 rank-1 on the fly ----------------
__global__ __launch_bounds__(256)
void k_gather1(const float* __restrict__ W1, const float* __restrict__ b1) {
    __shared__ float sW[D1], sB[D1];
    int tid = threadIdx.x;
    if (tid < D1) { sW[tid] = W1[tid]; sB[tid] = b1[tid]; }
    __syncthreads();
    int warp = tid >> 5, lane = tid & 31;
    int node = blockIdx.x * 8 + warp;
    if (node >= N_NODES) return;
    float w[8], b[8];
#pragma unroll
    for (int q = 0; q < 8; q++) { w[q] = sW[lane * 8 + q]; b[q] = sB[lane * 8 + q]; }
    float acc[8];
    float dis = d_dis[node];
    float coef = dis * dis, sv = d_s1[node];
#pragma unroll
    for (int q = 0; q < 8; q++) acc[q] = coef * fmaxf(fmaf(sv, w[q], b[q]), 0.0f);
    int beg = d_rowptr[node], end = d_rowptr[node + 1];
    for (int e = beg; e < end; e++) {
        int2 pay = d_epay[e];
        float nv = __int_as_float(pay.y);
        float s = d_s1[pay.x];
#pragma unroll
        for (int q = 0; q < 8; q++) acc[q] = fmaf(nv, fmaxf(fmaf(s, w[q], b[q]), 0.0f), acc[q]);
    }
    uint32_t hw[4];
#pragma unroll
    for (int q2 = 0; q2 < 4; q2++) hw[q2] = f2bf2(acc[q2 * 2], acc[q2 * 2 + 1]);
    size_t off = (size_t)node * D1 + lane * 8;
    *(uint4*)(d_a2hi + off) = make_uint4(hw[0], hw[1], hw[2], hw[3]);
}

// ---------------- layer 2 gather: a3 = bf16(A_hat @ h2), h2 stored hi/lo ----------------
__device__ __forceinline__ void acc_row16(float* acc, int row, float nv, int lane) {
    size_t off = (size_t)row * D2 + lane * 16;
    uint4 h0 = *(const uint4*)(d_h2hi + off);
    uint4 h1 = *(const uint4*)(d_h2hi + off + 8);
    uint4 l0 = *(const uint4*)(d_h2lo + off);
    uint4 l1 = *(const uint4*)(d_h2lo + off + 8);
    const uint32_t hu[8] = {h0.x, h0.y, h0.z, h0.w, h1.x, h1.y, h1.z, h1.w};
    const uint32_t lu[8] = {l0.x, l0.y, l0.z, l0.w, l1.x, l1.y, l1.z, l1.w};
#pragma unroll
    for (int q = 0; q < 8; q++) {
        float2 hv = bf2f(hu[q]);
        float2 lv = bf2f(lu[q]);
        acc[q * 2 + 0] = fmaf(nv, hv.x + lv.x, acc[q * 2 + 0]);
        acc[q * 2 + 1] = fmaf(nv, hv.y + lv.y, acc[q * 2 + 1]);
    }
}

__global__ __launch_bounds__(256)
void k_gather2(void) {
    int tid = threadIdx.x;
    int warp = tid >> 5, lane = tid & 31;
    int node = blockIdx.x * 8 + warp;
    if (node >= N_NODES) return;
    float acc[16];
#pragma unroll
    for (int q = 0; q < 16; q++) acc[q] = 0.0f;
    float dis = d_dis[node];
    acc_row16(acc, node, dis * dis, lane);
    int beg = d_rowptr[node], end = d_rowptr[node + 1];
    for (int e = beg; e < end; e++) {
        int2 pay = d_epay[e];
        acc_row16(acc, pay.x, __int_as_float(pay.y), lane);
    }
    uint32_t hw[8];
#pragma unroll
    for (int q2 = 0; q2 < 8; q2++) hw[q2] = f2bf2(acc[q2 * 2], acc[q2 * 2 + 1]);
    size_t off = (size_t)node * D2 + lane * 16;
    *(uint4*)(d_a3hi + off)     = make_uint4(hw[0], hw[1], hw[2], hw[3]);
    *(uint4*)(d_a3hi + off + 8) = make_uint4(hw[4], hw[5], hw[6], hw[7]);
}

// W [K, N] fp32 row-major -> B [N, K] bf16 hi/lo (transposed, K-major)
__global__ void k_wsplit(const float* __restrict__ W, __nv_bfloat16* __restrict__ bhi,
                         __nv_bfloat16* __restrict__ blo, int K, int N) {
    int idx = blockIdx.x * blockDim.x + threadIdx.x;
    if (idx >= N * K) return;
    int n = idx / K, k = idx - n * K;
    float v = W[(size_t)k * N + n];
    __nv_bfloat16 h = __float2bfloat16(v);
    bhi[idx] = h;
    blo[idx] = __float2bfloat16(v - __bfloat162float(h));
}

// ---------------- bf16-split GEMM: single-pass A, {A,Bhi,Blo} stages ----------------
// D = A @ (Whi + Wlo). Per k-chunk the A tile is loaded once and the a-fragments
// are reused for both the hi and lo products (10 ldmatrix / 32 mma per ks).
// Stage = A(16KB) + Bhi(16KB) + Blo(16KB) = 48KB; 2 stages = 96KB; 2 CTAs/SM.
// mode 0: h2 = relu(D+bias) stored as bf16 hi/lo           (layer 2)
// mode 1: relu(D+bias) pooled into d_pool[batch]            (layer 3)
__global__ __launch_bounds__(256, 2)
void mma_gemm(const __nv_bfloat16* __restrict__ A,
              const __nv_bfloat16* __restrict__ Bhi, const __nv_bfloat16* __restrict__ Blo,
              const float* __restrict__ bias, const void* __restrict__ batch,
              int M, int Nglob, int K, int mode) {
    extern __shared__ __align__(16) char dynsm[];

    const int tid = threadIdx.x;
    const int wid = tid >> 5, lane = tid & 31;
    const int g = lane >> 2, tig = lane & 3;
    const int warp_m = wid & 3, warp_n = wid >> 2;
    const int row0 = blockIdx.y * 128, col0 = blockIdx.x * 128;
    const int mr = warp_m * 32, nc = warp_n * 64;

    const int t   = lane >> 3;
    const int thi = t >> 1;
    const int rlo = (t & 1) * 8 + (lane & 7);

    const uint32_t smbase = smem_u32(dynsm);
    const uint32_t stA[2]  = { smbase,          smbase + 49152u };
    const uint32_t stBh[2] = { smbase + 16384u, smbase + 65536u };
    const uint32_t stBl[2] = { smbase + 32768u, smbase + 81920u };

    int rA0 = mr + rlo, rA1 = mr + 16 + rlo;
    uint32_t aoff0 = (uint32_t)(rA0 * 128), amask0 = (uint32_t)(rA0 & 7);
    uint32_t aoff1 = (uint32_t)(rA1 * 128), amask1 = (uint32_t)(rA1 & 7);
    uint32_t boff[4], bmask[4];
#pragma unroll
    for (int p = 0; p < 4; p++) {
        int rB = nc + p * 16 + rlo;
        boff[p] = (uint32_t)(rB * 128);
        bmask[p] = (uint32_t)(rB & 7);
    }

    float acc[2][8][4];
#pragma unroll
    for (int mf = 0; mf < 2; mf++)
#pragma unroll
        for (int nf = 0; nf < 8; nf++)
#pragma unroll
            for (int q = 0; q < 4; q++) acc[mf][nf][q] = 0.0f;

    const int nk = K >> 6;

    const int lr = tid >> 1;
    const int lc2 = (tid & 1) * 4;
    auto prefetch = [&](int kc, int s) {
        const int kof = kc << 6;
        int grow = row0 + lr;
        uint32_t asz = (grow < M) ? 16u : 0u;
        const __nv_bfloat16* agp = A   + (size_t)grow * K + kof + lc2 * 8;
        const __nv_bfloat16* bhp = Bhi + (size_t)(col0 + lr) * K + kof + lc2 * 8;
        const __nv_bfloat16* blp = Blo + (size_t)(col0 + lr) * K + kof + lc2 * 8;
        uint32_t arow = (uint32_t)(lr * 128);
#pragma unroll
        for (int j = 0; j < 4; j++) {
            int ch = lc2 + j;
            uint32_t soff = arow + (uint32_t)(((ch ^ (lr & 7)) << 4));
            cp_async16(stA[s] + soff, agp + j * 8, asz);
            cp_async16(stBh[s] + soff, bhp + j * 8, 16u);
            cp_async16(stBl[s] + soff, blp + j * 8, 16u);
        }
        cp_commit();
    };

    prefetch(0, 0);
    for (int kc = 0; kc < nk; kc++) {
        const int s = kc & 1;
        if (kc + 1 < nk) {
            prefetch(kc + 1, s ^ 1);
            asm volatile("cp.async.wait_group 1;" ::: "memory");
        } else {
            asm volatile("cp.async.wait_group 0;" ::: "memory");
        }
        __syncthreads();

#pragma unroll
        for (int ks = 0; ks < 4; ks++) {
            const uint32_t kg = (uint32_t)(2 * ks + thi);
            uint32_t a0[4], a1[4];
            ldm_x4(a0, stA[s] + aoff0 + (((kg ^ amask0) << 4)));
            ldm_x4(a1, stA[s] + aoff1 + (((kg ^ amask1) << 4)));
#pragma unroll
            for (int p = 0; p < 4; p++) {
                uint32_t bh[4], bl[4];
                uint32_t bo_ = boff[p] + (((kg ^ bmask[p]) << 4));
                ldm_x4(bh, stBh[s] + bo_);
                ldm_x4(bl, stBl[s] + bo_);
                mma16816(acc[0][2 * p + 0], a0, bh[0], bh[2]);
                mma16816(acc[0][2 * p + 1], a0, bh[1], bh[3]);
                mma16816(acc[1][2 * p + 0], a1, bh[0], bh[2]);
                mma16816(acc[1][2 * p + 1], a1, bh[1], bh[3]);
                mma16816(acc[0][2 * p + 0], a0, bl[0], bl[2]);
                mma16816(acc[0][2 * p + 1], a0, bl[1], bl[3]);
                mma16816(acc[1][2 * p + 0], a1, bl[0], bl[2]);
                mma16816(acc[1][2 * p + 1], a1, bl[1], bl[3]);
            }
        }
        __syncthreads();
    }

    // ---------------- epilogue ----------------
    if (mode == 0) {
#pragma unroll
        for (int mf = 0; mf < 2; mf++) {
#pragma unroll
            for (int half = 0; half < 2; half++) {
                int row = row0 + mr + mf * 16 + g + half * 8;
                if (row >= M) continue;
#pragma unroll
                for (int nf = 0; nf < 8; nf++) {
                    int col = col0 + nc + nf * 8 + tig * 2;
                    float2 bv = *(const float2*)&bias[col];
                    float v0 = fmaxf(acc[mf][nf][half * 2 + 0] + bv.x, 0.0f);
                    float v1 = fmaxf(acc[mf][nf][half * 2 + 1] + bv.y, 0.0f);
                    __nv_bfloat16 h0 = __float2bfloat16(v0), h1 = __float2bfloat16(v1);
                    size_t off = (size_t)row * D2 + col;
                    *(uint32_t*)(d_h2hi + off) = f2bf2(v0, v1);
                    *(uint32_t*)(d_h2lo + off) =
                        f2bf2(v0 - __bfloat162float(h0), v1 - __bfloat162float(h1));
                }
            }
        }
    } else {
#pragma unroll
        for (int mf = 0; mf < 2; mf++) {
            int ra = row0 + mr + mf * 16 + g;
            int v0ok = (ra < M), v1ok = (ra + 8 < M);
#pragma unroll
            for (int nf = 0; nf < 8; nf++) {
                int col = col0 + nc + nf * 8 + tig * 2;
                float2 bv = *(const float2*)&bias[col];
                acc[mf][nf][0] = v0ok ? fmaxf(acc[mf][nf][0] + bv.x, 0.0f) : 0.0f;
                acc[mf][nf][1] = v0ok ? fmaxf(acc[mf][nf][1] + bv.y, 0.0f) : 0.0f;
                acc[mf][nf][2] = v1ok ? fmaxf(acc[mf][nf][2] + bv.x, 0.0f) : 0.0f;
                acc[mf][nf][3] = v1ok ? fmaxf(acc[mf][nf][3] + bv.y, 0.0f) : 0.0f;
            }
        }
        unsigned mask = 0xffffffffu;
        int rv = row0 + mr + lane;
        int bl = (rv < N_NODES) ? load_idx(batch, rv) : -1;
        int b0 = __shfl_sync(mask, bl, 0);
        bool uni = __all_sync(mask, bl == b0);
        if (uni && b0 >= 0) {
            float s[8][2];
#pragma unroll
            for (int nf = 0; nf < 8; nf++) {
                s[nf][0] = acc[0][nf][0] + acc[0][nf][2] + acc[1][nf][0] + acc[1][nf][2];
                s[nf][1] = acc[0][nf][1] + acc[0][nf][3] + acc[1][nf][1] + acc[1][nf][3];
            }
#pragma unroll
            for (int off = 4; off < 32; off <<= 1)
#pragma unroll
                for (int nf = 0; nf < 8; nf++) {
                    s[nf][0] += __shfl_xor_sync(mask, s[nf][0], off);
                    s[nf][1] += __shfl_xor_sync(mask, s[nf][1], off);
                }
            if (lane < 4) {
#pragma unroll
                for (int nf = 0; nf < 8; nf++) {
                    int col = col0 + nc + nf * 8 + lane * 2;
                    red_add_v2(&d_pool[(size_t)b0 * D3 + col], s[nf][0], s[nf][1]);
                }
            }
        } else {
#pragma unroll
            for (int mf = 0; mf < 2; mf++)
#pragma unroll
                for (int half = 0; half < 2; half++) {
                    int row = row0 + mr + mf * 16 + g + half * 8;
                    if (row >= M) continue;
                    int gb = load_idx(batch, row);
#pragma unroll
                    for (int nf = 0; nf < 8; nf++) {
                        int col = col0 + nc + nf * 8 + tig * 2;
                        red_add_v2(&d_pool[(size_t)gb * D3 + col],
                                   acc[mf][nf][half * 2], acc[mf][nf][half * 2 + 1]);
                    }
                }
        }
    }
}

// ---------------- final linear [16,1024] @ [1024,1024] ----------------
__global__ void k_final(const float* __restrict__ Wo, const float* __restrict__ bo,
                        float* __restrict__ out) {
    __shared__ __align__(16) float sp[256][NGRAPH];
    __shared__ float sinv[NGRAPH];
    int tid = threadIdx.x;
    int c = blockIdx.x * 256 + tid;
    if (tid < NGRAPH) sinv[tid] = 1.0f / fmaxf(d_cnt[tid], 1.0f);
    float acc[NGRAPH];
#pragma unroll
    for (int g = 0; g < NGRAPH; g++) acc[g] = 0.0f;

    for (int kc = 0; kc < D3 / 256; kc++) {
        __syncthreads();
        for (int i = tid; i < 256 * NGRAPH; i += 256) {
            int k = i >> 4, g = i & 15;
            sp[k][g] = d_pool[(size_t)g * D3 + kc * 256 + k];
        }
        __syncthreads();
#pragma unroll 4
        for (int k = 0; k < 256; k++) {
            float w = Wo[(size_t)(kc * 256 + k) * D3 + c];
            const float4* pr = (const float4*)sp[k];
#pragma unroll
            for (int q = 0; q < 4; q++) {
                float4 pv = pr[q];
                acc[q * 4 + 0] = fmaf(pv.x, w, acc[q * 4 + 0]);
                acc[q * 4 + 1] = fmaf(pv.y, w, acc[q * 4 + 1]);
                acc[q * 4 + 2] = fmaf(pv.z, w, acc[q * 4 + 2]);
                acc[q * 4 + 3] = fmaf(pv.w, w, acc[q * 4 + 3]);
            }
        }
    }
    float b = bo[c];
#pragma unroll
    for (int g = 0; g < NGRAPH; g++)
        out[(size_t)g * D3 + c] = acc[g] * sinv[g] + b;
}

// ---------------- launcher ----------------
extern "C" void kernel_launch(void* const* d_in, const int* in_sizes, int n_in,
                              void* d_out, int out_size) {
    const float *x, *W1, *b1, *W2, *b2, *W3, *b3, *Wo, *bo;
    const void *ei, *batch;
    if (in_sizes[0] == N_NODES) {           // dict order
        x     = (const float*)d_in[0];
        ei    = d_in[1];
        batch = d_in[2];
        W1 = (const float*)d_in[3];  b1 = (const float*)d_in[4];
        W2 = (const float*)d_in[5];  b2 = (const float*)d_in[6];
        W3 = (const float*)d_in[7];  b3 = (const float*)d_in[8];
        Wo = (const float*)d_in[9];  bo = (const float*)d_in[10];
    } else {                                // alphabetical order
        W1 = (const float*)d_in[0];
        W2 = (const float*)d_in[1];
        W3 = (const float*)d_in[2];
        Wo = (const float*)d_in[3];
        b1 = (const float*)d_in[4];
        b2 = (const float*)d_in[5];
        b3 = (const float*)d_in[6];
        batch = d_in[7];
        bo = (const float*)d_in[8];
        ei = d_in[9];
        x  = (const float*)d_in[10];
    }
    float* out = (float*)d_out;

    __nv_bfloat16 *a2hi, *a3hi, *b2hi, *b2lo, *b3hi, *b3lo;
    cudaGetSymbolAddress((void**)&a2hi, d_a2hi);
    cudaGetSymbolAddress((void**)&a3hi, d_a3hi);
    cudaGetSymbolAddress((void**)&b2hi, d_b2hi);
    cudaGetSymbolAddress((void**)&b2lo, d_b2lo);
    cudaGetSymbolAddress((void**)&b3hi, d_b3hi);
    cudaGetSymbolAddress((void**)&b3lo, d_b3lo);

    static int smem_set = 0;
    if (!smem_set) {
        cudaFuncSetAttribute(mma_gemm, cudaFuncAttributeMaxDynamicSharedMemorySize, 98304);
        smem_set = 1;
    }

    const int TB = 256;
    int nb_nodes = (N_NODES + TB - 1) / TB;
    int nb_edges = (N_EDGES + TB - 1) / TB;
    int nb_node8 = (N_NODES + 7) / 8;

    k_init<<<nb_nodes, TB>>>(ei);
    k_deg_cnt<<<nb_edges, TB>>>(ei, batch);
    k_dis_s1<<<nb_nodes, TB>>>(x);
    k_scan<<<1, 1024>>>();
    k_fill<<<nb_edges, TB>>>(ei, x);

    // weight transposition + bf16 split (independent of graph pipeline)
    k_wsplit<<<(D2 * D1 + TB - 1) / TB, TB>>>(W2, b2hi, b2lo, D1, D2);
    k_wsplit<<<(D3 * D2 + TB - 1) / TB, TB>>>(W3, b3hi, b3lo, D2, D3);

    // layer 1: gather A_hat @ h1 (rank-1), emit bf16 directly
    k_gather1<<<nb_node8, TB>>>(W1, b1);

    // layer 2 GEMM: h2 = relu(a2 @ W2 + b2) stored bf16 hi/lo
    {
        dim3 grid(D2 / 128, (N_NODES + 127) / 128);
        mma_gemm<<<grid, 256, 98304>>>(a2hi, b2hi, b2lo, b2, nullptr, N_NODES, D2, D1, 0);
    }

    // layer 2 aggregation: gather, emit a3 bf16 directly
    k_gather2<<<nb_node8, TB>>>();

    // layer 3 GEMM with fused pooling
    {
        dim3 grid(D3 / 128, (N_NODES + 127) / 128);
        mma_gemm<<<grid, 256, 98304>>>(a3hi, b3hi, b3lo, b3, batch, N_NODES, D3, D2, 1);
    }

    k_final<<<4, 256>>>(Wo, bo, out);
}

// round 10
// speedup vs baseline: 2.5716x; 1.1210x over previous
#include <cuda_runtime.h>
#include <cuda_bf16.h>
#include <cstdint>

#define N_NODES 30000
#define N_EDGES 240000
#define NGRAPH  16
#define D1      256
#define D2      512
#define D3      1024

// ---------------- scratch (no allocations allowed) ----------------
__device__ int   d_idx64;            // 1 if indices are int64, 0 if int32
__device__ int   d_alloc;            // CSR segment allocator
__device__ int   d_cin[N_NODES];     // in-degree (edges only)
__device__ int   d_rowptr[N_NODES];  // segment start per node (arbitrary order)
__device__ int   d_cursor[N_NODES];
__device__ __align__(16) int2 d_epay[N_EDGES];      // (src, norm-bits) CSR payload
__device__ float d_dis[N_NODES];
__device__ float d_s1 [N_NODES];
__device__ __align__(16) float d_pool[NGRAPH * D3];
__device__ float d_cnt[NGRAPH];

// bf16 operand & activation buffers (activations single bf16; weights hi/lo)
__device__ __align__(16) __nv_bfloat16 d_a2hi[N_NODES * D1];
__device__ __align__(16) __nv_bfloat16 d_h2hi[N_NODES * D2];
__device__ __align__(16) __nv_bfloat16 d_a3hi[N_NODES * D2];
__device__ __align__(16) __nv_bfloat16 d_b2hi[D2 * D1];   // [N=512, K=256] K-major
__device__ __align__(16) __nv_bfloat16 d_b2lo[D2 * D1];
__device__ __align__(16) __nv_bfloat16 d_b3hi[D3 * D2];   // [N=1024, K=512] K-major
__device__ __align__(16) __nv_bfloat16 d_b3lo[D3 * D2];

// ---------------- small helpers ----------------
__device__ __forceinline__ int load_idx(const void* p, int i) {
    if (d_idx64) return (int)((const long long*)p)[i];
    return ((const int*)p)[i];
}
__device__ __forceinline__ void red_add_v2(float* p, float x, float y) {
    asm volatile("red.global.add.v2.f32 [%0], {%1,%2};"
                 :: "l"(p), "f"(x), "f"(y) : "memory");
}
__device__ __forceinline__ uint32_t smem_u32(const void* p) {
    uint32_t a;
    asm("{ .reg .u64 t; cvta.to.shared.u64 t, %1; cvt.u32.u64 %0, t; }" : "=r"(a) : "l"(p));
    return a;
}
__device__ __forceinline__ void ldm_x4(uint32_t* r, uint32_t addr) {
    asm volatile("ldmatrix.sync.aligned.m8n8.x4.shared.b16 {%0,%1,%2,%3}, [%4];"
                 : "=r"(r[0]), "=r"(r[1]), "=r"(r[2]), "=r"(r[3]) : "r"(addr));
}
__device__ __forceinline__ void cp_async16(uint32_t dst, const void* src, uint32_t srcsize) {
    asm volatile("cp.async.cg.shared.global [%0], [%1], 16, %2;"
                 :: "r"(dst), "l"(src), "r"(srcsize) : "memory");
}
__device__ __forceinline__ void cp_commit(void) {
    asm volatile("cp.async.commit_group;" ::: "memory");
}
__device__ __forceinline__ void mma16816(float* c, const uint32_t* a, uint32_t b0, uint32_t b1) {
    asm volatile(
        "mma.sync.aligned.m16n8k16.row.col.f32.bf16.bf16.f32 "
        "{%0,%1,%2,%3}, {%4,%5,%6,%7}, {%8,%9}, {%0,%1,%2,%3};"
        : "+f"(c[0]), "+f"(c[1]), "+f"(c[2]), "+f"(c[3])
        : "r"(a[0]), "r"(a[1]), "r"(a[2]), "r"(a[3]), "r"(b0), "r"(b1));
}
__device__ __forceinline__ float2 bf2f(uint32_t u) {
    __nv_bfloat162 h = *reinterpret_cast<__nv_bfloat162*>(&u);
    return __bfloat1622float2(h);
}
__device__ __forceinline__ uint32_t f2bf2(float a, float b) {
    __nv_bfloat162 h = __floats2bfloat162_rn(a, b);
    return *reinterpret_cast<uint32_t*>(&h);
}

// ---------------- setup (init + dtype detect fused) ----------------
__global__ void k_init(const void* __restrict__ ei) {
    int i = blockIdx.x * blockDim.x + threadIdx.x;
    if (i < N_NODES) d_cin[i] = 0;
    if (i < NGRAPH) d_cnt[i] = 0.0f;
    if (i < NGRAPH * D3) d_pool[i] = 0.0f;
    if (i == 0) {
        d_alloc = 0;
        const long long* p = (const long long*)ei;
        int ok = 1;
        for (int j = 0; j < 64; j++) {
            long long v = p[j];
            if (v < 0 || v >= N_NODES) { ok = 0; break; }
        }
        d_idx64 = ok;
    }
}

// in-degree count + batch count in one pass
__global__ void k_deg_cnt(const void* __restrict__ ei, const void* __restrict__ batch) {
    int i = blockIdx.x * blockDim.x + threadIdx.x;
    if (i < N_EDGES) atomicAdd(&d_cin[load_idx(ei, N_EDGES + i)], 1);
    if (i < N_NODES) atomicAdd(&d_cnt[load_idx(batch, i)], 1.0f);
}

// dis/s1 + CSR segment allocation (warp-aggregated atomic, order-free)
__global__ void k_dis_s1(const float* __restrict__ x) {
    int i = blockIdx.x * blockDim.x + threadIdx.x;
    int lane = threadIdx.x & 31;
    int valid = (i < N_NODES);
    int c = valid ? d_cin[i] : 0;
    if (valid) {
        float r = rsqrtf((float)(c + 1));
        d_dis[i] = r;
        d_s1[i]  = r * r * x[i];    // self-loop term of A_hat @ x
    }
    // warp inclusive scan of c
    unsigned mask = 0xffffffffu;
    int incl = c;
#pragma unroll
    for (int off = 1; off < 32; off <<= 1) {
        int v = __shfl_up_sync(mask, incl, off);
        if (lane >= off) incl += v;
    }
    int total = __shfl_sync(mask, incl, 31);
    int base = 0;
    if (lane == 31) base = atomicAdd(&d_alloc, total);
    base = __shfl_sync(mask, base, 31);
    if (valid) {
        int start = base + incl - c;
        d_rowptr[i] = start;
        d_cursor[i] = start;
    }
}

// CSR fill + edge contribution to s1
__global__ void k_fill(const void* __restrict__ ei, const float* __restrict__ x) {
    int e = blockIdx.x * blockDim.x + threadIdx.x;
    if (e >= N_EDGES) return;
    int s = load_idx(ei, e), d = load_idx(ei, N_EDGES + e);
    float nv = d_dis[s] * d_dis[d];
    int pos = atomicAdd(&d_cursor[d], 1);
    d_epay[pos] = make_int2(s, __float_as_int(nv));
    atomicAdd(&d_s1[d], nv * x[s]);
}

// ---------------- layer 1 gather: a2 = bf16(A_hat @ h1), h1 rank-1 on the fly ----------------
__global__ __launch_bounds__(256)
void k_gather1(const float* __restrict__ W1, const float* __restrict__ b1) {
    __shared__ float sW[D1], sB[D1];
    int tid = threadIdx.x;
    if (tid < D1) { sW[tid] = W1[tid]; sB[tid] = b1[tid]; }
    __syncthreads();
    int warp = tid >> 5, lane = tid & 31;
    int node = blockIdx.x * 8 + warp;
    if (node >= N_NODES) return;
    float w[8], b[8];
#pragma unroll
    for (int q = 0; q < 8; q++) { w[q] = sW[lane * 8 + q]; b[q] = sB[lane * 8 + q]; }
    float acc[8];
    float dis = d_dis[node];
    float coef = dis * dis, sv = d_s1[node];
#pragma unroll
    for (int q = 0; q < 8; q++) acc[q] = coef * fmaxf(fmaf(sv, w[q], b[q]), 0.0f);
    int beg = d_rowptr[node], end = beg + d_cin[node];
    for (int e = beg; e < end; e++) {
        int2 pay = d_epay[e];
        float nv = __int_as_float(pay.y);
        float s = d_s1[pay.x];
#pragma unroll
        for (int q = 0; q < 8; q++) acc[q] = fmaf(nv, fmaxf(fmaf(s, w[q], b[q]), 0.0f), acc[q]);
    }
    uint32_t hw[4];
#pragma unroll
    for (int q2 = 0; q2 < 4; q2++) hw[q2] = f2bf2(acc[q2 * 2], acc[q2 * 2 + 1]);
    size_t off = (size_t)node * D1 + lane * 8;
    *(uint4*)(d_a2hi + off) = make_uint4(hw[0], hw[1], hw[2], hw[3]);
}

// ---------------- layer 2 gather: a3 = bf16(A_hat @ h2), h2 stored bf16 ----------------
__device__ __forceinline__ void acc_row16(float* acc, int row, float nv, int lane) {
    size_t off = (size_t)row * D2 + lane * 16;
    uint4 h0 = *(const uint4*)(d_h2hi + off);
    uint4 h1 = *(const uint4*)(d_h2hi + off + 8);
    const uint32_t hu[8] = {h0.x, h0.y, h0.z, h0.w, h1.x, h1.y, h1.z, h1.w};
#pragma unroll
    for (int q = 0; q < 8; q++) {
        float2 hv = bf2f(hu[q]);
        acc[q * 2 + 0] = fmaf(nv, hv.x, acc[q * 2 + 0]);
        acc[q * 2 + 1] = fmaf(nv, hv.y, acc[q * 2 + 1]);
    }
}

__global__ __launch_bounds__(256)
void k_gather2(void) {
    int tid = threadIdx.x;
    int warp = tid >> 5, lane = tid & 31;
    int node = blockIdx.x * 8 + warp;
    if (node >= N_NODES) return;
    float acc[16];
#pragma unroll
    for (int q = 0; q < 16; q++) acc[q] = 0.0f;
    float dis = d_dis[node];
    acc_row16(acc, node, dis * dis, lane);
    int beg = d_rowptr[node], end = beg + d_cin[node];
    for (int e = beg; e < end; e++) {
        int2 pay = d_epay[e];
        acc_row16(acc, pay.x, __int_as_float(pay.y), lane);
    }
    uint32_t hw[8];
#pragma unroll
    for (int q2 = 0; q2 < 8; q2++) hw[q2] = f2bf2(acc[q2 * 2], acc[q2 * 2 + 1]);
    size_t off = (size_t)node * D2 + lane * 16;
    *(uint4*)(d_a3hi + off)     = make_uint4(hw[0], hw[1], hw[2], hw[3]);
    *(uint4*)(d_a3hi + off + 8) = make_uint4(hw[4], hw[5], hw[6], hw[7]);
}

// W [K, N] fp32 row-major -> B [N, K] bf16 hi/lo (transposed, K-major)
__global__ void k_wsplit(const float* __restrict__ W, __nv_bfloat16* __restrict__ bhi,
                         __nv_bfloat16* __restrict__ blo, int K, int N) {
    int idx = blockIdx.x * blockDim.x + threadIdx.x;
    if (idx >= N * K) return;
    int n = idx / K, k = idx - n * K;
    float v = W[(size_t)k * N + n];
    __nv_bfloat16 h = __float2bfloat16(v);
    bhi[idx] = h;
    blo[idx] = __float2bfloat16(v - __bfloat162float(h));
}

// ---------------- bf16-split GEMM: single-pass A, {A,Bhi,Blo} stages ----------------
// D = A @ (Whi + Wlo). Per k-chunk the A tile is loaded once and the a-fragments
// are reused for both the hi and lo products.
// Stage = A(16KB) + Bhi(16KB) + Blo(16KB) = 48KB; 2 stages = 96KB; 2 CTAs/SM.
// mode 0: h2 = relu(D+bias) stored as bf16                  (layer 2)
// mode 1: relu(D+bias) pooled into d_pool[batch]            (layer 3)
__global__ __launch_bounds__(256, 2)
void mma_gemm(const __nv_bfloat16* __restrict__ A,
              const __nv_bfloat16* __restrict__ Bhi, const __nv_bfloat16* __restrict__ Blo,
              const float* __restrict__ bias, const void* __restrict__ batch,
              int M, int Nglob, int K, int mode) {
    extern __shared__ __align__(16) char dynsm[];

    const int tid = threadIdx.x;
    const int wid = tid >> 5, lane = tid & 31;
    const int g = lane >> 2, tig = lane & 3;
    const int warp_m = wid & 3, warp_n = wid >> 2;
    const int row0 = blockIdx.y * 128, col0 = blockIdx.x * 128;
    const int mr = warp_m * 32, nc = warp_n * 64;

    const int t   = lane >> 3;
    const int thi = t >> 1;
    const int rlo = (t & 1) * 8 + (lane & 7);

    const uint32_t smbase = smem_u32(dynsm);
    const uint32_t stA[2]  = { smbase,          smbase + 49152u };
    const uint32_t stBh[2] = { smbase + 16384u, smbase + 65536u };
    const uint32_t stBl[2] = { smbase + 32768u, smbase + 81920u };

    int rA0 = mr + rlo, rA1 = mr + 16 + rlo;
    uint32_t aoff0 = (uint32_t)(rA0 * 128), amask0 = (uint32_t)(rA0 & 7);
    uint32_t aoff1 = (uint32_t)(rA1 * 128), amask1 = (uint32_t)(rA1 & 7);
    uint32_t boff[4], bmask[4];
#pragma unroll
    for (int p = 0; p < 4; p++) {
        int rB = nc + p * 16 + rlo;
        boff[p] = (uint32_t)(rB * 128);
        bmask[p] = (uint32_t)(rB & 7);
    }

    float acc[2][8][4];
#pragma unroll
    for (int mf = 0; mf < 2; mf++)
#pragma unroll
        for (int nf = 0; nf < 8; nf++)
#pragma unroll
            for (int q = 0; q < 4; q++) acc[mf][nf][q] = 0.0f;

    const int nk = K >> 6;

    const int lr = tid >> 1;
    const int lc2 = (tid & 1) * 4;
    auto prefetch = [&](int kc, int s) {
        const int kof = kc << 6;
        int grow = row0 + lr;
        uint32_t asz = (grow < M) ? 16u : 0u;
        const __nv_bfloat16* agp = A   + (size_t)grow * K + kof + lc2 * 8;
        const __nv_bfloat16* bhp = Bhi + (size_t)(col0 + lr) * K + kof + lc2 * 8;
        const __nv_bfloat16* blp = Blo + (size_t)(col0 + lr) * K + kof + lc2 * 8;
        uint32_t arow = (uint32_t)(lr * 128);
#pragma unroll
        for (int j = 0; j < 4; j++) {
            int ch = lc2 + j;
            uint32_t soff = arow + (uint32_t)(((ch ^ (lr & 7)) << 4));
            cp_async16(stA[s] + soff, agp + j * 8, asz);
            cp_async16(stBh[s] + soff, bhp + j * 8, 16u);
            cp_async16(stBl[s] + soff, blp + j * 8, 16u);
        }
        cp_commit();
    };

    prefetch(0, 0);
    for (int kc = 0; kc < nk; kc++) {
        const int s = kc & 1;
        if (kc + 1 < nk) {
            prefetch(kc + 1, s ^ 1);
            asm volatile("cp.async.wait_group 1;" ::: "memory");
        } else {
            asm volatile("cp.async.wait_group 0;" ::: "memory");
        }
        __syncthreads();

#pragma unroll
        for (int ks = 0; ks < 4; ks++) {
            const uint32_t kg = (uint32_t)(2 * ks + thi);
            uint32_t a0[4], a1[4];
            ldm_x4(a0, stA[s] + aoff0 + (((kg ^ amask0) << 4)));
            ldm_x4(a1, stA[s] + aoff1 + (((kg ^ amask1) << 4)));
#pragma unroll
            for (int p = 0; p < 4; p++) {
                uint32_t bh[4], bl[4];
                uint32_t bo_ = boff[p] + (((kg ^ bmask[p]) << 4));
                ldm_x4(bh, stBh[s] + bo_);
                ldm_x4(bl, stBl[s] + bo_);
                mma16816(acc[0][2 * p + 0], a0, bh[0], bh[2]);
                mma16816(acc[0][2 * p + 1], a0, bh[1], bh[3]);
                mma16816(acc[1][2 * p + 0], a1, bh[0], bh[2]);
                mma16816(acc[1][2 * p + 1], a1, bh[1], bh[3]);
                mma16816(acc[0][2 * p + 0], a0, bl[0], bl[2]);
                mma16816(acc[0][2 * p + 1], a0, bl[1], bl[3]);
                mma16816(acc[1][2 * p + 0], a1, bl[0], bl[2]);
                mma16816(acc[1][2 * p + 1], a1, bl[1], bl[3]);
            }
        }
        __syncthreads();
    }

    // ---------------- epilogue ----------------
    if (mode == 0) {
#pragma unroll
        for (int mf = 0; mf < 2; mf++) {
#pragma unroll
            for (int half = 0; half < 2; half++) {
                int row = row0 + mr + mf * 16 + g + half * 8;
                if (row >= M) continue;
#pragma unroll
                for (int nf = 0; nf < 8; nf++) {
                    int col = col0 + nc + nf * 8 + tig * 2;
                    float2 bv = *(const float2*)&bias[col];
                    float v0 = fmaxf(acc[mf][nf][half * 2 + 0] + bv.x, 0.0f);
                    float v1 = fmaxf(acc[mf][nf][half * 2 + 1] + bv.y, 0.0f);
                    *(uint32_t*)(d_h2hi + (size_t)row * D2 + col) = f2bf2(v0, v1);
                }
            }
        }
    } else {
#pragma unroll
        for (int mf = 0; mf < 2; mf++) {
            int ra = row0 + mr + mf * 16 + g;
            int v0ok = (ra < M), v1ok = (ra + 8 < M);
#pragma unroll
            for (int nf = 0; nf < 8; nf++) {
                int col = col0 + nc + nf * 8 + tig * 2;
                float2 bv = *(const float2*)&bias[col];
                acc[mf][nf][0] = v0ok ? fmaxf(acc[mf][nf][0] + bv.x, 0.0f) : 0.0f;
                acc[mf][nf][1] = v0ok ? fmaxf(acc[mf][nf][1] + bv.y, 0.0f) : 0.0f;
                acc[mf][nf][2] = v1ok ? fmaxf(acc[mf][nf][2] + bv.x, 0.0f) : 0.0f;
                acc[mf][nf][3] = v1ok ? fmaxf(acc[mf][nf][3] + bv.y, 0.0f) : 0.0f;
            }
        }
        unsigned mask = 0xffffffffu;
        int rv = row0 + mr + lane;
        int bl = (rv < N_NODES) ? load_idx(batch, rv) : -1;
        int b0 = __shfl_sync(mask, bl, 0);
        bool uni = __all_sync(mask, bl == b0);
        if (uni && b0 >= 0) {
            float s[8][2];
#pragma unroll
            for (int nf = 0; nf < 8; nf++) {
                s[nf][0] = acc[0][nf][0] + acc[0][nf][2] + acc[1][nf][0] + acc[1][nf][2];
                s[nf][1] = acc[0][nf][1] + acc[0][nf][3] + acc[1][nf][1] + acc[1][nf][3];
            }
#pragma unroll
            for (int off = 4; off < 32; off <<= 1)
#pragma unroll
                for (int nf = 0; nf < 8; nf++) {
                    s[nf][0] += __shfl_xor_sync(mask, s[nf][0], off);
                    s[nf][1] += __shfl_xor_sync(mask, s[nf][1], off);
                }
            if (lane < 4) {
#pragma unroll
                for (int nf = 0; nf < 8; nf++) {
                    int col = col0 + nc + nf * 8 + lane * 2;
                    red_add_v2(&d_pool[(size_t)b0 * D3 + col], s[nf][0], s[nf][1]);
                }
            }
        } else {
#pragma unroll
            for (int mf = 0; mf < 2; mf++)
#pragma unroll
                for (int half = 0; half < 2; half++) {
                    int row = row0 + mr + mf * 16 + g + half * 8;
                    if (row >= M) continue;
                    int gb = load_idx(batch, row);
#pragma unroll
                    for (int nf = 0; nf < 8; nf++) {
                        int col = col0 + nc + nf * 8 + tig * 2;
                        red_add_v2(&d_pool[(size_t)gb * D3 + col],
                                   acc[mf][nf][half * 2], acc[mf][nf][half * 2 + 1]);
                    }
                }
        }
    }
}

// ---------------- final linear [16,1024] @ [1024,1024] ----------------
__global__ void k_final(const float* __restrict__ Wo, const float* __restrict__ bo,
                        float* __restrict__ out) {
    __shared__ __align__(16) float sp[256][NGRAPH];
    __shared__ float sinv[NGRAPH];
    int tid = threadIdx.x;
    int c = blockIdx.x * 256 + tid;
    if (tid < NGRAPH) sinv[tid] = 1.0f / fmaxf(d_cnt[tid], 1.0f);
    float acc[NGRAPH];
#pragma unroll
    for (int g = 0; g < NGRAPH; g++) acc[g] = 0.0f;

    for (int kc = 0; kc < D3 / 256; kc++) {
        __syncthreads();
        for (int i = tid; i < 256 * NGRAPH; i += 256) {
            int k = i >> 4, g = i & 15;
            sp[k][g] = d_pool[(size_t)g * D3 + kc * 256 + k];
        }
        __syncthreads();
#pragma unroll 4
        for (int k = 0; k < 256; k++) {
            float w = Wo[(size_t)(kc * 256 + k) * D3 + c];
            const float4* pr = (const float4*)sp[k];
#pragma unroll
            for (int q = 0; q < 4; q++) {
                float4 pv = pr[q];
                acc[q * 4 + 0] = fmaf(pv.x, w, acc[q * 4 + 0]);
                acc[q * 4 + 1] = fmaf(pv.y, w, acc[q * 4 + 1]);
                acc[q * 4 + 2] = fmaf(pv.z, w, acc[q * 4 + 2]);
                acc[q * 4 + 3] = fmaf(pv.w, w, acc[q * 4 + 3]);
            }
        }
    }
    float b = bo[c];
#pragma unroll
    for (int g = 0; g < NGRAPH; g++)
        out[(size_t)g * D3 + c] = acc[g] * sinv[g] + b;
}

// ---------------- launcher ----------------
extern "C" void kernel_launch(void* const* d_in, const int* in_sizes, int n_in,
                              void* d_out, int out_size) {
    const float *x, *W1, *b1, *W2, *b2, *W3, *b3, *Wo, *bo;
    const void *ei, *batch;
    if (in_sizes[0] == N_NODES) {           // dict order
        x     = (const float*)d_in[0];
        ei    = d_in[1];
        batch = d_in[2];
        W1 = (const float*)d_in[3];  b1 = (const float*)d_in[4];
        W2 = (const float*)d_in[5];  b2 = (const float*)d_in[6];
        W3 = (const float*)d_in[7];  b3 = (const float*)d_in[8];
        Wo = (const float*)d_in[9];  bo = (const float*)d_in[10];
    } else {                                // alphabetical order
        W1 = (const float*)d_in[0];
        W2 = (const float*)d_in[1];
        W3 = (const float*)d_in[2];
        Wo = (const float*)d_in[3];
        b1 = (const float*)d_in[4];
        b2 = (const float*)d_in[5];
        b3 = (const float*)d_in[6];
        batch = d_in[7];
        bo = (const float*)d_in[8];
        ei = d_in[9];
        x  = (const float*)d_in[10];
    }
    float* out = (float*)d_out;

    __nv_bfloat16 *a2hi, *a3hi, *b2hi, *b2lo, *b3hi, *b3lo;
    cudaGetSymbolAddress((void**)&a2hi, d_a2hi);
    cudaGetSymbolAddress((void**)&a3hi, d_a3hi);
    cudaGetSymbolAddress((void**)&b2hi, d_b2hi);
    cudaGetSymbolAddress((void**)&b2lo, d_b2lo);
    cudaGetSymbolAddress((void**)&b3hi, d_b3hi);
    cudaGetSymbolAddress((void**)&b3lo, d_b3lo);

    static int smem_set = 0;
    if (!smem_set) {
        cudaFuncSetAttribute(mma_gemm, cudaFuncAttributeMaxDynamicSharedMemorySize, 98304);
        smem_set = 1;
    }

    const int TB = 256;
    int nb_nodes = (N_NODES + TB - 1) / TB;
    int nb_edges = (N_EDGES + TB - 1) / TB;
    int nb_node8 = (N_NODES + 7) / 8;

    k_init<<<nb_nodes, TB>>>(ei);
    k_deg_cnt<<<nb_edges, TB>>>(ei, batch);
    k_dis_s1<<<nb_nodes, TB>>>(x);
    k_fill<<<nb_edges, TB>>>(ei, x);

    // weight transposition + bf16 split (independent of graph pipeline)
    k_wsplit<<<(D2 * D1 + TB - 1) / TB, TB>>>(W2, b2hi, b2lo, D1, D2);
    k_wsplit<<<(D3 * D2 + TB - 1) / TB, TB>>>(W3, b3hi, b3lo, D2, D3);

    // layer 1: gather A_hat @ h1 (rank-1), emit bf16 directly
    k_gather1<<<nb_node8, TB>>>(W1, b1);

    // layer 2 GEMM: h2 = relu(a2 @ W2 + b2) stored bf16
    {
        dim3 grid(D2 / 128, (N_NODES + 127) / 128);
        mma_gemm<<<grid, 256, 98304>>>(a2hi, b2hi, b2lo, b2, nullptr, N_NODES, D2, D1, 0);
    }

    // layer 2 aggregation: gather, emit a3 bf16 directly
    k_gather2<<<nb_node8, TB>>>();

    // layer 3 GEMM with fused pooling
    {
        dim3 grid(D3 / 128, (N_NODES + 127) / 128);
        mma_gemm<<<grid, 256, 98304>>>(a3hi, b3hi, b3lo, b3, batch, N_NODES, D3, D2, 1);
    }

    k_final<<<4, 256>>>(Wo, bo, out);
}

// round 11
// speedup vs baseline: 3.4736x; 1.3507x over previous
#include <cuda_runtime.h>
#include <cuda_bf16.h>
#include <cstdint>

#define N_NODES 30000
#define N_EDGES 240000
#define NGRAPH  16
#define D1      256
#define D2      512
#define D3      1024

// ---------------- scratch (no allocations allowed) ----------------
__device__ int   d_idx64;            // 1 if indices are int64, 0 if int32
__device__ int   d_alloc;            // CSR segment allocator
__device__ int   d_cin[N_NODES];     // in-degree (edges only)
__device__ int   d_rowptr[N_NODES];  // segment start per node (arbitrary order)
__device__ int   d_cursor[N_NODES];
__device__ __align__(16) int2 d_epay[N_EDGES];      // (src, norm-bits) CSR payload
__device__ float d_dis[N_NODES];
__device__ float d_s1 [N_NODES];
__device__ __align__(16) float d_pool[NGRAPH * D3];
__device__ float d_cnt[NGRAPH];

// bf16 operand & activation buffers (activations single bf16; weights hi/lo)
__device__ __align__(16) __nv_bfloat16 d_a2hi[N_NODES * D1];
__device__ __align__(16) __nv_bfloat16 d_h2hi[N_NODES * D2];
__device__ __align__(16) __nv_bfloat16 d_a3hi[N_NODES * D2];
__device__ __align__(16) __nv_bfloat16 d_b2hi[D2 * D1];   // [N=512, K=256] K-major
__device__ __align__(16) __nv_bfloat16 d_b2lo[D2 * D1];
__device__ __align__(16) __nv_bfloat16 d_b3hi[D3 * D2];   // [N=1024, K=512] K-major
__device__ __align__(16) __nv_bfloat16 d_b3lo[D3 * D2];

// ---------------- small helpers ----------------
__device__ __forceinline__ int load_idx(const void* p, int i) {
    if (d_idx64) return (int)((const long long*)p)[i];
    return ((const int*)p)[i];
}
__device__ __forceinline__ void red_add_f32(float* p, float v) {
    asm volatile("red.global.add.f32 [%0], %1;" :: "l"(p), "f"(v) : "memory");
}
__device__ __forceinline__ void red_add_v2(float* p, float x, float y) {
    asm volatile("red.global.add.v2.f32 [%0], {%1,%2};"
                 :: "l"(p), "f"(x), "f"(y) : "memory");
}
__device__ __forceinline__ uint32_t smem_u32(const void* p) {
    uint32_t a;
    asm("{ .reg .u64 t; cvta.to.shared.u64 t, %1; cvt.u32.u64 %0, t; }" : "=r"(a) : "l"(p));
    return a;
}
__device__ __forceinline__ void ldm_x4(uint32_t* r, uint32_t addr) {
    asm volatile("ldmatrix.sync.aligned.m8n8.x4.shared.b16 {%0,%1,%2,%3}, [%4];"
                 : "=r"(r[0]), "=r"(r[1]), "=r"(r[2]), "=r"(r[3]) : "r"(addr));
}
__device__ __forceinline__ void cp_async16(uint32_t dst, const void* src, uint32_t srcsize) {
    asm volatile("cp.async.cg.shared.global [%0], [%1], 16, %2;"
                 :: "r"(dst), "l"(src), "r"(srcsize) : "memory");
}
__device__ __forceinline__ void cp_commit(void) {
    asm volatile("cp.async.commit_group;" ::: "memory");
}
__device__ __forceinline__ void mma16816(float* c, const uint32_t* a, uint32_t b0, uint32_t b1) {
    asm volatile(
        "mma.sync.aligned.m16n8k16.row.col.f32.bf16.bf16.f32 "
        "{%0,%1,%2,%3}, {%4,%5,%6,%7}, {%8,%9}, {%0,%1,%2,%3};"
        : "+f"(c[0]), "+f"(c[1]), "+f"(c[2]), "+f"(c[3])
        : "r"(a[0]), "r"(a[1]), "r"(a[2]), "r"(a[3]), "r"(b0), "r"(b1));
}
__device__ __forceinline__ float2 bf2f(uint32_t u) {
    __nv_bfloat162 h = *reinterpret_cast<__nv_bfloat162*>(&u);
    return __bfloat1622float2(h);
}
__device__ __forceinline__ uint32_t f2bf2(float a, float b) {
    __nv_bfloat162 h = __floats2bfloat162_rn(a, b);
    return *reinterpret_cast<uint32_t*>(&h);
}

// ---------------- setup (init + dtype detect fused) ----------------
__global__ void k_init(const void* __restrict__ ei) {
    int i = blockIdx.x * blockDim.x + threadIdx.x;
    if (i < N_NODES) d_cin[i] = 0;
    if (i < NGRAPH) d_cnt[i] = 0.0f;
    if (i < NGRAPH * D3) d_pool[i] = 0.0f;
    if (i == 0) {
        d_alloc = 0;
        const long long* p = (const long long*)ei;
        int ok = 1;
        for (int j = 0; j < 64; j++) {
            long long v = p[j];
            if (v < 0 || v >= N_NODES) { ok = 0; break; }
        }
        d_idx64 = ok;
    }
}

// initialize out with the output bias (k_final_acc red_adds on top)
__global__ void k_out_init(const float* __restrict__ bo, float* __restrict__ out) {
    int i = blockIdx.x * blockDim.x + threadIdx.x;
    if (i < NGRAPH * D3) out[i] = bo[i & (D3 - 1)];
}

// in-degree count + batch count in one pass
__global__ void k_deg_cnt(const void* __restrict__ ei, const void* __restrict__ batch) {
    int i = blockIdx.x * blockDim.x + threadIdx.x;
    if (i < N_EDGES) atomicAdd(&d_cin[load_idx(ei, N_EDGES + i)], 1);
    if (i < N_NODES) atomicAdd(&d_cnt[load_idx(batch, i)], 1.0f);
}

// dis/s1 + CSR segment allocation (warp-aggregated atomic, order-free)
__global__ void k_dis_s1(const float* __restrict__ x) {
    int i = blockIdx.x * blockDim.x + threadIdx.x;
    int lane = threadIdx.x & 31;
    int valid = (i < N_NODES);
    int c = valid ? d_cin[i] : 0;
    if (valid) {
        float r = rsqrtf((float)(c + 1));
        d_dis[i] = r;
        d_s1[i]  = r * r * x[i];    // self-loop term of A_hat @ x
    }
    unsigned mask = 0xffffffffu;
    int incl = c;
#pragma unroll
    for (int off = 1; off < 32; off <<= 1) {
        int v = __shfl_up_sync(mask, incl, off);
        if (lane >= off) incl += v;
    }
    int total = __shfl_sync(mask, incl, 31);
    int base = 0;
    if (lane == 31) base = atomicAdd(&d_alloc, total);
    base = __shfl_sync(mask, base, 31);
    if (valid) {
        int start = base + incl - c;
        d_rowptr[i] = start;
        d_cursor[i] = start;
    }
}

// CSR fill + edge contribution to s1
__global__ void k_fill(const void* __restrict__ ei, const float* __restrict__ x) {
    int e = blockIdx.x * blockDim.x + threadIdx.x;
    if (e >= N_EDGES) return;
    int s = load_idx(ei, e), d = load_idx(ei, N_EDGES + e);
    float nv = d_dis[s] * d_dis[d];
    int pos = atomicAdd(&d_cursor[d], 1);
    d_epay[pos] = make_int2(s, __float_as_int(nv));
    atomicAdd(&d_s1[d], nv * x[s]);
}

// ---------------- layer 1 gather: a2 = bf16(A_hat @ h1), h1 rank-1 on the fly ----------------
__global__ __launch_bounds__(256)
void k_gather1(const float* __restrict__ W1, const float* __restrict__ b1) {
    __shared__ float sW[D1], sB[D1];
    int tid = threadIdx.x;
    if (tid < D1) { sW[tid] = W1[tid]; sB[tid] = b1[tid]; }
    __syncthreads();
    int warp = tid >> 5, lane = tid & 31;
    int node = blockIdx.x * 8 + warp;
    if (node >= N_NODES) return;
    float w[8], b[8];
#pragma unroll
    for (int q = 0; q < 8; q++) { w[q] = sW[lane * 8 + q]; b[q] = sB[lane * 8 + q]; }
    float acc[8];
    float dis = d_dis[node];
    float coef = dis * dis, sv = d_s1[node];
#pragma unroll
    for (int q = 0; q < 8; q++) acc[q] = coef * fmaxf(fmaf(sv, w[q], b[q]), 0.0f);
    int beg = d_rowptr[node], end = beg + d_cin[node];
    for (int e = beg; e < end; e++) {
        int2 pay = d_epay[e];
        float nv = __int_as_float(pay.y);
        float s = d_s1[pay.x];
#pragma unroll
        for (int q = 0; q < 8; q++) acc[q] = fmaf(nv, fmaxf(fmaf(s, w[q], b[q]), 0.0f), acc[q]);
    }
    uint32_t hw[4];
#pragma unroll
    for (int q2 = 0; q2 < 4; q2++) hw[q2] = f2bf2(acc[q2 * 2], acc[q2 * 2 + 1]);
    size_t off = (size_t)node * D1 + lane * 8;
    *(uint4*)(d_a2hi + off) = make_uint4(hw[0], hw[1], hw[2], hw[3]);
}

// ---------------- layer 2 gather: a3 = bf16(A_hat @ h2), h2 stored bf16 ----------------
__device__ __forceinline__ void acc_row16(float* acc, int row, float nv, int lane) {
    size_t off = (size_t)row * D2 + lane * 16;
    uint4 h0 = *(const uint4*)(d_h2hi + off);
    uint4 h1 = *(const uint4*)(d_h2hi + off + 8);
    const uint32_t hu[8] = {h0.x, h0.y, h0.z, h0.w, h1.x, h1.y, h1.z, h1.w};
#pragma unroll
    for (int q = 0; q < 8; q++) {
        float2 hv = bf2f(hu[q]);
        acc[q * 2 + 0] = fmaf(nv, hv.x, acc[q * 2 + 0]);
        acc[q * 2 + 1] = fmaf(nv, hv.y, acc[q * 2 + 1]);
    }
}

__global__ __launch_bounds__(256)
void k_gather2(void) {
    int tid = threadIdx.x;
    int warp = tid >> 5, lane = tid & 31;
    int node = blockIdx.x * 8 + warp;
    if (node >= N_NODES) return;
    float acc[16];
#pragma unroll
    for (int q = 0; q < 16; q++) acc[q] = 0.0f;
    float dis = d_dis[node];
    acc_row16(acc, node, dis * dis, lane);
    int beg = d_rowptr[node], end = beg + d_cin[node];
    for (int e = beg; e < end; e++) {
        int2 pay = d_epay[e];
        acc_row16(acc, pay.x, __int_as_float(pay.y), lane);
    }
    uint32_t hw[8];
#pragma unroll
    for (int q2 = 0; q2 < 8; q2++) hw[q2] = f2bf2(acc[q2 * 2], acc[q2 * 2 + 1]);
    size_t off = (size_t)node * D2 + lane * 16;
    *(uint4*)(d_a3hi + off)     = make_uint4(hw[0], hw[1], hw[2], hw[3]);
    *(uint4*)(d_a3hi + off + 8) = make_uint4(hw[4], hw[5], hw[6], hw[7]);
}

// W [K, N] fp32 row-major -> B [N, K] bf16 hi/lo (transposed, K-major)
__global__ void k_wsplit(const float* __restrict__ W, __nv_bfloat16* __restrict__ bhi,
                         __nv_bfloat16* __restrict__ blo, int K, int N) {
    int idx = blockIdx.x * blockDim.x + threadIdx.x;
    if (idx >= N * K) return;
    int n = idx / K, k = idx - n * K;
    float v = W[(size_t)k * N + n];
    __nv_bfloat16 h = __float2bfloat16(v);
    bhi[idx] = h;
    blo[idx] = __float2bfloat16(v - __bfloat162float(h));
}

// ---------------- bf16-split GEMM: single-pass A, {A,Bhi,Blo} stages ----------------
// D = A @ (Whi + Wlo). Per k-chunk the A tile is loaded once and the a-fragments
// are reused for both the hi and lo products.
// Stage = A(16KB) + Bhi(16KB) + Blo(16KB) = 48KB; 2 stages = 96KB; 2 CTAs/SM.
// mode 0: h2 = relu(D+bias) stored as bf16                  (layer 2)
// mode 1: relu(D+bias) pooled into d_pool[batch]            (layer 3)
__global__ __launch_bounds__(256, 2)
void mma_gemm(const __nv_bfloat16* __restrict__ A,
              const __nv_bfloat16* __restrict__ Bhi, const __nv_bfloat16* __restrict__ Blo,
              const float* __restrict__ bias, const void* __restrict__ batch,
              int M, int Nglob, int K, int mode) {
    extern __shared__ __align__(16) char dynsm[];

    const int tid = threadIdx.x;
    const int wid = tid >> 5, lane = tid & 31;
    const int g = lane >> 2, tig = lane & 3;
    const int warp_m = wid & 3, warp_n = wid >> 2;
    const int row0 = blockIdx.y * 128, col0 = blockIdx.x * 128;
    const int mr = warp_m * 32, nc = warp_n * 64;

    const int t   = lane >> 3;
    const int thi = t >> 1;
    const int rlo = (t & 1) * 8 + (lane & 7);

    const uint32_t smbase = smem_u32(dynsm);
    const uint32_t stA[2]  = { smbase,          smbase + 49152u };
    const uint32_t stBh[2] = { smbase + 16384u, smbase + 65536u };
    const uint32_t stBl[2] = { smbase + 32768u, smbase + 81920u };

    int rA0 = mr + rlo, rA1 = mr + 16 + rlo;
    uint32_t aoff0 = (uint32_t)(rA0 * 128), amask0 = (uint32_t)(rA0 & 7);
    uint32_t aoff1 = (uint32_t)(rA1 * 128), amask1 = (uint32_t)(rA1 & 7);
    uint32_t boff[4], bmask[4];
#pragma unroll
    for (int p = 0; p < 4; p++) {
        int rB = nc + p * 16 + rlo;
        boff[p] = (uint32_t)(rB * 128);
        bmask[p] = (uint32_t)(rB & 7);
    }

    float acc[2][8][4];
#pragma unroll
    for (int mf = 0; mf < 2; mf++)
#pragma unroll
        for (int nf = 0; nf < 8; nf++)
#pragma unroll
            for (int q = 0; q < 4; q++) acc[mf][nf][q] = 0.0f;

    const int nk = K >> 6;

    const int lr = tid >> 1;
    const int lc2 = (tid & 1) * 4;
    auto prefetch = [&](int kc, int s) {
        const int kof = kc << 6;
        int grow = row0 + lr;
        uint32_t asz = (grow < M) ? 16u : 0u;
        const __nv_bfloat16* agp = A   + (size_t)grow * K + kof + lc2 * 8;
        const __nv_bfloat16* bhp = Bhi + (size_t)(col0 + lr) * K + kof + lc2 * 8;
        const __nv_bfloat16* blp = Blo + (size_t)(col0 + lr) * K + kof + lc2 * 8;
        uint32_t arow = (uint32_t)(lr * 128);
#pragma unroll
        for (int j = 0; j < 4; j++) {
            int ch = lc2 + j;
            uint32_t soff = arow + (uint32_t)(((ch ^ (lr & 7)) << 4));
            cp_async16(stA[s] + soff, agp + j * 8, asz);
            cp_async16(stBh[s] + soff, bhp + j * 8, 16u);
            cp_async16(stBl[s] + soff, blp + j * 8, 16u);
        }
        cp_commit();
    };

    prefetch(0, 0);
    for (int kc = 0; kc < nk; kc++) {
        const int s = kc & 1;
        if (kc + 1 < nk) {
            prefetch(kc + 1, s ^ 1);
            asm volatile("cp.async.wait_group 1;" ::: "memory");
        } else {
            asm volatile("cp.async.wait_group 0;" ::: "memory");
        }
        __syncthreads();

#pragma unroll
        for (int ks = 0; ks < 4; ks++) {
            const uint32_t kg = (uint32_t)(2 * ks + thi);
            uint32_t a0[4], a1[4];
            ldm_x4(a0, stA[s] + aoff0 + (((kg ^ amask0) << 4)));
            ldm_x4(a1, stA[s] + aoff1 + (((kg ^ amask1) << 4)));
#pragma unroll
            for (int p = 0; p < 4; p++) {
                uint32_t bh[4], bl[4];
                uint32_t bo_ = boff[p] + (((kg ^ bmask[p]) << 4));
                ldm_x4(bh, stBh[s] + bo_);
                ldm_x4(bl, stBl[s] + bo_);
                mma16816(acc[0][2 * p + 0], a0, bh[0], bh[2]);
                mma16816(acc[0][2 * p + 1], a0, bh[1], bh[3]);
                mma16816(acc[1][2 * p + 0], a1, bh[0], bh[2]);
                mma16816(acc[1][2 * p + 1], a1, bh[1], bh[3]);
                mma16816(acc[0][2 * p + 0], a0, bl[0], bl[2]);
                mma16816(acc[0][2 * p + 1], a0, bl[1], bl[3]);
                mma16816(acc[1][2 * p + 0], a1, bl[0], bl[2]);
                mma16816(acc[1][2 * p + 1], a1, bl[1], bl[3]);
            }
        }
        __syncthreads();
    }

    // ---------------- epilogue ----------------
    if (mode == 0) {
#pragma unroll
        for (int mf = 0; mf < 2; mf++) {
#pragma unroll
            for (int half = 0; half < 2; half++) {
                int row = row0 + mr + mf * 16 + g + half * 8;
                if (row >= M) continue;
#pragma unroll
                for (int nf = 0; nf < 8; nf++) {
                    int col = col0 + nc + nf * 8 + tig * 2;
                    float2 bv = *(const float2*)&bias[col];
                    float v0 = fmaxf(acc[mf][nf][half * 2 + 0] + bv.x, 0.0f);
                    float v1 = fmaxf(acc[mf][nf][half * 2 + 1] + bv.y, 0.0f);
                    *(uint32_t*)(d_h2hi + (size_t)row * D2 + col) = f2bf2(v0, v1);
                }
            }
        }
    } else {
#pragma unroll
        for (int mf = 0; mf < 2; mf++) {
            int ra = row0 + mr + mf * 16 + g;
            int v0ok = (ra < M), v1ok = (ra + 8 < M);
#pragma unroll
            for (int nf = 0; nf < 8; nf++) {
                int col = col0 + nc + nf * 8 + tig * 2;
                float2 bv = *(const float2*)&bias[col];
                acc[mf][nf][0] = v0ok ? fmaxf(acc[mf][nf][0] + bv.x, 0.0f) : 0.0f;
                acc[mf][nf][1] = v0ok ? fmaxf(acc[mf][nf][1] + bv.y, 0.0f) : 0.0f;
                acc[mf][nf][2] = v1ok ? fmaxf(acc[mf][nf][2] + bv.x, 0.0f) : 0.0f;
                acc[mf][nf][3] = v1ok ? fmaxf(acc[mf][nf][3] + bv.y, 0.0f) : 0.0f;
            }
        }
        unsigned mask = 0xffffffffu;
        int rv = row0 + mr + lane;
        int bl = (rv < N_NODES) ? load_idx(batch, rv) : -1;
        int b0 = __shfl_sync(mask, bl, 0);
        bool uni = __all_sync(mask, bl == b0);
        if (uni && b0 >= 0) {
            float s[8][2];
#pragma unroll
            for (int nf = 0; nf < 8; nf++) {
                s[nf][0] = acc[0][nf][0] + acc[0][nf][2] + acc[1][nf][0] + acc[1][nf][2];
                s[nf][1] = acc[0][nf][1] + acc[0][nf][3] + acc[1][nf][1] + acc[1][nf][3];
            }
#pragma unroll
            for (int off = 4; off < 32; off <<= 1)
#pragma unroll
                for (int nf = 0; nf < 8; nf++) {
                    s[nf][0] += __shfl_xor_sync(mask, s[nf][0], off);
                    s[nf][1] += __shfl_xor_sync(mask, s[nf][1], off);
                }
            if (lane < 4) {
#pragma unroll
                for (int nf = 0; nf < 8; nf++) {
                    int col = col0 + nc + nf * 8 + lane * 2;
                    red_add_v2(&d_pool[(size_t)b0 * D3 + col], s[nf][0], s[nf][1]);
                }
            }
        } else {
#pragma unroll
            for (int mf = 0; mf < 2; mf++)
#pragma unroll
                for (int half = 0; half < 2; half++) {
                    int row = row0 + mr + mf * 16 + g + half * 8;
                    if (row >= M) continue;
                    int gb = load_idx(batch, row);
#pragma unroll
                    for (int nf = 0; nf < 8; nf++) {
                        int col = col0 + nc + nf * 8 + tig * 2;
                        red_add_v2(&d_pool[(size_t)gb * D3 + col],
                                   acc[mf][nf][half * 2], acc[mf][nf][half * 2 + 1]);
                    }
                }
        }
    }
}

// ---------------- final linear [16,1024] @ [1024,1024], K-split + atomics ----------------
// grid (4 col-chunks, 8 k-chunks) x 256 threads. Each block: 256 cols x 128 k partial.
// out pre-initialized with bias by k_out_init.
__global__ void k_final_acc(const float* __restrict__ Wo, float* __restrict__ out) {
    __shared__ __align__(16) float sp[128][NGRAPH];
    __shared__ float sinv[NGRAPH];
    int tid = threadIdx.x;
    int c = blockIdx.x * 256 + tid;
    int k0 = blockIdx.y * 128;
    if (tid < NGRAPH) sinv[tid] = 1.0f / fmaxf(d_cnt[tid], 1.0f);
    for (int i = tid; i < 128 * NGRAPH; i += 256) {
        int k = i >> 4, g = i & 15;
        sp[k][g] = d_pool[(size_t)g * D3 + k0 + k];
    }
    __syncthreads();
    float acc[NGRAPH];
#pragma unroll
    for (int g = 0; g < NGRAPH; g++) acc[g] = 0.0f;
#pragma unroll 4
    for (int k = 0; k < 128; k++) {
        float w = Wo[(size_t)(k0 + k) * D3 + c];
        const float4* pr = (const float4*)sp[k];
#pragma unroll
        for (int q = 0; q < 4; q++) {
            float4 pv = pr[q];
            acc[q * 4 + 0] = fmaf(pv.x, w, acc[q * 4 + 0]);
            acc[q * 4 + 1] = fmaf(pv.y, w, acc[q * 4 + 1]);
            acc[q * 4 + 2] = fmaf(pv.z, w, acc[q * 4 + 2]);
            acc[q * 4 + 3] = fmaf(pv.w, w, acc[q * 4 + 3]);
        }
    }
#pragma unroll
    for (int g = 0; g < NGRAPH; g++)
        red_add_f32(&out[(size_t)g * D3 + c], acc[g] * sinv[g]);
}

// ---------------- launcher ----------------
extern "C" void kernel_launch(void* const* d_in, const int* in_sizes, int n_in,
                              void* d_out, int out_size) {
    const float *x, *W1, *b1, *W2, *b2, *W3, *b3, *Wo, *bo;
    const void *ei, *batch;
    if (in_sizes[0] == N_NODES) {           // dict order
        x     = (const float*)d_in[0];
        ei    = d_in[1];
        batch = d_in[2];
        W1 = (const float*)d_in[3];  b1 = (const float*)d_in[4];
        W2 = (const float*)d_in[5];  b2 = (const float*)d_in[6];
        W3 = (const float*)d_in[7];  b3 = (const float*)d_in[8];
        Wo = (const float*)d_in[9];  bo = (const float*)d_in[10];
    } else {                                // alphabetical order
        W1 = (const float*)d_in[0];
        W2 = (const float*)d_in[1];
        W3 = (const float*)d_in[2];
        Wo = (const float*)d_in[3];
        b1 = (const float*)d_in[4];
        b2 = (const float*)d_in[5];
        b3 = (const float*)d_in[6];
        batch = d_in[7];
        bo = (const float*)d_in[8];
        ei = d_in[9];
        x  = (const float*)d_in[10];
    }
    float* out = (float*)d_out;

    __nv_bfloat16 *a2hi, *a3hi, *b2hi, *b2lo, *b3hi, *b3lo;
    cudaGetSymbolAddress((void**)&a2hi, d_a2hi);
    cudaGetSymbolAddress((void**)&a3hi, d_a3hi);
    cudaGetSymbolAddress((void**)&b2hi, d_b2hi);
    cudaGetSymbolAddress((void**)&b2lo, d_b2lo);
    cudaGetSymbolAddress((void**)&b3hi, d_b3hi);
    cudaGetSymbolAddress((void**)&b3lo, d_b3lo);

    static int smem_set = 0;
    if (!smem_set) {
        cudaFuncSetAttribute(mma_gemm, cudaFuncAttributeMaxDynamicSharedMemorySize, 98304);
        smem_set = 1;
    }

    const int TB = 256;
    int nb_nodes = (N_NODES + TB - 1) / TB;
    int nb_edges = (N_EDGES + TB - 1) / TB;
    int nb_node8 = (N_NODES + 7) / 8;

    k_init<<<nb_nodes, TB>>>(ei);
    k_out_init<<<(NGRAPH * D3 + TB - 1) / TB, TB>>>(bo, out);
    k_deg_cnt<<<nb_edges, TB>>>(ei, batch);
    k_dis_s1<<<nb_nodes, TB>>>(x);
    k_fill<<<nb_edges, TB>>>(ei, x);

    // weight transposition + bf16 split (independent of graph pipeline)
    k_wsplit<<<(D2 * D1 + TB - 1) / TB, TB>>>(W2, b2hi, b2lo, D1, D2);
    k_wsplit<<<(D3 * D2 + TB - 1) / TB, TB>>>(W3, b3hi, b3lo, D2, D3);

    // layer 1: gather A_hat @ h1 (rank-1), emit bf16 directly
    k_gather1<<<nb_node8, TB>>>(W1, b1);

    // layer 2 GEMM: h2 = relu(a2 @ W2 + b2) stored bf16
    {
        dim3 grid(D2 / 128, (N_NODES + 127) / 128);
        mma_gemm<<<grid, 256, 98304>>>(a2hi, b2hi, b2lo, b2, nullptr, N_NODES, D2, D1, 0);
    }

    // layer 2 aggregation: gather, emit a3 bf16 directly
    k_gather2<<<nb_node8, TB>>>();

    // layer 3 GEMM with fused pooling
    {
        dim3 grid(D3 / 128, (N_NODES + 127) / 128);
        mma_gemm<<<grid, 256, 98304>>>(a3hi, b3hi, b3lo, b3, batch, N_NODES, D3, D2, 1);
    }

    // final linear, K-split across 32 blocks
    {
        dim3 grid(4, 8);
        k_final_acc<<<grid, 256>>>(Wo, out);
    }
}

// round 12
// speedup vs baseline: 4.7287x; 1.3613x over previous
#include <cuda_runtime.h>
#include <cuda_fp16.h>
#include <cstdint>

#define N_NODES 30000
#define N_EDGES 240000
#define NGRAPH  16
#define D1      256
#define D2      512
#define D3      1024

// ---------------- scratch (no allocations allowed) ----------------
__device__ int   d_idx64;            // 1 if indices are int64, 0 if int32
__device__ int   d_alloc;            // CSR segment allocator
__device__ int   d_cin[N_NODES];     // in-degree (edges only)
__device__ int   d_rowptr[N_NODES];  // segment start per node (arbitrary order)
__device__ int   d_cursor[N_NODES];
__device__ __align__(16) int2 d_epay[N_EDGES];      // (src, norm-bits) CSR payload
__device__ float d_dis[N_NODES];
__device__ float d_s1 [N_NODES];
__device__ __align__(16) float d_pool[NGRAPH * D3];
__device__ float d_cnt[NGRAPH];

// fp16 operand & activation buffers
__device__ __align__(16) __half d_a2h[N_NODES * D1];
__device__ __align__(16) __half d_h2h[N_NODES * D2];
__device__ __align__(16) __half d_a3h[N_NODES * D2];
__device__ __align__(16) __half d_b2h[D2 * D1];   // [N=512, K=256] K-major
__device__ __align__(16) __half d_b3h[D3 * D2];   // [N=1024, K=512] K-major

// ---------------- small helpers ----------------
__device__ __forceinline__ int load_idx(const void* p, int i) {
    if (d_idx64) return (int)((const long long*)p)[i];
    return ((const int*)p)[i];
}
__device__ __forceinline__ void red_add_f32(float* p, float v) {
    asm volatile("red.global.add.f32 [%0], %1;" :: "l"(p), "f"(v) : "memory");
}
__device__ __forceinline__ void red_add_v2(float* p, float x, float y) {
    asm volatile("red.global.add.v2.f32 [%0], {%1,%2};"
                 :: "l"(p), "f"(x), "f"(y) : "memory");
}
__device__ __forceinline__ uint32_t smem_u32(const void* p) {
    uint32_t a;
    asm("{ .reg .u64 t; cvta.to.shared.u64 t, %1; cvt.u32.u64 %0, t; }" : "=r"(a) : "l"(p));
    return a;
}
__device__ __forceinline__ void ldm_x4(uint32_t* r, uint32_t addr) {
    asm volatile("ldmatrix.sync.aligned.m8n8.x4.shared.b16 {%0,%1,%2,%3}, [%4];"
                 : "=r"(r[0]), "=r"(r[1]), "=r"(r[2]), "=r"(r[3]) : "r"(addr));
}
__device__ __forceinline__ void cp_async16(uint32_t dst, const void* src, uint32_t srcsize) {
    asm volatile("cp.async.cg.shared.global [%0], [%1], 16, %2;"
                 :: "r"(dst), "l"(src), "r"(srcsize) : "memory");
}
__device__ __forceinline__ void cp_commit(void) {
    asm volatile("cp.async.commit_group;" ::: "memory");
}
__device__ __forceinline__ void mma16816(float* c, const uint32_t* a, uint32_t b0, uint32_t b1) {
    asm volatile(
        "mma.sync.aligned.m16n8k16.row.col.f32.f16.f16.f32 "
        "{%0,%1,%2,%3}, {%4,%5,%6,%7}, {%8,%9}, {%0,%1,%2,%3};"
        : "+f"(c[0]), "+f"(c[1]), "+f"(c[2]), "+f"(c[3])
        : "r"(a[0]), "r"(a[1]), "r"(a[2]), "r"(a[3]), "r"(b0), "r"(b1));
}
__device__ __forceinline__ float2 h2f2(uint32_t u) {
    __half2 h = *reinterpret_cast<__half2*>(&u);
    return __half22float2(h);
}
__device__ __forceinline__ uint32_t f2h2(float a, float b) {
    __half2 h = __floats2half2_rn(a, b);
    return *reinterpret_cast<uint32_t*>(&h);
}

// ---------------- setup (init + dtype detect fused) ----------------
__global__ void k_init(const void* __restrict__ ei) {
    int i = blockIdx.x * blockDim.x + threadIdx.x;
    if (i < N_NODES) d_cin[i] = 0;
    if (i < NGRAPH) d_cnt[i] = 0.0f;
    if (i < NGRAPH * D3) d_pool[i] = 0.0f;
    if (i == 0) {
        d_alloc = 0;
        const long long* p = (const long long*)ei;
        int ok = 1;
        for (int j = 0; j < 64; j++) {
            long long v = p[j];
            if (v < 0 || v >= N_NODES) { ok = 0; break; }
        }
        d_idx64 = ok;
    }
}

// initialize out with the output bias (k_final_acc red_adds on top)
__global__ void k_out_init(const float* __restrict__ bo, float* __restrict__ out) {
    int i = blockIdx.x * blockDim.x + threadIdx.x;
    if (i < NGRAPH * D3) out[i] = bo[i & (D3 - 1)];
}

// in-degree count + batch count in one pass
__global__ void k_deg_cnt(const void* __restrict__ ei, const void* __restrict__ batch) {
    int i = blockIdx.x * blockDim.x + threadIdx.x;
    if (i < N_EDGES) atomicAdd(&d_cin[load_idx(ei, N_EDGES + i)], 1);
    if (i < N_NODES) atomicAdd(&d_cnt[load_idx(batch, i)], 1.0f);
}

// dis/s1 + CSR segment allocation (warp-aggregated atomic, order-free)
__global__ void k_dis_s1(const float* __restrict__ x) {
    int i = blockIdx.x * blockDim.x + threadIdx.x;
    int lane = threadIdx.x & 31;
    int valid = (i < N_NODES);
    int c = valid ? d_cin[i] : 0;
    if (valid) {
        float r = rsqrtf((float)(c + 1));
        d_dis[i] = r;
        d_s1[i]  = r * r * x[i];    // self-loop term of A_hat @ x
    }
    unsigned mask = 0xffffffffu;
    int incl = c;
#pragma unroll
    for (int off = 1; off < 32; off <<= 1) {
        int v = __shfl_up_sync(mask, incl, off);
        if (lane >= off) incl += v;
    }
    int total = __shfl_sync(mask, incl, 31);
    int base = 0;
    if (lane == 31) base = atomicAdd(&d_alloc, total);
    base = __shfl_sync(mask, base, 31);
    if (valid) {
        int start = base + incl - c;
        d_rowptr[i] = start;
        d_cursor[i] = start;
    }
}

// CSR fill + edge contribution to s1
__global__ void k_fill(const void* __restrict__ ei, const float* __restrict__ x) {
    int e = blockIdx.x * blockDim.x + threadIdx.x;
    if (e >= N_EDGES) return;
    int s = load_idx(ei, e), d = load_idx(ei, N_EDGES + e);
    float nv = d_dis[s] * d_dis[d];
    int pos = atomicAdd(&d_cursor[d], 1);
    d_epay[pos] = make_int2(s, __float_as_int(nv));
    atomicAdd(&d_s1[d], nv * x[s]);
}

// ---------------- layer 1 gather: a2 = fp16(A_hat @ h1), h1 rank-1 on the fly ----------------
__global__ __launch_bounds__(256)
void k_gather1(const float* __restrict__ W1, const float* __restrict__ b1) {
    __shared__ float sW[D1], sB[D1];
    int tid = threadIdx.x;
    if (tid < D1) { sW[tid] = W1[tid]; sB[tid] = b1[tid]; }
    __syncthreads();
    int warp = tid >> 5, lane = tid & 31;
    int node = blockIdx.x * 8 + warp;
    if (node >= N_NODES) return;
    float w[8], b[8];
#pragma unroll
    for (int q = 0; q < 8; q++) { w[q] = sW[lane * 8 + q]; b[q] = sB[lane * 8 + q]; }
    float acc[8];
    float dis = d_dis[node];
    float coef = dis * dis, sv = d_s1[node];
#pragma unroll
    for (int q = 0; q < 8; q++) acc[q] = coef * fmaxf(fmaf(sv, w[q], b[q]), 0.0f);
    int beg = d_rowptr[node], end = beg + d_cin[node];
    for (int e = beg; e < end; e++) {
        int2 pay = d_epay[e];
        float nv = __int_as_float(pay.y);
        float s = d_s1[pay.x];
#pragma unroll
        for (int q = 0; q < 8; q++) acc[q] = fmaf(nv, fmaxf(fmaf(s, w[q], b[q]), 0.0f), acc[q]);
    }
    uint32_t hw[4];
#pragma unroll
    for (int q2 = 0; q2 < 4; q2++) hw[q2] = f2h2(acc[q2 * 2], acc[q2 * 2 + 1]);
    size_t off = (size_t)node * D1 + lane * 8;
    *(uint4*)(d_a2h + off) = make_uint4(hw[0], hw[1], hw[2], hw[3]);
}

// ---------------- layer 2 gather: a3 = fp16(A_hat @ h2), h2 stored fp16 ----------------
__device__ __forceinline__ void acc_row16(float* acc, int row, float nv, int lane) {
    size_t off = (size_t)row * D2 + lane * 16;
    uint4 h0 = *(const uint4*)(d_h2h + off);
    uint4 h1 = *(const uint4*)(d_h2h + off + 8);
    const uint32_t hu[8] = {h0.x, h0.y, h0.z, h0.w, h1.x, h1.y, h1.z, h1.w};
#pragma unroll
    for (int q = 0; q < 8; q++) {
        float2 hv = h2f2(hu[q]);
        acc[q * 2 + 0] = fmaf(nv, hv.x, acc[q * 2 + 0]);
        acc[q * 2 + 1] = fmaf(nv, hv.y, acc[q * 2 + 1]);
    }
}

__global__ __launch_bounds__(256)
void k_gather2(void) {
    int tid = threadIdx.x;
    int warp = tid >> 5, lane = tid & 31;
    int node = blockIdx.x * 8 + warp;
    if (node >= N_NODES) return;
    float acc[16];
#pragma unroll
    for (int q = 0; q < 16; q++) acc[q] = 0.0f;
    float dis = d_dis[node];
    acc_row16(acc, node, dis * dis, lane);
    int beg = d_rowptr[node], end = beg + d_cin[node];
    for (int e = beg; e < end; e++) {
        int2 pay = d_epay[e];
        acc_row16(acc, pay.x, __int_as_float(pay.y), lane);
    }
    uint32_t hw[8];
#pragma unroll
    for (int q2 = 0; q2 < 8; q2++) hw[q2] = f2h2(acc[q2 * 2], acc[q2 * 2 + 1]);
    size_t off = (size_t)node * D2 + lane * 16;
    *(uint4*)(d_a3h + off)     = make_uint4(hw[0], hw[1], hw[2], hw[3]);
    *(uint4*)(d_a3h + off + 8) = make_uint4(hw[4], hw[5], hw[6], hw[7]);
}

// W [K, N] fp32 row-major -> B [N, K] fp16 (transposed, K-major)
__global__ void k_wconv(const float* __restrict__ W, __half* __restrict__ bh, int K, int N) {
    int idx = blockIdx.x * blockDim.x + threadIdx.x;
    if (idx >= N * K) return;
    int n = idx / K, k = idx - n * K;
    bh[idx] = __float2half_rn(W[(size_t)k * N + n]);
}

// ---------------- fp16 GEMM: ldmatrix + 3-stage cp.async pipeline ----------------
// Stage = A(16KB) + B(16KB) = 32KB; 3 stages = 96KB; 2 CTAs/SM.
// mode 0: h2 = relu(D+bias) stored as fp16                  (layer 2)
// mode 1: relu(D+bias) pooled into d_pool[batch]            (layer 3)
__global__ __launch_bounds__(256, 2)
void mma_gemm(const __half* __restrict__ A, const __half* __restrict__ B,
              const float* __restrict__ bias, const void* __restrict__ batch,
              int M, int Nglob, int K, int mode) {
    extern __shared__ __align__(16) char dynsm[];

    const int tid = threadIdx.x;
    const int wid = tid >> 5, lane = tid & 31;
    const int g = lane >> 2, tig = lane & 3;
    const int warp_m = wid & 3, warp_n = wid >> 2;
    const int row0 = blockIdx.y * 128, col0 = blockIdx.x * 128;
    const int mr = warp_m * 32, nc = warp_n * 64;

    const int t   = lane >> 3;
    const int thi = t >> 1;
    const int rlo = (t & 1) * 8 + (lane & 7);

    const uint32_t smbase = smem_u32(dynsm);
    const uint32_t stA[3] = { smbase, smbase + 32768u, smbase + 65536u };
    const uint32_t stB[3] = { smbase + 16384u, smbase + 49152u, smbase + 81920u };

    int rA0 = mr + rlo, rA1 = mr + 16 + rlo;
    uint32_t aoff0 = (uint32_t)(rA0 * 128), amask0 = (uint32_t)(rA0 & 7);
    uint32_t aoff1 = (uint32_t)(rA1 * 128), amask1 = (uint32_t)(rA1 & 7);
    uint32_t boff[4], bmask[4];
#pragma unroll
    for (int p = 0; p < 4; p++) {
        int rB = nc + p * 16 + rlo;
        boff[p] = (uint32_t)(rB * 128);
        bmask[p] = (uint32_t)(rB & 7);
    }

    float acc[2][8][4];
#pragma unroll
    for (int mf = 0; mf < 2; mf++)
#pragma unroll
        for (int nf = 0; nf < 8; nf++)
#pragma unroll
            for (int q = 0; q < 4; q++) acc[mf][nf][q] = 0.0f;

    const int nk = K >> 6;

    const int lr = tid >> 1;
    const int lc2 = (tid & 1) * 4;
    auto prefetch = [&](int kc, int s) {
        const int kof = kc << 6;
        int grow = row0 + lr;
        uint32_t asz = (grow < M) ? 16u : 0u;
        const __half* agp = A + (size_t)grow * K + kof + lc2 * 8;
        const __half* bgp = B + (size_t)(col0 + lr) * K + kof + lc2 * 8;
        uint32_t arow = (uint32_t)(lr * 128);
#pragma unroll
        for (int j = 0; j < 4; j++) {
            int ch = lc2 + j;
            uint32_t soff = arow + (uint32_t)(((ch ^ (lr & 7)) << 4));
            cp_async16(stA[s] + soff, agp + j * 8, asz);
            cp_async16(stB[s] + soff, bgp + j * 8, 16u);
        }
        cp_commit();
    };

    prefetch(0, 0);
    if (nk > 1) prefetch(1, 1);
    int sidx = 0;
    for (int kc = 0; kc < nk; kc++) {
        if (kc + 2 < nk) {
            prefetch(kc + 2, (sidx + 2) % 3);
            asm volatile("cp.async.wait_group 2;" ::: "memory");
        } else {
            asm volatile("cp.async.wait_group 0;" ::: "memory");
        }
        __syncthreads();
        const int s = sidx;

#pragma unroll
        for (int ks = 0; ks < 4; ks++) {
            const uint32_t kg = (uint32_t)(2 * ks + thi);
            uint32_t a0[4], a1[4];
            ldm_x4(a0, stA[s] + aoff0 + (((kg ^ amask0) << 4)));
            ldm_x4(a1, stA[s] + aoff1 + (((kg ^ amask1) << 4)));
#pragma unroll
            for (int p = 0; p < 4; p++) {
                uint32_t bf[4];
                ldm_x4(bf, stB[s] + boff[p] + (((kg ^ bmask[p]) << 4)));
                mma16816(acc[0][2 * p + 0], a0, bf[0], bf[2]);
                mma16816(acc[0][2 * p + 1], a0, bf[1], bf[3]);
                mma16816(acc[1][2 * p + 0], a1, bf[0], bf[2]);
                mma16816(acc[1][2 * p + 1], a1, bf[1], bf[3]);
            }
        }
        __syncthreads();
        sidx = (sidx + 1) % 3;
    }

    // ---------------- epilogue ----------------
    if (mode == 0) {
#pragma unroll
        for (int mf = 0; mf < 2; mf++) {
#pragma unroll
            for (int half = 0; half < 2; half++) {
                int row = row0 + mr + mf * 16 + g + half * 8;
                if (row >= M) continue;
#pragma unroll
                for (int nf = 0; nf < 8; nf++) {
                    int col = col0 + nc + nf * 8 + tig * 2;
                    float2 bv = *(const float2*)&bias[col];
                    float v0 = fmaxf(acc[mf][nf][half * 2 + 0] + bv.x, 0.0f);
                    float v1 = fmaxf(acc[mf][nf][half * 2 + 1] + bv.y, 0.0f);
                    *(uint32_t*)(d_h2h + (size_t)row * D2 + col) = f2h2(v0, v1);
                }
            }
        }
    } else {
#pragma unroll
        for (int mf = 0; mf < 2; mf++) {
            int ra = row0 + mr + mf * 16 + g;
            int v0ok = (ra < M), v1ok = (ra + 8 < M);
#pragma unroll
            for (int nf = 0; nf < 8; nf++) {
                int col = col0 + nc + nf * 8 + tig * 2;
                float2 bv = *(const float2*)&bias[col];
                acc[mf][nf][0] = v0ok ? fmaxf(acc[mf][nf][0] + bv.x, 0.0f) : 0.0f;
                acc[mf][nf][1] = v0ok ? fmaxf(acc[mf][nf][1] + bv.y, 0.0f) : 0.0f;
                acc[mf][nf][2] = v1ok ? fmaxf(acc[mf][nf][2] + bv.x, 0.0f) : 0.0f;
                acc[mf][nf][3] = v1ok ? fmaxf(acc[mf][nf][3] + bv.y, 0.0f) : 0.0f;
            }
        }
        unsigned mask = 0xffffffffu;
        int rv = row0 + mr + lane;
        int bl = (rv < N_NODES) ? load_idx(batch, rv) : -1;
        int b0 = __shfl_sync(mask, bl, 0);
        bool uni = __all_sync(mask, bl == b0);
        if (uni && b0 >= 0) {
            float s[8][2];
#pragma unroll
            for (int nf = 0; nf < 8; nf++) {
                s[nf][0] = acc[0][nf][0] + acc[0][nf][2] + acc[1][nf][0] + acc[1][nf][2];
                s[nf][1] = acc[0][nf][1] + acc[0][nf][3] + acc[1][nf][1] + acc[1][nf][3];
            }
#pragma unroll
            for (int off = 4; off < 32; off <<= 1)
#pragma unroll
                for (int nf = 0; nf < 8; nf++) {
                    s[nf][0] += __shfl_xor_sync(mask, s[nf][0], off);
                    s[nf][1] += __shfl_xor_sync(mask, s[nf][1], off);
                }
            if (lane < 4) {
#pragma unroll
                for (int nf = 0; nf < 8; nf++) {
                    int col = col0 + nc + nf * 8 + lane * 2;
                    red_add_v2(&d_pool[(size_t)b0 * D3 + col], s[nf][0], s[nf][1]);
                }
            }
        } else {
#pragma unroll
            for (int mf = 0; mf < 2; mf++)
#pragma unroll
                for (int half = 0; half < 2; half++) {
                    int row = row0 + mr + mf * 16 + g + half * 8;
                    if (row >= M) continue;
                    int gb = load_idx(batch, row);
#pragma unroll
                    for (int nf = 0; nf < 8; nf++) {
                        int col = col0 + nc + nf * 8 + tig * 2;
                        red_add_v2(&d_pool[(size_t)gb * D3 + col],
                                   acc[mf][nf][half * 2], acc[mf][nf][half * 2 + 1]);
                    }
                }
        }
    }
}

// ---------------- final linear [16,1024] @ [1024,1024], K-split + atomics ----------------
__global__ void k_final_acc(const float* __restrict__ Wo, float* __restrict__ out) {
    __shared__ __align__(16) float sp[128][NGRAPH];
    __shared__ float sinv[NGRAPH];
    int tid = threadIdx.x;
    int c = blockIdx.x * 256 + tid;
    int k0 = blockIdx.y * 128;
    if (tid < NGRAPH) sinv[tid] = 1.0f / fmaxf(d_cnt[tid], 1.0f);
    for (int i = tid; i < 128 * NGRAPH; i += 256) {
        int k = i >> 4, g = i & 15;
        sp[k][g] = d_pool[(size_t)g * D3 + k0 + k];
    }
    __syncthreads();
    float acc[NGRAPH];
#pragma unroll
    for (int g = 0; g < NGRAPH; g++) acc[g] = 0.0f;
#pragma unroll 4
    for (int k = 0; k < 128; k++) {
        float w = Wo[(size_t)(k0 + k) * D3 + c];
        const float4* pr = (const float4*)sp[k];
#pragma unroll
        for (int q = 0; q < 4; q++) {
            float4 pv = pr[q];
            acc[q * 4 + 0] = fmaf(pv.x, w, acc[q * 4 + 0]);
            acc[q * 4 + 1] = fmaf(pv.y, w, acc[q * 4 + 1]);
            acc[q * 4 + 2] = fmaf(pv.z, w, acc[q * 4 + 2]);
            acc[q * 4 + 3] = fmaf(pv.w, w, acc[q * 4 + 3]);
        }
    }
#pragma unroll
    for (int g = 0; g < NGRAPH; g++)
        red_add_f32(&out[(size_t)g * D3 + c], acc[g] * sinv[g]);
}

// ---------------- launcher ----------------
extern "C" void kernel_launch(void* const* d_in, const int* in_sizes, int n_in,
                              void* d_out, int out_size) {
    const float *x, *W1, *b1, *W2, *b2, *W3, *b3, *Wo, *bo;
    const void *ei, *batch;
    if (in_sizes[0] == N_NODES) {           // dict order
        x     = (const float*)d_in[0];
        ei    = d_in[1];
        batch = d_in[2];
        W1 = (const float*)d_in[3];  b1 = (const float*)d_in[4];
        W2 = (const float*)d_in[5];  b2 = (const float*)d_in[6];
        W3 = (const float*)d_in[7];  b3 = (const float*)d_in[8];
        Wo = (const float*)d_in[9];  bo = (const float*)d_in[10];
    } else {                                // alphabetical order
        W1 = (const float*)d_in[0];
        W2 = (const float*)d_in[1];
        W3 = (const float*)d_in[2];
        Wo = (const float*)d_in[3];
        b1 = (const float*)d_in[4];
        b2 = (const float*)d_in[5];
        b3 = (const float*)d_in[6];
        batch = d_in[7];
        bo = (const float*)d_in[8];
        ei = d_in[9];
        x  = (const float*)d_in[10];
    }
    float* out = (float*)d_out;

    __half *a2h, *a3h, *b2h, *b3h;
    cudaGetSymbolAddress((void**)&a2h, d_a2h);
    cudaGetSymbolAddress((void**)&a3h, d_a3h);
    cudaGetSymbolAddress((void**)&b2h, d_b2h);
    cudaGetSymbolAddress((void**)&b3h, d_b3h);

    static int smem_set = 0;
    if (!smem_set) {
        cudaFuncSetAttribute(mma_gemm, cudaFuncAttributeMaxDynamicSharedMemorySize, 98304);
        smem_set = 1;
    }

    const int TB = 256;
    int nb_nodes = (N_NODES + TB - 1) / TB;
    int nb_edges = (N_EDGES + TB - 1) / TB;
    int nb_node8 = (N_NODES + 7) / 8;

    k_init<<<nb_nodes, TB>>>(ei);
    k_out_init<<<(NGRAPH * D3 + TB - 1) / TB, TB>>>(bo, out);
    k_deg_cnt<<<nb_edges, TB>>>(ei, batch);
    k_dis_s1<<<nb_nodes, TB>>>(x);
    k_fill<<<nb_edges, TB>>>(ei, x);

    // weight transposition + fp16 conversion
    k_wconv<<<(D2 * D1 + TB - 1) / TB, TB>>>(W2, b2h, D1, D2);
    k_wconv<<<(D3 * D2 + TB - 1) / TB, TB>>>(W3, b3h, D2, D3);

    // layer 1: gather A_hat @ h1 (rank-1), emit fp16 directly
    k_gather1<<<nb_node8, TB>>>(W1, b1);

    // layer 2 GEMM: h2 = relu(a2 @ W2 + b2) stored fp16
    {
        dim3 grid(D2 / 128, (N_NODES + 127) / 128);
        mma_gemm<<<grid, 256, 98304>>>(a2h, b2h, b2, nullptr, N_NODES, D2, D1, 0);
    }

    // layer 2 aggregation: gather, emit a3 fp16 directly
    k_gather2<<<nb_node8, TB>>>();

    // layer 3 GEMM with fused pooling
    {
        dim3 grid(D3 / 128, (N_NODES + 127) / 128);
        mma_gemm<<<grid, 256, 98304>>>(a3h, b3h, b3, batch, N_NODES, D3, D2, 1);
    }

    // final linear, K-split across 32 blocks
    {
        dim3 grid(4, 8);
        k_final_acc<<<grid, 256>>>(Wo, out);
    }
}

// round 13
// speedup vs baseline: 4.7774x; 1.0103x over previous
#include <cuda_runtime.h>
#include <cuda_fp16.h>
#include <cstdint>

#define N_NODES 30000
#define N_EDGES 240000
#define NGRAPH  16
#define D1      256
#define D2      512
#define D3      1024

// ---------------- scratch (no allocations allowed) ----------------
__device__ int   d_idx64;            // 1 if indices are int64, 0 if int32
__device__ int   d_alloc;            // CSR segment allocator
__device__ int   d_cin[N_NODES];     // in-degree (edges only)
__device__ int   d_rowptr[N_NODES];  // segment start per node (arbitrary order)
__device__ int   d_cursor[N_NODES];
__device__ __align__(16) int2 d_epay[N_EDGES];      // (src, norm-bits) CSR payload
__device__ float d_dis[N_NODES];
__device__ float d_s1 [N_NODES];
__device__ __align__(16) float d_pool[NGRAPH * D3];
__device__ float d_cnt[NGRAPH];

// fp16 operand & activation buffers
__device__ __align__(16) __half d_a2h[N_NODES * D1];
__device__ __align__(16) __half d_h2h[N_NODES * D2];
__device__ __align__(16) __half d_a3h[N_NODES * D2];
__device__ __align__(16) __half d_b2h[D2 * D1];   // [N=512, K=256] K-major
__device__ __align__(16) __half d_b3h[D3 * D2];   // [N=1024, K=512] K-major

// ---------------- small helpers ----------------
__device__ __forceinline__ int load_idx(const void* p, int i) {
    if (d_idx64) return (int)((const long long*)p)[i];
    return ((const int*)p)[i];
}
__device__ __forceinline__ void red_add_f32(float* p, float v) {
    asm volatile("red.global.add.f32 [%0], %1;" :: "l"(p), "f"(v) : "memory");
}
__device__ __forceinline__ void red_add_v2(float* p, float x, float y) {
    asm volatile("red.global.add.v2.f32 [%0], {%1,%2};"
                 :: "l"(p), "f"(x), "f"(y) : "memory");
}
__device__ __forceinline__ uint32_t smem_u32(const void* p) {
    uint32_t a;
    asm("{ .reg .u64 t; cvta.to.shared.u64 t, %1; cvt.u32.u64 %0, t; }" : "=r"(a) : "l"(p));
    return a;
}
__device__ __forceinline__ void ldm_x4(uint32_t* r, uint32_t addr) {
    asm volatile("ldmatrix.sync.aligned.m8n8.x4.shared.b16 {%0,%1,%2,%3}, [%4];"
                 : "=r"(r[0]), "=r"(r[1]), "=r"(r[2]), "=r"(r[3]) : "r"(addr));
}
__device__ __forceinline__ void cp_async16(uint32_t dst, const void* src, uint32_t srcsize) {
    asm volatile("cp.async.cg.shared.global [%0], [%1], 16, %2;"
                 :: "r"(dst), "l"(src), "r"(srcsize) : "memory");
}
__device__ __forceinline__ void cp_commit(void) {
    asm volatile("cp.async.commit_group;" ::: "memory");
}
__device__ __forceinline__ void mma16816(float* c, const uint32_t* a, uint32_t b0, uint32_t b1) {
    asm volatile(
        "mma.sync.aligned.m16n8k16.row.col.f32.f16.f16.f32 "
        "{%0,%1,%2,%3}, {%4,%5,%6,%7}, {%8,%9}, {%0,%1,%2,%3};"
        : "+f"(c[0]), "+f"(c[1]), "+f"(c[2]), "+f"(c[3])
        : "r"(a[0]), "r"(a[1]), "r"(a[2]), "r"(a[3]), "r"(b0), "r"(b1));
}
__device__ __forceinline__ float2 h2f2(uint32_t u) {
    __half2 h = *reinterpret_cast<__half2*>(&u);
    return __half22float2(h);
}
__device__ __forceinline__ uint32_t f2h2(float a, float b) {
    __half2 h = __floats2half2_rn(a, b);
    return *reinterpret_cast<uint32_t*>(&h);
}

// ---------------- setup (init + dtype detect + out-bias init fused) ----------------
__global__ void k_init(const void* __restrict__ ei, const float* __restrict__ bo,
                       float* __restrict__ out) {
    int i = blockIdx.x * blockDim.x + threadIdx.x;
    if (i < N_NODES) d_cin[i] = 0;
    if (i < NGRAPH) d_cnt[i] = 0.0f;
    if (i < NGRAPH * D3) {
        d_pool[i] = 0.0f;
        out[i] = bo[i & (D3 - 1)];
    }
    if (i == 0) {
        d_alloc = 0;
        const long long* p = (const long long*)ei;
        int ok = 1;
        for (int j = 0; j < 64; j++) {
            long long v = p[j];
            if (v < 0 || v >= N_NODES) { ok = 0; break; }
        }
        d_idx64 = ok;
    }
}

// in-degree count + batch count in one pass
__global__ void k_deg_cnt(const void* __restrict__ ei, const void* __restrict__ batch) {
    int i = blockIdx.x * blockDim.x + threadIdx.x;
    if (i < N_EDGES) atomicAdd(&d_cin[load_idx(ei, N_EDGES + i)], 1);
    if (i < N_NODES) atomicAdd(&d_cnt[load_idx(batch, i)], 1.0f);
}

// dis/s1 + CSR segment allocation (warp-aggregated atomic, order-free)
__global__ void k_dis_s1(const float* __restrict__ x) {
    int i = blockIdx.x * blockDim.x + threadIdx.x;
    int lane = threadIdx.x & 31;
    int valid = (i < N_NODES);
    int c = valid ? d_cin[i] : 0;
    if (valid) {
        float r = rsqrtf((float)(c + 1));
        d_dis[i] = r;
        d_s1[i]  = r * r * x[i];    // self-loop term of A_hat @ x
    }
    unsigned mask = 0xffffffffu;
    int incl = c;
#pragma unroll
    for (int off = 1; off < 32; off <<= 1) {
        int v = __shfl_up_sync(mask, incl, off);
        if (lane >= off) incl += v;
    }
    int total = __shfl_sync(mask, incl, 31);
    int base = 0;
    if (lane == 31) base = atomicAdd(&d_alloc, total);
    base = __shfl_sync(mask, base, 31);
    if (valid) {
        int start = base + incl - c;
        d_rowptr[i] = start;
        d_cursor[i] = start;
    }
}

// CSR fill + edge contribution to s1
__global__ void k_fill(const void* __restrict__ ei, const float* __restrict__ x) {
    int e = blockIdx.x * blockDim.x + threadIdx.x;
    if (e >= N_EDGES) return;
    int s = load_idx(ei, e), d = load_idx(ei, N_EDGES + e);
    float nv = d_dis[s] * d_dis[d];
    int pos = atomicAdd(&d_cursor[d], 1);
    d_epay[pos] = make_int2(s, __float_as_int(nv));
    atomicAdd(&d_s1[d], nv * x[s]);
}

// ---------------- layer 1 gather: a2 = fp16(A_hat @ h1), h1 rank-1 on the fly ----------------
__global__ __launch_bounds__(256)
void k_gather1(const float* __restrict__ W1, const float* __restrict__ b1) {
    __shared__ float sW[D1], sB[D1];
    int tid = threadIdx.x;
    if (tid < D1) { sW[tid] = W1[tid]; sB[tid] = b1[tid]; }
    __syncthreads();
    int warp = tid >> 5, lane = tid & 31;
    int node = blockIdx.x * 8 + warp;
    if (node >= N_NODES) return;
    float w[8], b[8];
#pragma unroll
    for (int q = 0; q < 8; q++) { w[q] = sW[lane * 8 + q]; b[q] = sB[lane * 8 + q]; }
    float acc[8];
    float dis = d_dis[node];
    float coef = dis * dis, sv = d_s1[node];
#pragma unroll
    for (int q = 0; q < 8; q++) acc[q] = coef * fmaxf(fmaf(sv, w[q], b[q]), 0.0f);
    int beg = d_rowptr[node], end = beg + d_cin[node];
    for (int e = beg; e < end; e++) {
        int2 pay = d_epay[e];
        float nv = __int_as_float(pay.y);
        float s = d_s1[pay.x];
#pragma unroll
        for (int q = 0; q < 8; q++) acc[q] = fmaf(nv, fmaxf(fmaf(s, w[q], b[q]), 0.0f), acc[q]);
    }
    uint32_t hw[4];
#pragma unroll
    for (int q2 = 0; q2 < 4; q2++) hw[q2] = f2h2(acc[q2 * 2], acc[q2 * 2 + 1]);
    size_t off = (size_t)node * D1 + lane * 8;
    *(uint4*)(d_a2h + off) = make_uint4(hw[0], hw[1], hw[2], hw[3]);
}

// ---------------- layer 2 gather: a3 = fp16(A_hat @ h2), h2 stored fp16 ----------------
__device__ __forceinline__ void acc_row16(float* acc, int row, float nv, int lane) {
    size_t off = (size_t)row * D2 + lane * 16;
    uint4 h0 = *(const uint4*)(d_h2h + off);
    uint4 h1 = *(const uint4*)(d_h2h + off + 8);
    const uint32_t hu[8] = {h0.x, h0.y, h0.z, h0.w, h1.x, h1.y, h1.z, h1.w};
#pragma unroll
    for (int q = 0; q < 8; q++) {
        float2 hv = h2f2(hu[q]);
        acc[q * 2 + 0] = fmaf(nv, hv.x, acc[q * 2 + 0]);
        acc[q * 2 + 1] = fmaf(nv, hv.y, acc[q * 2 + 1]);
    }
}

__global__ __launch_bounds__(256)
void k_gather2(void) {
    int tid = threadIdx.x;
    int warp = tid >> 5, lane = tid & 31;
    int node = blockIdx.x * 8 + warp;
    if (node >= N_NODES) return;
    float acc[16];
#pragma unroll
    for (int q = 0; q < 16; q++) acc[q] = 0.0f;
    float dis = d_dis[node];
    acc_row16(acc, node, dis * dis, lane);
    int beg = d_rowptr[node], end = beg + d_cin[node];
    for (int e = beg; e < end; e++) {
        int2 pay = d_epay[e];
        acc_row16(acc, pay.x, __int_as_float(pay.y), lane);
    }
    uint32_t hw[8];
#pragma unroll
    for (int q2 = 0; q2 < 8; q2++) hw[q2] = f2h2(acc[q2 * 2], acc[q2 * 2 + 1]);
    size_t off = (size_t)node * D2 + lane * 16;
    *(uint4*)(d_a3h + off)     = make_uint4(hw[0], hw[1], hw[2], hw[3]);
    *(uint4*)(d_a3h + off + 8) = make_uint4(hw[4], hw[5], hw[6], hw[7]);
}

// W [K, N] fp32 row-major -> B [N, K] fp16 (transposed, K-major), tiled/coalesced
__global__ __launch_bounds__(256)
void k_wconv(const float* __restrict__ W, __half* __restrict__ bh, int K, int N) {
    __shared__ float tile[32][33];
    int n0 = blockIdx.x * 32, k0 = blockIdx.y * 32;
    int tx = threadIdx.x & 31, ty = threadIdx.x >> 5;   // 32 x 8
#pragma unroll
    for (int j = 0; j < 32; j += 8)
        tile[ty + j][tx] = W[(size_t)(k0 + ty + j) * N + n0 + tx];
    __syncthreads();
#pragma unroll
    for (int j = 0; j < 32; j += 8)
        bh[(size_t)(n0 + ty + j) * K + k0 + tx] = __float2half_rn(tile[tx][ty + j]);
}

// ---------------- fp16 GEMM: ldmatrix + 3-stage cp.async pipeline, 1 sync/chunk ----------------
// mode 0: h2 = relu(D+bias) stored as fp16                  (layer 2)
// mode 1: relu(D+bias) pooled into d_pool[batch]            (layer 3)
__global__ __launch_bounds__(256, 2)
void mma_gemm(const __half* __restrict__ A, const __half* __restrict__ B,
              const float* __restrict__ bias, const void* __restrict__ batch,
              int M, int Nglob, int K, int mode) {
    extern __shared__ __align__(16) char dynsm[];

    const int tid = threadIdx.x;
    const int wid = tid >> 5, lane = tid & 31;
    const int g = lane >> 2, tig = lane & 3;
    const int warp_m = wid & 3, warp_n = wid >> 2;
    const int row0 = blockIdx.y * 128, col0 = blockIdx.x * 128;
    const int mr = warp_m * 32, nc = warp_n * 64;

    const int t   = lane >> 3;
    const int thi = t >> 1;
    const int rlo = (t & 1) * 8 + (lane & 7);

    const uint32_t smbase = smem_u32(dynsm);
    const uint32_t stA[3] = { smbase, smbase + 32768u, smbase + 65536u };
    const uint32_t stB[3] = { smbase + 16384u, smbase + 49152u, smbase + 81920u };

    int rA0 = mr + rlo, rA1 = mr + 16 + rlo;
    uint32_t aoff0 = (uint32_t)(rA0 * 128), amask0 = (uint32_t)(rA0 & 7);
    uint32_t aoff1 = (uint32_t)(rA1 * 128), amask1 = (uint32_t)(rA1 & 7);
    uint32_t boff[4], bmask[4];
#pragma unroll
    for (int p = 0; p < 4; p++) {
        int rB = nc + p * 16 + rlo;
        boff[p] = (uint32_t)(rB * 128);
        bmask[p] = (uint32_t)(rB & 7);
    }

    float acc[2][8][4];
#pragma unroll
    for (int mf = 0; mf < 2; mf++)
#pragma unroll
        for (int nf = 0; nf < 8; nf++)
#pragma unroll
            for (int q = 0; q < 4; q++) acc[mf][nf][q] = 0.0f;

    const int nk = K >> 6;

    const int lr = tid >> 1;
    const int lc2 = (tid & 1) * 4;
    auto prefetch = [&](int kc, int s) {
        const int kof = kc << 6;
        int grow = row0 + lr;
        uint32_t asz = (grow < M) ? 16u : 0u;
        const __half* agp = A + (size_t)grow * K + kof + lc2 * 8;
        const __half* bgp = B + (size_t)(col0 + lr) * K + kof + lc2 * 8;
        uint32_t arow = (uint32_t)(lr * 128);
#pragma unroll
        for (int j = 0; j < 4; j++) {
            int ch = lc2 + j;
            uint32_t soff = arow + (uint32_t)(((ch ^ (lr & 7)) << 4));
            cp_async16(stA[s] + soff, agp + j * 8, asz);
            cp_async16(stB[s] + soff, bgp + j * 8, 16u);
        }
        cp_commit();
    };

    prefetch(0, 0);
    if (nk > 1) prefetch(1, 1);
    int sidx = 0;
    for (int kc = 0; kc < nk; kc++) {
        if (kc == nk - 1) {
            asm volatile("cp.async.wait_group 0;" ::: "memory");
        } else {
            asm volatile("cp.async.wait_group 1;" ::: "memory");
        }
        __syncthreads();
        // safe: all warps finished reading stage (kc+2)%3 at iter kc-1 before this barrier
        if (kc + 2 < nk) prefetch(kc + 2, (sidx + 2) % 3);
        const int s = sidx;

#pragma unroll
        for (int ks = 0; ks < 4; ks++) {
            const uint32_t kg = (uint32_t)(2 * ks + thi);
            uint32_t a0[4], a1[4];
            ldm_x4(a0, stA[s] + aoff0 + (((kg ^ amask0) << 4)));
            ldm_x4(a1, stA[s] + aoff1 + (((kg ^ amask1) << 4)));
#pragma unroll
            for (int p = 0; p < 4; p++) {
                uint32_t bf[4];
                ldm_x4(bf, stB[s] + boff[p] + (((kg ^ bmask[p]) << 4)));
                mma16816(acc[0][2 * p + 0], a0, bf[0], bf[2]);
                mma16816(acc[0][2 * p + 1], a0, bf[1], bf[3]);
                mma16816(acc[1][2 * p + 0], a1, bf[0], bf[2]);
                mma16816(acc[1][2 * p + 1], a1, bf[1], bf[3]);
            }
        }
        sidx = (sidx + 1) % 3;
    }

    // ---------------- epilogue ----------------
    if (mode == 0) {
#pragma unroll
        for (int mf = 0; mf < 2; mf++) {
#pragma unroll
            for (int half = 0; half < 2; half++) {
                int row = row0 + mr + mf * 16 + g + half * 8;
                if (row >= M) continue;
#pragma unroll
                for (int nf = 0; nf < 8; nf++) {
                    int col = col0 + nc + nf * 8 + tig * 2;
                    float2 bv = *(const float2*)&bias[col];
                    float v0 = fmaxf(acc[mf][nf][half * 2 + 0] + bv.x, 0.0f);
                    float v1 = fmaxf(acc[mf][nf][half * 2 + 1] + bv.y, 0.0f);
                    *(uint32_t*)(d_h2h + (size_t)row * D2 + col) = f2h2(v0, v1);
                }
            }
        }
    } else {
#pragma unroll
        for (int mf = 0; mf < 2; mf++) {
            int ra = row0 + mr + mf * 16 + g;
            int v0ok = (ra < M), v1ok = (ra + 8 < M);
#pragma unroll
            for (int nf = 0; nf < 8; nf++) {
                int col = col0 + nc + nf * 8 + tig * 2;
                float2 bv = *(const float2*)&bias[col];
                acc[mf][nf][0] = v0ok ? fmaxf(acc[mf][nf][0] + bv.x, 0.0f) : 0.0f;
                acc[mf][nf][1] = v0ok ? fmaxf(acc[mf][nf][1] + bv.y, 0.0f) : 0.0f;
                acc[mf][nf][2] = v1ok ? fmaxf(acc[mf][nf][2] + bv.x, 0.0f) : 0.0f;
                acc[mf][nf][3] = v1ok ? fmaxf(acc[mf][nf][3] + bv.y, 0.0f) : 0.0f;
            }
        }
        unsigned mask = 0xffffffffu;
        int rv = row0 + mr + lane;
        int bl = (rv < N_NODES) ? load_idx(batch, rv) : -1;
        int b0 = __shfl_sync(mask, bl, 0);
        bool uni = __all_sync(mask, bl == b0);
        if (uni && b0 >= 0) {
            float s[8][2];
#pragma unroll
            for (int nf = 0; nf < 8; nf++) {
                s[nf][0] = acc[0][nf][0] + acc[0][nf][2] + acc[1][nf][0] + acc[1][nf][2];
                s[nf][1] = acc[0][nf][1] + acc[0][nf][3] + acc[1][nf][1] + acc[1][nf][3];
            }
#pragma unroll
            for (int off = 4; off < 32; off <<= 1)
#pragma unroll
                for (int nf = 0; nf < 8; nf++) {
                    s[nf][0] += __shfl_xor_sync(mask, s[nf][0], off);
                    s[nf][1] += __shfl_xor_sync(mask, s[nf][1], off);
                }
            if (lane < 4) {
#pragma unroll
                for (int nf = 0; nf < 8; nf++) {
                    int col = col0 + nc + nf * 8 + lane * 2;
                    red_add_v2(&d_pool[(size_t)b0 * D3 + col], s[nf][0], s[nf][1]);
                }
            }
        } else {
#pragma unroll
            for (int mf = 0; mf < 2; mf++)
#pragma unroll
                for (int half = 0; half < 2; half++) {
                    int row = row0 + mr + mf * 16 + g + half * 8;
                    if (row >= M) continue;
                    int gb = load_idx(batch, row);
#pragma unroll
                    for (int nf = 0; nf < 8; nf++) {
                        int col = col0 + nc + nf * 8 + tig * 2;
                        red_add_v2(&d_pool[(size_t)gb * D3 + col],
                                   acc[mf][nf][half * 2], acc[mf][nf][half * 2 + 1]);
                    }
                }
        }
    }
}

// ---------------- final linear [16,1024] @ [1024,1024], K-split + atomics ----------------
__global__ void k_final_acc(const float* __restrict__ Wo, float* __restrict__ out) {
    __shared__ __align__(16) float sp[128][NGRAPH];
    __shared__ float sinv[NGRAPH];
    int tid = threadIdx.x;
    int c = blockIdx.x * 256 + tid;
    int k0 = blockIdx.y * 128;
    if (tid < NGRAPH) sinv[tid] = 1.0f / fmaxf(d_cnt[tid], 1.0f);
    for (int i = tid; i < 128 * NGRAPH; i += 256) {
        int k = i >> 4, g = i & 15;
        sp[k][g] = d_pool[(size_t)g * D3 + k0 + k];
    }
    __syncthreads();
    float acc[NGRAPH];
#pragma unroll
    for (int g = 0; g < NGRAPH; g++) acc[g] = 0.0f;
#pragma unroll 4
    for (int k = 0; k < 128; k++) {
        float w = Wo[(size_t)(k0 + k) * D3 + c];
        const float4* pr = (const float4*)sp[k];
#pragma unroll
        for (int q = 0; q < 4; q++) {
            float4 pv = pr[q];
            acc[q * 4 + 0] = fmaf(pv.x, w, acc[q * 4 + 0]);
            acc[q * 4 + 1] = fmaf(pv.y, w, acc[q * 4 + 1]);
            acc[q * 4 + 2] = fmaf(pv.z, w, acc[q * 4 + 2]);
            acc[q * 4 + 3] = fmaf(pv.w, w, acc[q * 4 + 3]);
        }
    }
#pragma unroll
    for (int g = 0; g < NGRAPH; g++)
        red_add_f32(&out[(size_t)g * D3 + c], acc[g] * sinv[g]);
}

// ---------------- launcher ----------------
extern "C" void kernel_launch(void* const* d_in, const int* in_sizes, int n_in,
                              void* d_out, int out_size) {
    const float *x, *W1, *b1, *W2, *b2, *W3, *b3, *Wo, *bo;
    const void *ei, *batch;
    if (in_sizes[0] == N_NODES) {           // dict order
        x     = (const float*)d_in[0];
        ei    = d_in[1];
        batch = d_in[2];
        W1 = (const float*)d_in[3];  b1 = (const float*)d_in[4];
        W2 = (const float*)d_in[5];  b2 = (const float*)d_in[6];
        W3 = (const float*)d_in[7];  b3 = (const float*)d_in[8];
        Wo = (const float*)d_in[9];  bo = (const float*)d_in[10];
    } else {                                // alphabetical order
        W1 = (const float*)d_in[0];
        W2 = (const float*)d_in[1];
        W3 = (const float*)d_in[2];
        Wo = (const float*)d_in[3];
        b1 = (const float*)d_in[4];
        b2 = (const float*)d_in[5];
        b3 = (const float*)d_in[6];
        batch = d_in[7];
        bo = (const float*)d_in[8];
        ei = d_in[9];
        x  = (const float*)d_in[10];
    }
    float* out = (float*)d_out;

    __half *a2h, *a3h, *b2h, *b3h;
    cudaGetSymbolAddress((void**)&a2h, d_a2h);
    cudaGetSymbolAddress((void**)&a3h, d_a3h);
    cudaGetSymbolAddress((void**)&b2h, d_b2h);
    cudaGetSymbolAddress((void**)&b3h, d_b3h);

    static int init_done = 0;
    static cudaStream_t s_side;
    static cudaEvent_t ev_fork, ev_join;
    if (!init_done) {
        cudaFuncSetAttribute(mma_gemm, cudaFuncAttributeMaxDynamicSharedMemorySize, 98304);
        cudaStreamCreateWithFlags(&s_side, cudaStreamNonBlocking);
        cudaEventCreateWithFlags(&ev_fork, cudaEventDisableTiming);
        cudaEventCreateWithFlags(&ev_join, cudaEventDisableTiming);
        init_done = 1;
    }

    const int TB = 256;
    int nb_nodes = (N_NODES + TB - 1) / TB;
    int nb_edges = (N_EDGES + TB - 1) / TB;
    int nb_node8 = (N_NODES + 7) / 8;

    // fork: weight conversions on the side stream, overlapped with graph setup
    cudaEventRecord(ev_fork, 0);
    cudaStreamWaitEvent(s_side, ev_fork, 0);
    {
        dim3 g2w(D2 / 32, D1 / 32);
        k_wconv<<<g2w, 256, 0, s_side>>>(W2, b2h, D1, D2);
        dim3 g3w(D3 / 32, D2 / 32);
        k_wconv<<<g3w, 256, 0, s_side>>>(W3, b3h, D2, D3);
    }
    cudaEventRecord(ev_join, s_side);

    // main chain
    k_init<<<nb_nodes, TB>>>(ei, bo, out);
    k_deg_cnt<<<nb_edges, TB>>>(ei, batch);
    k_dis_s1<<<nb_nodes, TB>>>(x);
    k_fill<<<nb_edges, TB>>>(ei, x);
    k_gather1<<<nb_node8, TB>>>(W1, b1);

    // join weight conversions before first GEMM
    cudaStreamWaitEvent(0, ev_join, 0);

    // layer 2 GEMM: h2 = relu(a2 @ W2 + b2) stored fp16
    {
        dim3 grid(D2 / 128, (N_NODES + 127) / 128);
        mma_gemm<<<grid, 256, 98304>>>(a2h, b2h, b2, nullptr, N_NODES, D2, D1, 0);
    }

    // layer 2 aggregation: gather, emit a3 fp16 directly
    k_gather2<<<nb_node8, TB>>>();

    // layer 3 GEMM with fused pooling
    {
        dim3 grid(D3 / 128, (N_NODES + 127) / 128);
        mma_gemm<<<grid, 256, 98304>>>(a3h, b3h, b3, batch, N_NODES, D3, D2, 1);
    }

    // final linear, K-split across 32 blocks
    {
        dim3 grid(4, 8);
        k_final_acc<<<grid, 256>>>(Wo, out);
    }
}

// round 14
// speedup vs baseline: 5.3721x; 1.1245x over previous
#include <cuda_runtime.h>
#include <cuda_fp16.h>
#include <cstdint>

#define N_NODES 30000
#define N_EDGES 240000
#define NGRAPH  16
#define D1      256
#define D2      512
#define D3      1024

// ---------------- scratch (no allocations allowed) ----------------
__device__ int   d_idx64;            // 1 if indices are int64, 0 if int32
__device__ int   d_alloc;            // CSR segment allocator
__device__ int   d_cin[N_NODES];     // in-degree (edges only)
__device__ int   d_rowptr[N_NODES];  // segment start per node (arbitrary order)
__device__ int   d_cursor[N_NODES];
__device__ __align__(16) int2 d_epay[N_EDGES];      // (src, norm-bits) CSR payload
__device__ float d_dis[N_NODES];
__device__ float d_s1 [N_NODES];
__device__ __align__(16) float d_pool[NGRAPH * D3];
__device__ float d_cnt[NGRAPH];

// fp16 operand & activation buffers
__device__ __align__(16) __half d_a2h[N_NODES * D1];
__device__ __align__(16) __half d_h2h[N_NODES * D2];
__device__ __align__(16) __half d_a3h[N_NODES * D2];
__device__ __align__(16) __half d_b2h[D2 * D1];   // [N=512, K=256] K-major
__device__ __align__(16) __half d_b3h[D3 * D2];   // [N=1024, K=512] K-major

// ---------------- small helpers ----------------
__device__ __forceinline__ int load_idx(const void* p, int i) {
    if (d_idx64) return (int)((const long long*)p)[i];
    return ((const int*)p)[i];
}
__device__ __forceinline__ void red_add_f32(float* p, float v) {
    asm volatile("red.global.add.f32 [%0], %1;" :: "l"(p), "f"(v) : "memory");
}
__device__ __forceinline__ void red_add_v2(float* p, float x, float y) {
    asm volatile("red.global.add.v2.f32 [%0], {%1,%2};"
                 :: "l"(p), "f"(x), "f"(y) : "memory");
}
__device__ __forceinline__ uint32_t smem_u32(const void* p) {
    uint32_t a;
    asm("{ .reg .u64 t; cvta.to.shared.u64 t, %1; cvt.u32.u64 %0, t; }" : "=r"(a) : "l"(p));
    return a;
}
__device__ __forceinline__ void ldm_x4(uint32_t* r, uint32_t addr) {
    asm volatile("ldmatrix.sync.aligned.m8n8.x4.shared.b16 {%0,%1,%2,%3}, [%4];"
                 : "=r"(r[0]), "=r"(r[1]), "=r"(r[2]), "=r"(r[3]) : "r"(addr));
}
__device__ __forceinline__ void cp_async16(uint32_t dst, const void* src, uint32_t srcsize) {
    asm volatile("cp.async.cg.shared.global [%0], [%1], 16, %2;"
                 :: "r"(dst), "l"(src), "r"(srcsize) : "memory");
}
__device__ __forceinline__ void cp_commit(void) {
    asm volatile("cp.async.commit_group;" ::: "memory");
}
__device__ __forceinline__ void mma16816(float* c, const uint32_t* a, uint32_t b0, uint32_t b1) {
    asm volatile(
        "mma.sync.aligned.m16n8k16.row.col.f32.f16.f16.f32 "
        "{%0,%1,%2,%3}, {%4,%5,%6,%7}, {%8,%9}, {%0,%1,%2,%3};"
        : "+f"(c[0]), "+f"(c[1]), "+f"(c[2]), "+f"(c[3])
        : "r"(a[0]), "r"(a[1]), "r"(a[2]), "r"(a[3]), "r"(b0), "r"(b1));
}
__device__ __forceinline__ float2 h2f2(uint32_t u) {
    __half2 h = *reinterpret_cast<__half2*>(&u);
    return __half22float2(h);
}
__device__ __forceinline__ uint32_t f2h2(float a, float b) {
    __half2 h = __floats2half2_rn(a, b);
    return *reinterpret_cast<uint32_t*>(&h);
}

// ---------------- setup (init + dtype detect + out-bias init fused) ----------------
__global__ void k_init(const void* __restrict__ ei, const float* __restrict__ bo,
                       float* __restrict__ out) {
    int i = blockIdx.x * blockDim.x + threadIdx.x;
    if (i < N_NODES) d_cin[i] = 0;
    if (i < NGRAPH) d_cnt[i] = 0.0f;
    if (i < NGRAPH * D3) {
        d_pool[i] = 0.0f;
        out[i] = bo[i & (D3 - 1)];
    }
    if (i == 0) {
        d_alloc = 0;
        const long long* p = (const long long*)ei;
        int ok = 1;
        for (int j = 0; j < 64; j++) {
            long long v = p[j];
            if (v < 0 || v >= N_NODES) { ok = 0; break; }
        }
        d_idx64 = ok;
    }
}

// in-degree + batch count, 4 items/thread (MLP=4), warp-aggregated cnt atomics
__global__ void k_deg_cnt(const void* __restrict__ ei, const void* __restrict__ batch) {
    int base = (blockIdx.x * blockDim.x + threadIdx.x) * 4;

    // edges: 4 independent loads then 4 atomics (MLP=4 hides DRAM latency)
    int dst[4];
#pragma unroll
    for (int j = 0; j < 4; j++) {
        int e = base + j;
        dst[j] = (e < N_EDGES) ? load_idx(ei, N_EDGES + e) : -1;
    }
#pragma unroll
    for (int j = 0; j < 4; j++)
        if (dst[j] >= 0) atomicAdd(&d_cin[dst[j]], 1);

    // batch counts: local run aggregation over 4 sorted ids, then warp match
    int g0 = -1, c0 = 0, g1 = -1, c1 = 0;
#pragma unroll
    for (int j = 0; j < 4; j++) {
        int i = base + j;
        if (i >= N_NODES) break;
        int g = load_idx(batch, i);
        if (g == g0) c0++;
        else if (g == g1) c1++;
        else if (g0 < 0) { g0 = g; c0 = 1; }
        else if (g1 < 0) { g1 = g; c1 = 1; }
        else atomicAdd(&d_cnt[g], 1.0f);    // >2 distinct in a 4-run: rare
    }
    unsigned am = __activemask();
    if (g0 >= 0) {
        // warp-level: sum c0 across lanes with equal g0, leader issues one atomic
        unsigned m = __match_any_sync(am, g0);
        float sum = (float)c0;
        // reduce within matched group via shfl over the group mask
        for (int off = 16; off; off >>= 1) {
            float v = __shfl_down_sync(am, sum, off);
            int src = (threadIdx.x & 31) + off;
            if ((m >> src) & 1) sum += v;
        }
        if ((threadIdx.x & 31) == (__ffs(m) - 1)) atomicAdd(&d_cnt[g0], sum);
    }
    if (g1 >= 0) atomicAdd(&d_cnt[g1], (float)c1);   // run boundary: at most 1/thread
}

// dis/s1 + CSR segment allocation (warp-aggregated atomic, order-free)
__global__ void k_dis_s1(const float* __restrict__ x) {
    int i = blockIdx.x * blockDim.x + threadIdx.x;
    int lane = threadIdx.x & 31;
    int valid = (i < N_NODES);
    int c = valid ? d_cin[i] : 0;
    if (valid) {
        float r = rsqrtf((float)(c + 1));
        d_dis[i] = r;
        d_s1[i]  = r * r * x[i];    // self-loop term of A_hat @ x
    }
    unsigned mask = 0xffffffffu;
    int incl = c;
#pragma unroll
    for (int off = 1; off < 32; off <<= 1) {
        int v = __shfl_up_sync(mask, incl, off);
        if (lane >= off) incl += v;
    }
    int total = __shfl_sync(mask, incl, 31);
    int base = 0;
    if (lane == 31) base = atomicAdd(&d_alloc, total);
    base = __shfl_sync(mask, base, 31);
    if (valid) {
        int start = base + incl - c;
        d_rowptr[i] = start;
        d_cursor[i] = start;
    }
}

// CSR fill + edge contribution to s1
__global__ void k_fill(const void* __restrict__ ei, const float* __restrict__ x) {
    int e = blockIdx.x * blockDim.x + threadIdx.x;
    if (e >= N_EDGES) return;
    int s = load_idx(ei, e), d = load_idx(ei, N_EDGES + e);
    float nv = d_dis[s] * d_dis[d];
    int pos = atomicAdd(&d_cursor[d], 1);
    d_epay[pos] = make_int2(s, __float_as_int(nv));
    atomicAdd(&d_s1[d], nv * x[s]);
}

// ---------------- layer 1 gather: a2 = fp16(A_hat @ h1), h1 rank-1 on the fly ----------------
__global__ __launch_bounds__(256)
void k_gather1(const float* __restrict__ W1, const float* __restrict__ b1) {
    __shared__ float sW[D1], sB[D1];
    int tid = threadIdx.x;
    if (tid < D1) { sW[tid] = W1[tid]; sB[tid] = b1[tid]; }
    __syncthreads();
    int warp = tid >> 5, lane = tid & 31;
    int node = blockIdx.x * 8 + warp;
    if (node >= N_NODES) return;
    float w[8], b[8];
#pragma unroll
    for (int q = 0; q < 8; q++) { w[q] = sW[lane * 8 + q]; b[q] = sB[lane * 8 + q]; }
    float acc[8];
    float dis = d_dis[node];
    float coef = dis * dis, sv = d_s1[node];
#pragma unroll
    for (int q = 0; q < 8; q++) acc[q] = coef * fmaxf(fmaf(sv, w[q], b[q]), 0.0f);
    int beg = d_rowptr[node], end = beg + d_cin[node];
    for (int e = beg; e < end; e++) {
        int2 pay = d_epay[e];
        float nv = __int_as_float(pay.y);
        float s = d_s1[pay.x];
#pragma unroll
        for (int q = 0; q < 8; q++) acc[q] = fmaf(nv, fmaxf(fmaf(s, w[q], b[q]), 0.0f), acc[q]);
    }
    uint32_t hw[4];
#pragma unroll
    for (int q2 = 0; q2 < 4; q2++) hw[q2] = f2h2(acc[q2 * 2], acc[q2 * 2 + 1]);
    size_t off = (size_t)node * D1 + lane * 8;
    *(uint4*)(d_a2h + off) = make_uint4(hw[0], hw[1], hw[2], hw[3]);
}

// ---------------- layer 2 gather: a3 = fp16(A_hat @ h2), h2 stored fp16 ----------------
__device__ __forceinline__ void acc_row16(float* acc, int row, float nv, int lane) {
    size_t off = (size_t)row * D2 + lane * 16;
    uint4 h0 = *(const uint4*)(d_h2h + off);
    uint4 h1 = *(const uint4*)(d_h2h + off + 8);
    const uint32_t hu[8] = {h0.x, h0.y, h0.z, h0.w, h1.x, h1.y, h1.z, h1.w};
#pragma unroll
    for (int q = 0; q < 8; q++) {
        float2 hv = h2f2(hu[q]);
        acc[q * 2 + 0] = fmaf(nv, hv.x, acc[q * 2 + 0]);
        acc[q * 2 + 1] = fmaf(nv, hv.y, acc[q * 2 + 1]);
    }
}

__global__ __launch_bounds__(256)
void k_gather2(void) {
    int tid = threadIdx.x;
    int warp = tid >> 5, lane = tid & 31;
    int node = blockIdx.x * 8 + warp;
    if (node >= N_NODES) return;
    float acc[16];
#pragma unroll
    for (int q = 0; q < 16; q++) acc[q] = 0.0f;
    float dis = d_dis[node];
    acc_row16(acc, node, dis * dis, lane);
    int beg = d_rowptr[node], end = beg + d_cin[node];
    for (int e = beg; e < end; e++) {
        int2 pay = d_epay[e];
        acc_row16(acc, pay.x, __int_as_float(pay.y), lane);
    }
    uint32_t hw[8];
#pragma unroll
    for (int q2 = 0; q2 < 8; q2++) hw[q2] = f2h2(acc[q2 * 2], acc[q2 * 2 + 1]);
    size_t off = (size_t)node * D2 + lane * 16;
    *(uint4*)(d_a3h + off)     = make_uint4(hw[0], hw[1], hw[2], hw[3]);
    *(uint4*)(d_a3h + off + 8) = make_uint4(hw[4], hw[5], hw[6], hw[7]);
}

// W [K, N] fp32 row-major -> B [N, K] fp16 (transposed, K-major), tiled/coalesced
__global__ __launch_bounds__(256)
void k_wconv(const float* __restrict__ W, __half* __restrict__ bh, int K, int N) {
    __shared__ float tile[32][33];
    int n0 = blockIdx.x * 32, k0 = blockIdx.y * 32;
    int tx = threadIdx.x & 31, ty = threadIdx.x >> 5;   // 32 x 8
#pragma unroll
    for (int j = 0; j < 32; j += 8)
        tile[ty + j][tx] = W[(size_t)(k0 + ty + j) * N + n0 + tx];
    __syncthreads();
#pragma unroll
    for (int j = 0; j < 32; j += 8)
        bh[(size_t)(n0 + ty + j) * K + k0 + tx] = __float2half_rn(tile[tx][ty + j]);
}

// ---------------- fp16 GEMM: ldmatrix + 3-stage cp.async pipeline, 1 sync/chunk ----------------
// mode 0: h2 = relu(D+bias) stored as fp16                  (layer 2)
// mode 1: relu(D+bias) pooled into d_pool[batch]            (layer 3)
__global__ __launch_bounds__(256, 2)
void mma_gemm(const __half* __restrict__ A, const __half* __restrict__ B,
              const float* __restrict__ bias, const void* __restrict__ batch,
              int M, int Nglob, int K, int mode) {
    extern __shared__ __align__(16) char dynsm[];

    const int tid = threadIdx.x;
    const int wid = tid >> 5, lane = tid & 31;
    const int g = lane >> 2, tig = lane & 3;
    const int warp_m = wid & 3, warp_n = wid >> 2;
    const int row0 = blockIdx.y * 128, col0 = blockIdx.x * 128;
    const int mr = warp_m * 32, nc = warp_n * 64;

    const int t   = lane >> 3;
    const int thi = t >> 1;
    const int rlo = (t & 1) * 8 + (lane & 7);

    const uint32_t smbase = smem_u32(dynsm);
    const uint32_t stA[3] = { smbase, smbase + 32768u, smbase + 65536u };
    const uint32_t stB[3] = { smbase + 16384u, smbase + 49152u, smbase + 81920u };

    int rA0 = mr + rlo, rA1 = mr + 16 + rlo;
    uint32_t aoff0 = (uint32_t)(rA0 * 128), amask0 = (uint32_t)(rA0 & 7);
    uint32_t aoff1 = (uint32_t)(rA1 * 128), amask1 = (uint32_t)(rA1 & 7);
    uint32_t boff[4], bmask[4];
#pragma unroll
    for (int p = 0; p < 4; p++) {
        int rB = nc + p * 16 + rlo;
        boff[p] = (uint32_t)(rB * 128);
        bmask[p] = (uint32_t)(rB & 7);
    }

    float acc[2][8][4];
#pragma unroll
    for (int mf = 0; mf < 2; mf++)
#pragma unroll
        for (int nf = 0; nf < 8; nf++)
#pragma unroll
            for (int q = 0; q < 4; q++) acc[mf][nf][q] = 0.0f;

    const int nk = K >> 6;

    const int lr = tid >> 1;
    const int lc2 = (tid & 1) * 4;
    auto prefetch = [&](int kc, int s) {
        const int kof = kc << 6;
        int grow = row0 + lr;
        uint32_t asz = (grow < M) ? 16u : 0u;
        const __half* agp = A + (size_t)grow * K + kof + lc2 * 8;
        const __half* bgp = B + (size_t)(col0 + lr) * K + kof + lc2 * 8;
        uint32_t arow = (uint32_t)(lr * 128);
#pragma unroll
        for (int j = 0; j < 4; j++) {
            int ch = lc2 + j;
            uint32_t soff = arow + (uint32_t)(((ch ^ (lr & 7)) << 4));
            cp_async16(stA[s] + soff, agp + j * 8, asz);
            cp_async16(stB[s] + soff, bgp + j * 8, 16u);
        }
        cp_commit();
    };

    prefetch(0, 0);
    if (nk > 1) prefetch(1, 1);
    int sidx = 0;
    for (int kc = 0; kc < nk; kc++) {
        if (kc == nk - 1) {
            asm volatile("cp.async.wait_group 0;" ::: "memory");
        } else {
            asm volatile("cp.async.wait_group 1;" ::: "memory");
        }
        __syncthreads();
        if (kc + 2 < nk) prefetch(kc + 2, (sidx + 2) % 3);
        const int s = sidx;

#pragma unroll
        for (int ks = 0; ks < 4; ks++) {
            const uint32_t kg = (uint32_t)(2 * ks + thi);
            uint32_t a0[4], a1[4];
            ldm_x4(a0, stA[s] + aoff0 + (((kg ^ amask0) << 4)));
            ldm_x4(a1, stA[s] + aoff1 + (((kg ^ amask1) << 4)));
#pragma unroll
            for (int p = 0; p < 4; p++) {
                uint32_t bf[4];
                ldm_x4(bf, stB[s] + boff[p] + (((kg ^ bmask[p]) << 4)));
                mma16816(acc[0][2 * p + 0], a0, bf[0], bf[2]);
                mma16816(acc[0][2 * p + 1], a0, bf[1], bf[3]);
                mma16816(acc[1][2 * p + 0], a1, bf[0], bf[2]);
                mma16816(acc[1][2 * p + 1], a1, bf[1], bf[3]);
            }
        }
        sidx = (sidx + 1) % 3;
    }

    // ---------------- epilogue ----------------
    if (mode == 0) {
#pragma unroll
        for (int mf = 0; mf < 2; mf++) {
#pragma unroll
            for (int half = 0; half < 2; half++) {
                int row = row0 + mr + mf * 16 + g + half * 8;
                if (row >= M) continue;
#pragma unroll
                for (int nf = 0; nf < 8; nf++) {
                    int col = col0 + nc + nf * 8 + tig * 2;
                    float2 bv = *(const float2*)&bias[col];
                    float v0 = fmaxf(acc[mf][nf][half * 2 + 0] + bv.x, 0.0f);
                    float v1 = fmaxf(acc[mf][nf][half * 2 + 1] + bv.y, 0.0f);
                    *(uint32_t*)(d_h2h + (size_t)row * D2 + col) = f2h2(v0, v1);
                }
            }
        }
    } else {
#pragma unroll
        for (int mf = 0; mf < 2; mf++) {
            int ra = row0 + mr + mf * 16 + g;
            int v0ok = (ra < M), v1ok = (ra + 8 < M);
#pragma unroll
            for (int nf = 0; nf < 8; nf++) {
                int col = col0 + nc + nf * 8 + tig * 2;
                float2 bv = *(const float2*)&bias[col];
                acc[mf][nf][0] = v0ok ? fmaxf(acc[mf][nf][0] + bv.x, 0.0f) : 0.0f;
                acc[mf][nf][1] = v0ok ? fmaxf(acc[mf][nf][1] + bv.y, 0.0f) : 0.0f;
                acc[mf][nf][2] = v1ok ? fmaxf(acc[mf][nf][2] + bv.x, 0.0f) : 0.0f;
                acc[mf][nf][3] = v1ok ? fmaxf(acc[mf][nf][3] + bv.y, 0.0f) : 0.0f;
            }
        }
        unsigned mask = 0xffffffffu;
        int rv = row0 + mr + lane;
        int bl = (rv < N_NODES) ? load_idx(batch, rv) : -1;
        int b0 = __shfl_sync(mask, bl, 0);
        bool uni = __all_sync(mask, bl == b0);
        if (uni && b0 >= 0) {
            float s[8][2];
#pragma unroll
            for (int nf = 0; nf < 8; nf++) {
                s[nf][0] = acc[0][nf][0] + acc[0][nf][2] + acc[1][nf][0] + acc[1][nf][2];
                s[nf][1] = acc[0][nf][1] + acc[0][nf][3] + acc[1][nf][1] + acc[1][nf][3];
            }
#pragma unroll
            for (int off = 4; off < 32; off <<= 1)
#pragma unroll
                for (int nf = 0; nf < 8; nf++) {
                    s[nf][0] += __shfl_xor_sync(mask, s[nf][0], off);
                    s[nf][1] += __shfl_xor_sync(mask, s[nf][1], off);
                }
            if (lane < 4) {
#pragma unroll
                for (int nf = 0; nf < 8; nf++) {
                    int col = col0 + nc + nf * 8 + lane * 2;
                    red_add_v2(&d_pool[(size_t)b0 * D3 + col], s[nf][0], s[nf][1]);
                }
            }
        } else {
#pragma unroll
            for (int mf = 0; mf < 2; mf++)
#pragma unroll
                for (int half = 0; half < 2; half++) {
                    int row = row0 + mr + mf * 16 + g + half * 8;
                    if (row >= M) continue;
                    int gb = load_idx(batch, row);
#pragma unroll
                    for (int nf = 0; nf < 8; nf++) {
                        int col = col0 + nc + nf * 8 + tig * 2;
                        red_add_v2(&d_pool[(size_t)gb * D3 + col],
                                   acc[mf][nf][half * 2], acc[mf][nf][half * 2 + 1]);
                    }
                }
        }
    }
}

// ---------------- final linear [16,1024] @ [1024,1024], K-split + atomics ----------------
__global__ void k_final_acc(const float* __restrict__ Wo, float* __restrict__ out) {
    __shared__ __align__(16) float sp[128][NGRAPH];
    __shared__ float sinv[NGRAPH];
    int tid = threadIdx.x;
    int c = blockIdx.x * 256 + tid;
    int k0 = blockIdx.y * 128;
    if (tid < NGRAPH) sinv[tid] = 1.0f / fmaxf(d_cnt[tid], 1.0f);
    for (int i = tid; i < 128 * NGRAPH; i += 256) {
        int k = i >> 4, g = i & 15;
        sp[k][g] = d_pool[(size_t)g * D3 + k0 + k];
    }
    __syncthreads();
    float acc[NGRAPH];
#pragma unroll
    for (int g = 0; g < NGRAPH; g++) acc[g] = 0.0f;
#pragma unroll 4
    for (int k = 0; k < 128; k++) {
        float w = Wo[(size_t)(k0 + k) * D3 + c];
        const float4* pr = (const float4*)sp[k];
#pragma unroll
        for (int q = 0; q < 4; q++) {
            float4 pv = pr[q];
            acc[q * 4 + 0] = fmaf(pv.x, w, acc[q * 4 + 0]);
            acc[q * 4 + 1] = fmaf(pv.y, w, acc[q * 4 + 1]);
            acc[q * 4 + 2] = fmaf(pv.z, w, acc[q * 4 + 2]);
            acc[q * 4 + 3] = fmaf(pv.w, w, acc[q * 4 + 3]);
        }
    }
#pragma unroll
    for (int g = 0; g < NGRAPH; g++)
        red_add_f32(&out[(size_t)g * D3 + c], acc[g] * sinv[g]);
}

// ---------------- launcher ----------------
extern "C" void kernel_launch(void* const* d_in, const int* in_sizes, int n_in,
                              void* d_out, int out_size) {
    const float *x, *W1, *b1, *W2, *b2, *W3, *b3, *Wo, *bo;
    const void *ei, *batch;
    if (in_sizes[0] == N_NODES) {           // dict order
        x     = (const float*)d_in[0];
        ei    = d_in[1];
        batch = d_in[2];
        W1 = (const float*)d_in[3];  b1 = (const float*)d_in[4];
        W2 = (const float*)d_in[5];  b2 = (const float*)d_in[6];
        W3 = (const float*)d_in[7];  b3 = (const float*)d_in[8];
        Wo = (const float*)d_in[9];  bo = (const float*)d_in[10];
    } else {                                // alphabetical order
        W1 = (const float*)d_in[0];
        W2 = (const float*)d_in[1];
        W3 = (const float*)d_in[2];
        Wo = (const float*)d_in[3];
        b1 = (const float*)d_in[4];
        b2 = (const float*)d_in[5];
        b3 = (const float*)d_in[6];
        batch = d_in[7];
        bo = (const float*)d_in[8];
        ei = d_in[9];
        x  = (const float*)d_in[10];
    }
    float* out = (float*)d_out;

    __half *a2h, *a3h, *b2h, *b3h;
    cudaGetSymbolAddress((void**)&a2h, d_a2h);
    cudaGetSymbolAddress((void**)&a3h, d_a3h);
    cudaGetSymbolAddress((void**)&b2h, d_b2h);
    cudaGetSymbolAddress((void**)&b3h, d_b3h);

    static int init_done = 0;
    static cudaStream_t s_side;
    static cudaEvent_t ev_fork, ev_join;
    if (!init_done) {
        cudaFuncSetAttribute(mma_gemm, cudaFuncAttributeMaxDynamicSharedMemorySize, 98304);
        cudaStreamCreateWithFlags(&s_side, cudaStreamNonBlocking);
        cudaEventCreateWithFlags(&ev_fork, cudaEventDisableTiming);
        cudaEventCreateWithFlags(&ev_join, cudaEventDisableTiming);
        init_done = 1;
    }

    const int TB = 256;
    int nb_nodes = (N_NODES + TB - 1) / TB;
    int nb_edges = (N_EDGES + TB - 1) / TB;
    int nb_deg   = (N_EDGES + TB * 4 - 1) / (TB * 4);
    int nb_node8 = (N_NODES + 7) / 8;

    // fork: weight conversions on the side stream, overlapped with graph setup
    cudaEventRecord(ev_fork, 0);
    cudaStreamWaitEvent(s_side, ev_fork, 0);
    {
        dim3 g2w(D2 / 32, D1 / 32);
        k_wconv<<<g2w, 256, 0, s_side>>>(W2, b2h, D1, D2);
        dim3 g3w(D3 / 32, D2 / 32);
        k_wconv<<<g3w, 256, 0, s_side>>>(W3, b3h, D2, D3);
    }
    cudaEventRecord(ev_join, s_side);

    // main chain
    k_init<<<nb_nodes, TB>>>(ei, bo, out);
    k_deg_cnt<<<nb_deg, TB>>>(ei, batch);
    k_dis_s1<<<nb_nodes, TB>>>(x);
    k_fill<<<nb_edges, TB>>>(ei, x);
    k_gather1<<<nb_node8, TB>>>(W1, b1);

    // join weight conversions before first GEMM
    cudaStreamWaitEvent(0, ev_join, 0);

    // layer 2 GEMM: h2 = relu(a2 @ W2 + b2) stored fp16
    {
        dim3 grid(D2 / 128, (N_NODES + 127) / 128);
        mma_gemm<<<grid, 256, 98304>>>(a2h, b2h, b2, nullptr, N_NODES, D2, D1, 0);
    }

    // layer 2 aggregation: gather, emit a3 fp16 directly
    k_gather2<<<nb_node8, TB>>>();

    // layer 3 GEMM with fused pooling
    {
        dim3 grid(D3 / 128, (N_NODES + 127) / 128);
        mma_gemm<<<grid, 256, 98304>>>(a3h, b3h, b3, batch, N_NODES, D3, D2, 1);
    }

    // final linear, K-split across 32 blocks
    {
        dim3 grid(4, 8);
        k_final_acc<<<grid, 256>>>(Wo, out);
    }
}